// round 1
// baseline (speedup 1.0000x reference)
#include <cuda_runtime.h>
#include <math.h>

#define Bb 4
#define Ss 2048
#define Dd 1024
#define Hh 512
#define Ee 8
#define Ff 2816
#define Rr 16
#define HIDk 128
#define Nn 8192
#define NP 16384
#define LN_EPS 1e-5f

// ---------------- static device scratch ----------------
__device__ float g_base[Nn * HIDk];        // x@W1x + hb + b1   [N,128]
__device__ float g_hb[Bb * HIDk];          // hist@W1h + b1
__device__ float g_pk[Ee * HIDk];          // persona@W1p
__device__ float g_cgw[Dd];                // ln_g * wg
__device__ float g_CgCb[2];                // sum(ln_g*wg), sum(ln_b*wg)+bg
__device__ float g_logits[Nn * Ee];
__device__ int   g_cnt[Ee];
__device__ int   g_off[Ee];
__device__ int   g_te[Nn * 2];
__device__ int   g_tp[Nn * 2];
__device__ float g_tw[Nn * 2];
__device__ int   g_ptok[NP];
__device__ float g_pw[NP];
__device__ float g_Wgm[(size_t)Ee * Dd * Ff];   // merged gate  92MB
__device__ float g_Wum[(size_t)Ee * Dd * Ff];   // merged up    92MB
__device__ float g_Wdm[(size_t)Ee * Ff * Dd];   // merged down  92MB
__device__ float g_H[(size_t)NP * Ff];          // silu(g)*u   184MB

// ---------------- prep: hb, pk, cgw, Cg/Cb ----------------
__global__ void prep_kernel(const float* __restrict__ hist, const float* __restrict__ W1h,
                            const float* __restrict__ b1,
                            const float* __restrict__ persona, const float* __restrict__ W1p,
                            const float* __restrict__ ln_g, const float* __restrict__ ln_b,
                            const float* __restrict__ Wg, const float* __restrict__ bg) {
    int bx = blockIdx.x, tid = threadIdx.x;
    if (bx < 4) {
        float acc = b1[tid];
        const float* hr = hist + bx * Hh;
        for (int k = 0; k < Hh; k++) acc += hr[k] * W1h[k * HIDk + tid];
        g_hb[bx * HIDk + tid] = acc;
    } else if (bx < 12) {
        int e = bx - 4;
        float acc = 0.f;
        const float* pr = persona + e * Dd;
        for (int k = 0; k < Dd; k++) acc += pr[k] * W1p[k * HIDk + tid];
        g_pk[e * HIDk + tid] = acc;
    } else {
        __shared__ float sg[128], sb[128];
        float a = 0.f, b = 0.f;
        for (int d = tid; d < Dd; d += 128) {
            float w = Wg[d];
            float c = ln_g[d] * w;
            g_cgw[d] = c;
            a += c;
            b += ln_b[d] * w;
        }
        sg[tid] = a; sb[tid] = b;
        __syncthreads();
        for (int s = 64; s > 0; s >>= 1) {
            if (tid < s) { sg[tid] += sg[tid + s]; sb[tid] += sb[tid + s]; }
            __syncthreads();
        }
        if (tid == 0) { g_CgCb[0] = sg[0]; g_CgCb[1] = sb[0] + bg[0]; }
    }
}

// ---------------- base = x @ W1x + hb(b) (hb includes b1) ----------------
__global__ __launch_bounds__(256) void base_kernel(const float* __restrict__ x,
                                                   const float* __restrict__ W1x) {
    __shared__ float Xs[64][16];
    __shared__ float Ws[16][128];
    int tid = threadIdx.x;
    int n0 = blockIdx.x * 64;
    int tx = tid & 15, ty = tid >> 4;
    float acc[4][8];
#pragma unroll
    for (int i = 0; i < 4; i++)
#pragma unroll
        for (int j = 0; j < 8; j++) acc[i][j] = 0.f;

    for (int ks = 0; ks < 64; ks++) {
        int k0 = ks * 16;
        {
            int row = tid >> 2, kk = (tid & 3) * 4;
            *(float4*)&Xs[row][kk] = *(const float4*)(x + (size_t)(n0 + row) * Dd + k0 + kk);
        }
        {
            int kk = tid >> 4, j = (tid & 15) * 8;
            const float* s = W1x + (size_t)(k0 + kk) * HIDk + j;
            *(float4*)&Ws[kk][j]     = *(const float4*)s;
            *(float4*)&Ws[kk][j + 4] = *(const float4*)(s + 4);
        }
        __syncthreads();
#pragma unroll
        for (int kk = 0; kk < 16; kk++) {
            float4 w0 = *(float4*)&Ws[kk][tx * 8];
            float4 w1 = *(float4*)&Ws[kk][tx * 8 + 4];
#pragma unroll
            for (int i = 0; i < 4; i++) {
                float xv = Xs[ty * 4 + i][kk];
                acc[i][0] += xv * w0.x; acc[i][1] += xv * w0.y;
                acc[i][2] += xv * w0.z; acc[i][3] += xv * w0.w;
                acc[i][4] += xv * w1.x; acc[i][5] += xv * w1.y;
                acc[i][6] += xv * w1.z; acc[i][7] += xv * w1.w;
            }
        }
        __syncthreads();
    }
    int b = n0 >> 11;
    const float* hb = g_hb + b * HIDk + tx * 8;
#pragma unroll
    for (int i = 0; i < 4; i++) {
        int n = n0 + ty * 4 + i;
        float4 o0 = make_float4(acc[i][0] + hb[0], acc[i][1] + hb[1],
                                acc[i][2] + hb[2], acc[i][3] + hb[3]);
        float4 o1 = make_float4(acc[i][4] + hb[4], acc[i][5] + hb[5],
                                acc[i][6] + hb[6], acc[i][7] + hb[7]);
        *(float4*)&g_base[(size_t)n * HIDk + tx * 8]     = o0;
        *(float4*)&g_base[(size_t)n * HIDk + tx * 8 + 4] = o1;
    }
}

// ---------------- merged weights: W' = W + A@B ----------------
// grid (528, 8): per expert, 176 tiles gate + 176 up + 176 down; tile = 64 rows x 256 cols
__global__ __launch_bounds__(256) void merge_kernel(
    const float* __restrict__ Wgate, const float* __restrict__ Wup, const float* __restrict__ Wdown,
    const float* __restrict__ Ag, const float* __restrict__ Bg,
    const float* __restrict__ Au, const float* __restrict__ Bu,
    const float* __restrict__ Ad, const float* __restrict__ Bd) {
    __shared__ float Bs[16][256];
    __shared__ float As[64][16];
    int e = blockIdx.y, bx = blockIdx.x, tid = threadIdx.x;
    const float *src, *Abase, *Bbase;
    float* dst;
    int cols, rtile, ftile;
    if (bx < 176) {
        rtile = bx / 11; ftile = bx % 11; cols = Ff;
        src = Wgate + (size_t)e * Dd * Ff; dst = g_Wgm + (size_t)e * Dd * Ff;
        Abase = Ag + (size_t)e * Dd * Rr;  Bbase = Bg + (size_t)e * Rr * Ff;
    } else if (bx < 352) {
        bx -= 176;
        rtile = bx / 11; ftile = bx % 11; cols = Ff;
        src = Wup + (size_t)e * Dd * Ff;  dst = g_Wum + (size_t)e * Dd * Ff;
        Abase = Au + (size_t)e * Dd * Rr;  Bbase = Bu + (size_t)e * Rr * Ff;
    } else {
        bx -= 352;
        rtile = bx / 4;  ftile = bx % 4;  cols = Dd;
        src = Wdown + (size_t)e * Ff * Dd; dst = g_Wdm + (size_t)e * Ff * Dd;
        Abase = Ad + (size_t)e * Ff * Rr;  Bbase = Bd + (size_t)e * Rr * Dd;
    }
    int f0 = ftile * 256;
    // stage A tile: 64 rows x 16 (flat 1024 floats)
    *((float4*)&As[0][0] + tid) = *((const float4*)(Abase + (size_t)rtile * 64 * 16) + tid);
    // stage B tile: 16 x 256
    {
        int k = tid >> 4, c0 = (tid & 15) * 16;
#pragma unroll
        for (int q = 0; q < 4; q++)
            *(float4*)&Bs[k][c0 + 4 * q] = *(const float4*)(Bbase + (size_t)k * cols + f0 + c0 + 4 * q);
    }
    __syncthreads();
    for (int rl = 0; rl < 64; rl++) {
        size_t idx = (size_t)(rtile * 64 + rl) * cols + f0 + tid;
        float v = src[idx];
#pragma unroll
        for (int k = 0; k < 16; k++) v += As[rl][k] * Bs[k][tid];
        dst[idx] = v;
    }
}

// ---------------- fused gate logits: relu(base+pk)@W2 -> relu -> LN-collapsed dot ----------------
// grid (256, 8): 32 tokens per block, one expert per blockIdx.y, full D reduction in-block
__global__ __launch_bounds__(256) void logits_kernel(const float* __restrict__ W2,
                                                     const float* __restrict__ b2) {
    __shared__ float h1s[32][128];
    __shared__ float w2s[16][256];
    int e = blockIdx.y, n0 = blockIdx.x * 32;
    int tid = threadIdx.x, lane = tid & 31, wp = tid >> 5;
    // stage h1 = relu(base + pk[e])
    {
        int t = tid >> 3, kh = (tid & 7) * 16;
        const float4* bp = (const float4*)(g_base + (size_t)(n0 + t) * HIDk + kh);
        const float4* pp = (const float4*)(g_pk + e * HIDk + kh);
#pragma unroll
        for (int q = 0; q < 4; q++) {
            float4 a = bp[q], b = pp[q];
            h1s[t][kh + 4 * q + 0] = fmaxf(a.x + b.x, 0.f);
            h1s[t][kh + 4 * q + 1] = fmaxf(a.y + b.y, 0.f);
            h1s[t][kh + 4 * q + 2] = fmaxf(a.z + b.z, 0.f);
            h1s[t][kh + 4 * q + 3] = fmaxf(a.w + b.w, 0.f);
        }
    }
    __syncthreads();
    float s1[4] = {0.f, 0.f, 0.f, 0.f};
    float s2[4] = {0.f, 0.f, 0.f, 0.f};
    float s3[4] = {0.f, 0.f, 0.f, 0.f};
    for (int c = 0; c < 4; c++) {
        float acc[4][8];
#pragma unroll
        for (int i = 0; i < 4; i++)
#pragma unroll
            for (int m = 0; m < 8; m++) acc[i][m] = 0.f;
        for (int s = 0; s < 8; s++) {
            __syncthreads();
            {
                int kk = tid >> 4, dl = (tid & 15) * 16;
#pragma unroll
                for (int q = 0; q < 4; q++)
                    *(float4*)&w2s[kk][dl + 4 * q] =
                        *(const float4*)(W2 + (size_t)(s * 16 + kk) * Dd + c * 256 + dl + 4 * q);
            }
            __syncthreads();
#pragma unroll
            for (int kk = 0; kk < 16; kk++) {
                int k = s * 16 + kk;
                float xv[4];
#pragma unroll
                for (int i = 0; i < 4; i++) xv[i] = h1s[wp * 4 + i][k];
#pragma unroll
                for (int m = 0; m < 8; m++) {
                    float wv = w2s[kk][lane + 32 * m];
#pragma unroll
                    for (int i = 0; i < 4; i++) acc[i][m] += xv[i] * wv;
                }
            }
        }
#pragma unroll
        for (int m = 0; m < 8; m++) {
            int d = c * 256 + lane + 32 * m;
            float bb = b2[d], cg = g_cgw[d];
#pragma unroll
            for (int i = 0; i < 4; i++) {
                float f = fmaxf(acc[i][m] + bb, 0.f);
                s1[i] += f * cg; s2[i] += f; s3[i] += f * f;
            }
        }
    }
#pragma unroll
    for (int off = 16; off > 0; off >>= 1) {
#pragma unroll
        for (int i = 0; i < 4; i++) {
            s1[i] += __shfl_down_sync(0xffffffffu, s1[i], off);
            s2[i] += __shfl_down_sync(0xffffffffu, s2[i], off);
            s3[i] += __shfl_down_sync(0xffffffffu, s3[i], off);
        }
    }
    if (lane == 0) {
        float Cg = g_CgCb[0], Cb = g_CgCb[1];
#pragma unroll
        for (int i = 0; i < 4; i++) {
            float mu = s2[i] * (1.f / (float)Dd);
            float var = s3[i] * (1.f / (float)Dd) - mu * mu;
            float rstd = rsqrtf(var + LN_EPS);
            g_logits[(size_t)(n0 + wp * 4 + i) * Ee + e] = rstd * (s1[i] - mu * Cg) + Cb;
        }
    }
}

// ---------------- softmax + top-2 routing ----------------
__global__ void route_kernel() {
    int n = blockIdx.x * 256 + threadIdx.x;
    float l[Ee];
    float m = -1e30f;
#pragma unroll
    for (int e = 0; e < Ee; e++) { l[e] = g_logits[(size_t)n * Ee + e]; m = fmaxf(m, l[e]); }
    float s = 0.f;
#pragma unroll
    for (int e = 0; e < Ee; e++) { l[e] = expf(l[e] - m); s += l[e]; }
    float inv = 1.f / s;
#pragma unroll
    for (int e = 0; e < Ee; e++) l[e] *= inv;
    int i0 = 0; float b0 = l[0];
#pragma unroll
    for (int e = 1; e < Ee; e++) if (l[e] > b0) { b0 = l[e]; i0 = e; }
    int i1 = -1; float b1 = -1.f;
#pragma unroll
    for (int e = 0; e < Ee; e++) if (e != i0 && l[e] > b1) { b1 = l[e]; i1 = e; }
    int p0 = atomicAdd(&g_cnt[i0], 1);
    int p1 = atomicAdd(&g_cnt[i1], 1);
    g_te[2 * n] = i0; g_tp[2 * n] = p0; g_tw[2 * n] = b0;
    g_te[2 * n + 1] = i1; g_tp[2 * n + 1] = p1; g_tw[2 * n + 1] = b1;
}

__global__ void scan_kernel() {
    int a = 0;
    for (int e = 0; e < Ee; e++) { g_off[e] = a; a += g_cnt[e]; }
}

__global__ void scatter_kernel() {
    int n = blockIdx.x * 256 + threadIdx.x;
#pragma unroll
    for (int i = 0; i < 2; i++) {
        int slot = g_off[g_te[2 * n + i]] + g_tp[2 * n + i];
        g_ptok[slot] = n;
        g_pw[slot] = g_tw[2 * n + i];
    }
}

// ---------------- expert GEMM1: H = silu(X@Wg') * (X@Wu'), gathered rows ----------------
// grid (128 rowtiles, 22 ftiles, 8 experts), tile 64 x 128, thread 4x8 dual accum
__global__ __launch_bounds__(256) void gemm1_kernel(const float* __restrict__ x) {
    __shared__ float Xs[64][16];
    __shared__ float Wgs[16][128];
    __shared__ float Wus[16][128];
    __shared__ int stoks[64];
    int e = blockIdx.z;
    int cnt = g_cnt[e];
    int r0 = blockIdx.x * 64;
    if (r0 >= cnt) return;
    int off = g_off[e];
    int f0 = blockIdx.y * 128;
    int tid = threadIdx.x, tx = tid & 15, ty = tid >> 4;
    if (tid < 64) {
        int lr = r0 + tid;
        if (lr >= cnt) lr = cnt - 1;
        stoks[tid] = g_ptok[off + lr];
    }
    __syncthreads();
    float ag[4][8], au[4][8];
#pragma unroll
    for (int i = 0; i < 4; i++)
#pragma unroll
        for (int j = 0; j < 8; j++) { ag[i][j] = 0.f; au[i][j] = 0.f; }
    const float* Wgp = g_Wgm + (size_t)e * Dd * Ff;
    const float* Wupp = g_Wum + (size_t)e * Dd * Ff;
    for (int ks = 0; ks < 64; ks++) {
        int k0 = ks * 16;
        {
            int row = tid >> 2, kk = (tid & 3) * 4;
            *(float4*)&Xs[row][kk] = *(const float4*)(x + (size_t)stoks[row] * Dd + k0 + kk);
        }
        {
            int kk = tid >> 4, j = (tid & 15) * 8;
            const float* sg = Wgp + (size_t)(k0 + kk) * Ff + f0 + j;
            *(float4*)&Wgs[kk][j]     = *(const float4*)sg;
            *(float4*)&Wgs[kk][j + 4] = *(const float4*)(sg + 4);
            const float* su = Wupp + (size_t)(k0 + kk) * Ff + f0 + j;
            *(float4*)&Wus[kk][j]     = *(const float4*)su;
            *(float4*)&Wus[kk][j + 4] = *(const float4*)(su + 4);
        }
        __syncthreads();
#pragma unroll
        for (int kk = 0; kk < 16; kk++) {
            float4 wg0 = *(float4*)&Wgs[kk][tx * 8];
            float4 wg1 = *(float4*)&Wgs[kk][tx * 8 + 4];
            float4 wu0 = *(float4*)&Wus[kk][tx * 8];
            float4 wu1 = *(float4*)&Wus[kk][tx * 8 + 4];
#pragma unroll
            for (int i = 0; i < 4; i++) {
                float xv = Xs[ty * 4 + i][kk];
                ag[i][0] += xv * wg0.x; ag[i][1] += xv * wg0.y;
                ag[i][2] += xv * wg0.z; ag[i][3] += xv * wg0.w;
                ag[i][4] += xv * wg1.x; ag[i][5] += xv * wg1.y;
                ag[i][6] += xv * wg1.z; ag[i][7] += xv * wg1.w;
                au[i][0] += xv * wu0.x; au[i][1] += xv * wu0.y;
                au[i][2] += xv * wu0.z; au[i][3] += xv * wu0.w;
                au[i][4] += xv * wu1.x; au[i][5] += xv * wu1.y;
                au[i][6] += xv * wu1.z; au[i][7] += xv * wu1.w;
            }
        }
        __syncthreads();
    }
#pragma unroll
    for (int i = 0; i < 4; i++) {
        int lr = r0 + ty * 4 + i;
        if (lr < cnt) {
            float h[8];
#pragma unroll
            for (int j = 0; j < 8; j++) {
                float g = ag[i][j];
                h[j] = g / (1.f + expf(-g)) * au[i][j];
            }
            size_t base = (size_t)(off + lr) * Ff + f0 + tx * 8;
            *(float4*)&g_H[base]     = make_float4(h[0], h[1], h[2], h[3]);
            *(float4*)&g_H[base + 4] = make_float4(h[4], h[5], h[6], h[7]);
        }
    }
}

// ---------------- expert GEMM2: out[tok] += w * (H@Wd') ----------------
// grid (128 rowtiles, 8 dtiles, 8 experts)
__global__ __launch_bounds__(256) void gemm2_kernel(float* __restrict__ out) {
    __shared__ float Hs[64][16];
    __shared__ float Ws[16][128];
    int e = blockIdx.z;
    int cnt = g_cnt[e];
    int r0 = blockIdx.x * 64;
    if (r0 >= cnt) return;
    int off = g_off[e];
    int d0 = blockIdx.y * 128;
    int tid = threadIdx.x, tx = tid & 15, ty = tid >> 4;
    float acc[4][8];
#pragma unroll
    for (int i = 0; i < 4; i++)
#pragma unroll
        for (int j = 0; j < 8; j++) acc[i][j] = 0.f;
    const float* Wd = g_Wdm + (size_t)e * Ff * Dd;
    for (int ks = 0; ks < 176; ks++) {
        int k0 = ks * 16;
        {
            int row = tid >> 2, kk = (tid & 3) * 4;
            int lr = r0 + row;
            if (lr >= cnt) lr = cnt - 1;
            *(float4*)&Hs[row][kk] = *(const float4*)(g_H + (size_t)(off + lr) * Ff + k0 + kk);
        }
        {
            int kk = tid >> 4, j = (tid & 15) * 8;
            const float* s = Wd + (size_t)(k0 + kk) * Dd + d0 + j;
            *(float4*)&Ws[kk][j]     = *(const float4*)s;
            *(float4*)&Ws[kk][j + 4] = *(const float4*)(s + 4);
        }
        __syncthreads();
#pragma unroll
        for (int kk = 0; kk < 16; kk++) {
            float4 w0 = *(float4*)&Ws[kk][tx * 8];
            float4 w1 = *(float4*)&Ws[kk][tx * 8 + 4];
#pragma unroll
            for (int i = 0; i < 4; i++) {
                float xv = Hs[ty * 4 + i][kk];
                acc[i][0] += xv * w0.x; acc[i][1] += xv * w0.y;
                acc[i][2] += xv * w0.z; acc[i][3] += xv * w0.w;
                acc[i][4] += xv * w1.x; acc[i][5] += xv * w1.y;
                acc[i][6] += xv * w1.z; acc[i][7] += xv * w1.w;
            }
        }
        __syncthreads();
    }
#pragma unroll
    for (int i = 0; i < 4; i++) {
        int lr = r0 + ty * 4 + i;
        if (lr < cnt) {
            int slot = off + lr;
            int tok = g_ptok[slot];
            float w = g_pw[slot];
            float* op = out + (size_t)tok * Dd + d0 + tx * 8;
#pragma unroll
            for (int j = 0; j < 8; j++) atomicAdd(op + j, acc[i][j] * w);
        }
    }
}

// ---------------- launch ----------------
extern "C" void kernel_launch(void* const* d_in, const int* in_sizes, int n_in,
                              void* d_out, int out_size) {
    (void)in_sizes; (void)n_in;
    const float* x       = (const float*)d_in[0];
    const float* hist    = (const float*)d_in[1];
    const float* persona = (const float*)d_in[2];
    const float* W1x     = (const float*)d_in[3];
    const float* W1h     = (const float*)d_in[4];
    const float* W1p     = (const float*)d_in[5];
    const float* b1      = (const float*)d_in[6];
    const float* W2      = (const float*)d_in[7];
    const float* b2      = (const float*)d_in[8];
    const float* ln_g    = (const float*)d_in[9];
    const float* ln_b    = (const float*)d_in[10];
    const float* Wg      = (const float*)d_in[11];
    const float* bg      = (const float*)d_in[12];
    const float* Wgate   = (const float*)d_in[13];
    const float* Wup     = (const float*)d_in[14];
    const float* Wdown   = (const float*)d_in[15];
    const float* Ag      = (const float*)d_in[16];
    const float* Bg      = (const float*)d_in[17];
    const float* Au      = (const float*)d_in[18];
    const float* Bu      = (const float*)d_in[19];
    const float* Ad      = (const float*)d_in[20];
    const float* Bd      = (const float*)d_in[21];
    float* out = (float*)d_out;

    void* cntp = nullptr;
    cudaGetSymbolAddress(&cntp, g_cnt);

    cudaMemsetAsync(out, 0, (size_t)out_size * sizeof(float));
    cudaMemsetAsync(cntp, 0, Ee * sizeof(int));

    prep_kernel<<<13, 128>>>(hist, W1h, b1, persona, W1p, ln_g, ln_b, Wg, bg);
    base_kernel<<<Nn / 64, 256>>>(x, W1x);
    merge_kernel<<<dim3(528, Ee), 256>>>(Wgate, Wup, Wdown, Ag, Bg, Au, Bu, Ad, Bd);
    logits_kernel<<<dim3(Nn / 32, Ee), 256>>>(W2, b2);
    route_kernel<<<Nn / 256, 256>>>();
    scan_kernel<<<1, 1>>>();
    scatter_kernel<<<Nn / 256, 256>>>();
    gemm1_kernel<<<dim3(128, Ff / 128, Ee), 256>>>(x);
    gemm2_kernel<<<dim3(128, Dd / 128, Ee), 256>>>(out);
}

// round 3
// speedup vs baseline: 2.7754x; 2.7754x over previous
#include <cuda_runtime.h>
#include <cuda_fp16.h>
#include <math.h>
#include <stdint.h>

#define Bb 4
#define Ss 2048
#define Dd 1024
#define Hh 512
#define Ee 8
#define Ff 2816
#define Rr 16
#define HIDk 128
#define Nn 8192
#define NP 16384
#define LN_EPS 1e-5f

// ===================== baseline-PTX helpers (no sm_103a-only features) =====================
__device__ __forceinline__ uint32_t smem_u32(const void* p) {
    uint32_t a;
    asm("{ .reg .u64 t; cvta.to.shared.u64 t, %1; cvt.u32.u64 %0, t; }" : "=r"(a) : "l"(p));
    return a;
}

#define CPASYNC16(dst, src) \
    asm volatile("cp.async.cg.shared.global [%0], [%1], 16;\n" :: "r"(dst), "l"(src))
#define CP_COMMIT() asm volatile("cp.async.commit_group;\n" ::: "memory")
#define CP_WAIT(N)  asm volatile("cp.async.wait_group %0;\n" :: "n"(N) : "memory")

#define LDSM4(R, addr) \
    asm volatile("ldmatrix.sync.aligned.m8n8.x4.shared.b16 {%0,%1,%2,%3}, [%4];" \
        : "=r"((R)[0]), "=r"((R)[1]), "=r"((R)[2]), "=r"((R)[3]) : "r"(addr))

#define MMA16816(C, A, B0, B1) \
    asm volatile("mma.sync.aligned.m16n8k16.row.col.f32.f16.f16.f32 " \
        "{%0,%1,%2,%3}, {%4,%5,%6,%7}, {%8,%9}, {%0,%1,%2,%3};" \
        : "+f"((C)[0]), "+f"((C)[1]), "+f"((C)[2]), "+f"((C)[3]) \
        : "r"((A)[0]), "r"((A)[1]), "r"((A)[2]), "r"((A)[3]), "r"(B0), "r"(B1))

__device__ __forceinline__ void f2h_split(float v, unsigned short& hi, unsigned short& lo) {
    __half h = __float2half_rn(v);
    hi = __half_as_ushort(h);
    lo = __half_as_ushort(__float2half_rn(v - __half2float(h)));
}

// ===================== static device scratch =====================
__device__ float g_base[Nn * HIDk];
__device__ float g_hb[Bb * HIDk];
__device__ float g_pk[Ee * HIDk];
__device__ float g_cgw[Dd];
__device__ float g_CgCb[2];
__device__ float g_logits[Nn * Ee];
__device__ int   g_cnt[Ee];
__device__ int   g_off[Ee];
__device__ int   g_te[Nn * 2];
__device__ int   g_tp[Nn * 2];
__device__ float g_tw[Nn * 2];
__device__ int   g_ptok[NP];
__device__ float g_pw[NP];
// fp16 hi/lo split storage
__device__ unsigned short g_xh[(size_t)Nn * Dd];
__device__ unsigned short g_xl[(size_t)Nn * Dd];
__device__ unsigned short g_WgH[(size_t)Ee * Ff * Dd];   // [e][f][d]  K-major
__device__ unsigned short g_WgL[(size_t)Ee * Ff * Dd];
__device__ unsigned short g_WuH[(size_t)Ee * Ff * Dd];
__device__ unsigned short g_WuL[(size_t)Ee * Ff * Dd];
__device__ unsigned short g_WdH[(size_t)Ee * Dd * Ff];   // [e][d][f]  K-major
__device__ unsigned short g_WdL[(size_t)Ee * Dd * Ff];
__device__ unsigned short g_Hh[(size_t)NP * Ff];
__device__ unsigned short g_Hl[(size_t)NP * Ff];

// ===================== prep =====================
__global__ void prep_kernel(const float* __restrict__ hist, const float* __restrict__ W1h,
                            const float* __restrict__ b1,
                            const float* __restrict__ persona, const float* __restrict__ W1p,
                            const float* __restrict__ ln_g, const float* __restrict__ ln_b,
                            const float* __restrict__ Wg, const float* __restrict__ bg) {
    int bx = blockIdx.x, tid = threadIdx.x;
    if (bx < 4) {
        float acc = b1[tid];
        const float* hr = hist + bx * Hh;
        for (int k = 0; k < Hh; k++) acc += hr[k] * W1h[k * HIDk + tid];
        g_hb[bx * HIDk + tid] = acc;
    } else if (bx < 12) {
        int e = bx - 4;
        float acc = 0.f;
        const float* pr = persona + e * Dd;
        for (int k = 0; k < Dd; k++) acc += pr[k] * W1p[k * HIDk + tid];
        g_pk[e * HIDk + tid] = acc;
    } else {
        __shared__ float sg[128], sb[128];
        float a = 0.f, b = 0.f;
        for (int d = tid; d < Dd; d += 128) {
            float w = Wg[d];
            float c = ln_g[d] * w;
            g_cgw[d] = c;
            a += c;
            b += ln_b[d] * w;
        }
        sg[tid] = a; sb[tid] = b;
        __syncthreads();
        for (int s = 64; s > 0; s >>= 1) {
            if (tid < s) { sg[tid] += sg[tid + s]; sb[tid] += sb[tid + s]; }
            __syncthreads();
        }
        if (tid == 0) { g_CgCb[0] = sg[0]; g_CgCb[1] = sb[0] + bg[0]; }
    }
}

// ===================== x -> fp16 hi/lo =====================
__global__ void xconv_kernel(const float* __restrict__ x) {
    size_t i = (size_t)blockIdx.x * 256 + threadIdx.x;
    float4 v = ((const float4*)x)[i];
    unsigned short h0, l0, h1, l1, h2, l2, h3, l3;
    f2h_split(v.x, h0, l0); f2h_split(v.y, h1, l1);
    f2h_split(v.z, h2, l2); f2h_split(v.w, h3, l3);
    uint2 ph = make_uint2((uint32_t)h0 | ((uint32_t)h1 << 16), (uint32_t)h2 | ((uint32_t)h3 << 16));
    uint2 pl = make_uint2((uint32_t)l0 | ((uint32_t)l1 << 16), (uint32_t)l2 | ((uint32_t)l3 << 16));
    *(uint2*)(g_xh + i * 4) = ph;
    *(uint2*)(g_xl + i * 4) = pl;
}

// ===================== base = x @ W1x + hb =====================
__global__ __launch_bounds__(256) void base_kernel(const float* __restrict__ x,
                                                   const float* __restrict__ W1x) {
    __shared__ float Xs[64][16];
    __shared__ float Ws[16][128];
    int tid = threadIdx.x;
    int n0 = blockIdx.x * 64;
    int tx = tid & 15, ty = tid >> 4;
    float acc[4][8];
#pragma unroll
    for (int i = 0; i < 4; i++)
#pragma unroll
        for (int j = 0; j < 8; j++) acc[i][j] = 0.f;

    for (int ks = 0; ks < 64; ks++) {
        int k0 = ks * 16;
        {
            int row = tid >> 2, kk = (tid & 3) * 4;
            *(float4*)&Xs[row][kk] = *(const float4*)(x + (size_t)(n0 + row) * Dd + k0 + kk);
        }
        {
            int kk = tid >> 4, j = (tid & 15) * 8;
            const float* s = W1x + (size_t)(k0 + kk) * HIDk + j;
            *(float4*)&Ws[kk][j]     = *(const float4*)s;
            *(float4*)&Ws[kk][j + 4] = *(const float4*)(s + 4);
        }
        __syncthreads();
#pragma unroll
        for (int kk = 0; kk < 16; kk++) {
            float4 w0 = *(float4*)&Ws[kk][tx * 8];
            float4 w1 = *(float4*)&Ws[kk][tx * 8 + 4];
#pragma unroll
            for (int i = 0; i < 4; i++) {
                float xv = Xs[ty * 4 + i][kk];
                acc[i][0] += xv * w0.x; acc[i][1] += xv * w0.y;
                acc[i][2] += xv * w0.z; acc[i][3] += xv * w0.w;
                acc[i][4] += xv * w1.x; acc[i][5] += xv * w1.y;
                acc[i][6] += xv * w1.z; acc[i][7] += xv * w1.w;
            }
        }
        __syncthreads();
    }
    int b = n0 >> 11;
    const float* hb = g_hb + b * HIDk + tx * 8;
#pragma unroll
    for (int i = 0; i < 4; i++) {
        int n = n0 + ty * 4 + i;
        float4 o0 = make_float4(acc[i][0] + hb[0], acc[i][1] + hb[1],
                                acc[i][2] + hb[2], acc[i][3] + hb[3]);
        float4 o1 = make_float4(acc[i][4] + hb[4], acc[i][5] + hb[5],
                                acc[i][6] + hb[6], acc[i][7] + hb[7]);
        *(float4*)&g_base[(size_t)n * HIDk + tx * 8]     = o0;
        *(float4*)&g_base[(size_t)n * HIDk + tx * 8 + 4] = o1;
    }
}

// ===================== merge: W' = W + A@B, output transposed fp16 hi/lo =====================
__global__ __launch_bounds__(256) void merge_kernel(
    const float* __restrict__ Wgate, const float* __restrict__ Wup, const float* __restrict__ Wdown,
    const float* __restrict__ Ag, const float* __restrict__ Bg,
    const float* __restrict__ Au, const float* __restrict__ Bu,
    const float* __restrict__ Ad, const float* __restrict__ Bd) {
    __shared__ float As[128][17];
    __shared__ float Bs[16][65];
    __shared__ unsigned short Thi[64][136];
    __shared__ unsigned short Tlo[64][136];
    int e = blockIdx.y, t = blockIdx.x, tid = threadIdx.x;
    const float *src, *Ap, *Bp;
    unsigned short *dhi, *dlo;
    int r0, c0, rowStride, outStride;
    if (t < 352) {
        int kt = t / 44, ft = t % 44;
        r0 = kt * 128; c0 = ft * 64; rowStride = Ff; outStride = Dd;
        src = Wgate + (size_t)e * Dd * Ff; Ap = Ag + (size_t)e * Dd * Rr; Bp = Bg + (size_t)e * Rr * Ff;
        dhi = g_WgH + (size_t)e * Ff * Dd; dlo = g_WgL + (size_t)e * Ff * Dd;
    } else if (t < 704) {
        t -= 352;
        int kt = t / 44, ft = t % 44;
        r0 = kt * 128; c0 = ft * 64; rowStride = Ff; outStride = Dd;
        src = Wup + (size_t)e * Dd * Ff; Ap = Au + (size_t)e * Dd * Rr; Bp = Bu + (size_t)e * Rr * Ff;
        dhi = g_WuH + (size_t)e * Ff * Dd; dlo = g_WuL + (size_t)e * Ff * Dd;
    } else {
        t -= 704;
        int kt = t / 16, ft = t % 16;
        r0 = kt * 128; c0 = ft * 64; rowStride = Dd; outStride = Ff;
        src = Wdown + (size_t)e * Ff * Dd; Ap = Ad + (size_t)e * Ff * Rr; Bp = Bd + (size_t)e * Rr * Dd;
        dhi = g_WdH + (size_t)e * Dd * Ff; dlo = g_WdL + (size_t)e * Dd * Ff;
    }
    {
        int r = tid >> 1, k0 = (tid & 1) * 8;
#pragma unroll
        for (int kk = 0; kk < 8; kk++)
            As[r][k0 + kk] = Ap[(size_t)(r0 + r) * Rr + k0 + kk];
    }
    for (int i = tid; i < 1024; i += 256) {
        int k = i >> 6, c = i & 63;
        Bs[k][c] = Bp[(size_t)k * rowStride + c0 + c];
    }
    __syncthreads();
    {
        int c = tid & 63, rb = tid >> 6;
        for (int rr = 0; rr < 32; rr++) {
            int r = rb * 32 + rr;
            float v = src[(size_t)(r0 + r) * rowStride + c0 + c];
#pragma unroll
            for (int k = 0; k < 16; k++) v += As[r][k] * Bs[k][c];
            unsigned short hb_, lb_;
            f2h_split(v, hb_, lb_);
            Thi[c][r] = hb_;
            Tlo[c][r] = lb_;
        }
    }
    __syncthreads();
    {
        int c = tid >> 2, qq = tid & 3;
        const uint4* sh = (const uint4*)&Thi[c][qq * 32];
        const uint4* sl = (const uint4*)&Tlo[c][qq * 32];
        uint4* dH = (uint4*)(dhi + (size_t)(c0 + c) * outStride + r0 + qq * 32);
        uint4* dL = (uint4*)(dlo + (size_t)(c0 + c) * outStride + r0 + qq * 32);
#pragma unroll
        for (int m = 0; m < 4; m++) { dH[m] = sh[m]; dL[m] = sl[m]; }
    }
}

// ===================== fused gate logits =====================
__global__ __launch_bounds__(256) void logits_kernel(const float* __restrict__ W2,
                                                     const float* __restrict__ b2) {
    __shared__ float h1s[32][128];
    __shared__ float w2s[16][256];
    int e = blockIdx.y, n0 = blockIdx.x * 32;
    int tid = threadIdx.x, lane = tid & 31, wp = tid >> 5;
    {
        int t = tid >> 3, kh = (tid & 7) * 16;
        const float4* bp = (const float4*)(g_base + (size_t)(n0 + t) * HIDk + kh);
        const float4* pp = (const float4*)(g_pk + e * HIDk + kh);
#pragma unroll
        for (int q = 0; q < 4; q++) {
            float4 a = bp[q], b = pp[q];
            h1s[t][kh + 4 * q + 0] = fmaxf(a.x + b.x, 0.f);
            h1s[t][kh + 4 * q + 1] = fmaxf(a.y + b.y, 0.f);
            h1s[t][kh + 4 * q + 2] = fmaxf(a.z + b.z, 0.f);
            h1s[t][kh + 4 * q + 3] = fmaxf(a.w + b.w, 0.f);
        }
    }
    __syncthreads();
    float s1[4] = {0.f, 0.f, 0.f, 0.f};
    float s2[4] = {0.f, 0.f, 0.f, 0.f};
    float s3[4] = {0.f, 0.f, 0.f, 0.f};
    for (int c = 0; c < 4; c++) {
        float acc[4][8];
#pragma unroll
        for (int i = 0; i < 4; i++)
#pragma unroll
            for (int m = 0; m < 8; m++) acc[i][m] = 0.f;
        for (int s = 0; s < 8; s++) {
            __syncthreads();
            {
                int kk = tid >> 4, dl = (tid & 15) * 16;
#pragma unroll
                for (int q = 0; q < 4; q++)
                    *(float4*)&w2s[kk][dl + 4 * q] =
                        *(const float4*)(W2 + (size_t)(s * 16 + kk) * Dd + c * 256 + dl + 4 * q);
            }
            __syncthreads();
#pragma unroll
            for (int kk = 0; kk < 16; kk++) {
                int k = s * 16 + kk;
                float xv[4];
#pragma unroll
                for (int i = 0; i < 4; i++) xv[i] = h1s[wp * 4 + i][k];
#pragma unroll
                for (int m = 0; m < 8; m++) {
                    float wv = w2s[kk][lane + 32 * m];
#pragma unroll
                    for (int i = 0; i < 4; i++) acc[i][m] += xv[i] * wv;
                }
            }
        }
#pragma unroll
        for (int m = 0; m < 8; m++) {
            int d = c * 256 + lane + 32 * m;
            float bb = b2[d], cg = g_cgw[d];
#pragma unroll
            for (int i = 0; i < 4; i++) {
                float f = fmaxf(acc[i][m] + bb, 0.f);
                s1[i] += f * cg; s2[i] += f; s3[i] += f * f;
            }
        }
    }
#pragma unroll
    for (int off = 16; off > 0; off >>= 1) {
#pragma unroll
        for (int i = 0; i < 4; i++) {
            s1[i] += __shfl_down_sync(0xffffffffu, s1[i], off);
            s2[i] += __shfl_down_sync(0xffffffffu, s2[i], off);
            s3[i] += __shfl_down_sync(0xffffffffu, s3[i], off);
        }
    }
    if (lane == 0) {
        float Cg = g_CgCb[0], Cb = g_CgCb[1];
#pragma unroll
        for (int i = 0; i < 4; i++) {
            float mu = s2[i] * (1.f / (float)Dd);
            float var = s3[i] * (1.f / (float)Dd) - mu * mu;
            float rstd = rsqrtf(var + LN_EPS);
            g_logits[(size_t)(n0 + wp * 4 + i) * Ee + e] = rstd * (s1[i] - mu * Cg) + Cb;
        }
    }
}

// ===================== routing =====================
__global__ void route_kernel() {
    int n = blockIdx.x * 256 + threadIdx.x;
    float l[Ee];
    float m = -1e30f;
#pragma unroll
    for (int e = 0; e < Ee; e++) { l[e] = g_logits[(size_t)n * Ee + e]; m = fmaxf(m, l[e]); }
    float s = 0.f;
#pragma unroll
    for (int e = 0; e < Ee; e++) { l[e] = expf(l[e] - m); s += l[e]; }
    float inv = 1.f / s;
#pragma unroll
    for (int e = 0; e < Ee; e++) l[e] *= inv;
    int i0 = 0; float b0 = l[0];
#pragma unroll
    for (int e = 1; e < Ee; e++) if (l[e] > b0) { b0 = l[e]; i0 = e; }
    int i1 = -1; float b1 = -1.f;
#pragma unroll
    for (int e = 0; e < Ee; e++) if (e != i0 && l[e] > b1) { b1 = l[e]; i1 = e; }
    int p0 = atomicAdd(&g_cnt[i0], 1);
    int p1 = atomicAdd(&g_cnt[i1], 1);
    g_te[2 * n] = i0; g_tp[2 * n] = p0; g_tw[2 * n] = b0;
    g_te[2 * n + 1] = i1; g_tp[2 * n + 1] = p1; g_tw[2 * n + 1] = b1;
}

__global__ void scan_kernel() {
    int a = 0;
    for (int e = 0; e < Ee; e++) { g_off[e] = a; a += g_cnt[e]; }
}

__global__ void scatter_kernel() {
    int n = blockIdx.x * 256 + threadIdx.x;
#pragma unroll
    for (int i = 0; i < 2; i++) {
        int slot = g_off[g_te[2 * n + i]] + g_tp[2 * n + i];
        g_ptok[slot] = n;
        g_pw[slot] = g_tw[2 * n + i];
    }
}

// ===================== expert GEMM1 (mma.sync, fp16-split, dual gate+up) =====================
// CTA: 128 tokens x 64 f-cols (gate AND up). K=1024, chunks of 32. 8 warps (4 M x 2 N).
// smem stage layout (80B row stride): A_hi(128x32)@0, A_lo@10240, B_hi(gate64+up64)@20480, B_lo@30720
#define G1_STAGE 40960
#define G1_SMEM (1024 + 2 * G1_STAGE)

__global__ __launch_bounds__(256, 2) void moe_gemm1() {
    extern __shared__ char sm[];
    int e = blockIdx.z;
    int cnt = g_cnt[e];
    int r0 = blockIdx.x * 128;
    if (r0 >= cnt) return;
    int off = g_off[e];
    int f0 = blockIdx.y * 64;
    int tid = threadIdx.x, lane = tid & 31, wid = tid >> 5;
    int wy = wid & 3, wx = wid >> 2;

    int* stok = (int*)sm;
    if (tid < 128) {
        int lr = r0 + tid; if (lr >= cnt) lr = cnt - 1;
        stok[tid] = g_ptok[off + lr];
    }
    __syncthreads();

    uint32_t sb0 = smem_u32(sm) + 1024;

    // per-thread 8 cp.async segments
    uint32_t sdst[8];
    const char* gsrc[8];
#pragma unroll
    for (int j = 0; j < 8; j++) {
        int sid = tid + 256 * j;
        int region = sid >> 9;
        int rid = sid & 511;
        int row = rid >> 2, seg = rid & 3;
        sdst[j] = (uint32_t)(region * 10240 + row * 80 + seg * 16);
        const unsigned short* g;
        if (region == 0)      g = g_xh + (size_t)stok[row] * Dd;
        else if (region == 1) g = g_xl + (size_t)stok[row] * Dd;
        else if (region == 2) g = (row < 64) ? g_WgH + ((size_t)e * Ff + f0 + row) * Dd
                                             : g_WuH + ((size_t)e * Ff + f0 + row - 64) * Dd;
        else                  g = (row < 64) ? g_WgL + ((size_t)e * Ff + f0 + row) * Dd
                                             : g_WuL + ((size_t)e * Ff + f0 + row - 64) * Dd;
        gsrc[j] = (const char*)(g + seg * 8);
    }

    float accG[2][4][4], accU[2][4][4];
#pragma unroll
    for (int a = 0; a < 2; a++)
#pragma unroll
        for (int b = 0; b < 4; b++)
#pragma unroll
            for (int c = 0; c < 4; c++) { accG[a][b][c] = 0.f; accU[a][b][c] = 0.f; }

    uint32_t aoff = (uint32_t)((wy * 32 + (lane & 15)) * 80 + (lane >> 4) * 16);
    uint32_t boff = (uint32_t)((wx * 32 + ((lane & 7) | ((lane >> 4) << 3))) * 80 + ((lane >> 3) & 1) * 16);

    // prologue
#pragma unroll
    for (int j = 0; j < 8; j++) CPASYNC16(sb0 + sdst[j], gsrc[j]);
    CP_COMMIT();

    const int NCH = 32;
    for (int ch = 0; ch < NCH; ch++) {
        if (ch + 1 < NCH) {
            uint32_t sbn = sb0 + ((ch + 1) & 1) * G1_STAGE;
            int cb = (ch + 1) * 64;
#pragma unroll
            for (int j = 0; j < 8; j++) CPASYNC16(sbn + sdst[j], gsrc[j] + cb);
            CP_COMMIT();
            CP_WAIT(1);
        } else {
            CP_WAIT(0);
        }
        __syncthreads();
        uint32_t s = sb0 + (ch & 1) * G1_STAGE;
#pragma unroll
        for (int k16 = 0; k16 < 2; k16++) {
            uint32_t kb = k16 * 32;
            uint32_t ah[2][4], al[2][4], bh[2][4], bu[2][4];
#pragma unroll
            for (int mt = 0; mt < 2; mt++) {
                LDSM4(ah[mt], s + aoff + mt * (16 * 80) + kb);
                LDSM4(al[mt], s + 10240 + aoff + mt * (16 * 80) + kb);
            }
#pragma unroll
            for (int nt = 0; nt < 2; nt++) {
                LDSM4(bh[nt], s + 20480 + boff + nt * (16 * 80) + kb);
                LDSM4(bu[nt], s + 20480 + 5120 + boff + nt * (16 * 80) + kb);
            }
#pragma unroll
            for (int mt = 0; mt < 2; mt++)
#pragma unroll
                for (int nt = 0; nt < 2; nt++)
#pragma unroll
                    for (int h = 0; h < 2; h++) {
                        MMA16816(accG[mt][nt * 2 + h], ah[mt], bh[nt][2 * h], bh[nt][2 * h + 1]);
                        MMA16816(accG[mt][nt * 2 + h], al[mt], bh[nt][2 * h], bh[nt][2 * h + 1]);
                        MMA16816(accU[mt][nt * 2 + h], ah[mt], bu[nt][2 * h], bu[nt][2 * h + 1]);
                        MMA16816(accU[mt][nt * 2 + h], al[mt], bu[nt][2 * h], bu[nt][2 * h + 1]);
                    }
            // B lo
#pragma unroll
            for (int nt = 0; nt < 2; nt++) {
                LDSM4(bh[nt], s + 30720 + boff + nt * (16 * 80) + kb);
                LDSM4(bu[nt], s + 30720 + 5120 + boff + nt * (16 * 80) + kb);
            }
#pragma unroll
            for (int mt = 0; mt < 2; mt++)
#pragma unroll
                for (int nt = 0; nt < 2; nt++)
#pragma unroll
                    for (int h = 0; h < 2; h++) {
                        MMA16816(accG[mt][nt * 2 + h], ah[mt], bh[nt][2 * h], bh[nt][2 * h + 1]);
                        MMA16816(accU[mt][nt * 2 + h], ah[mt], bu[nt][2 * h], bu[nt][2 * h + 1]);
                    }
        }
        __syncthreads();
    }

    // epilogue: H = silu(g)*u, store fp16 hi/lo
#pragma unroll
    for (int mt = 0; mt < 2; mt++)
#pragma unroll
        for (int rh = 0; rh < 2; rh++) {
            int lr = wy * 32 + mt * 16 + (lane >> 2) + rh * 8;
            if (r0 + lr < cnt) {
                int slot = off + r0 + lr;
#pragma unroll
                for (int nt8 = 0; nt8 < 4; nt8++) {
                    int col = f0 + wx * 32 + nt8 * 8 + (lane & 3) * 2;
                    float g0 = accG[mt][nt8][rh * 2 + 0], g1 = accG[mt][nt8][rh * 2 + 1];
                    float u0 = accU[mt][nt8][rh * 2 + 0], u1 = accU[mt][nt8][rh * 2 + 1];
                    float h0 = g0 / (1.f + __expf(-g0)) * u0;
                    float h1 = g1 / (1.f + __expf(-g1)) * u1;
                    unsigned short a0, b0, a1, b1;
                    f2h_split(h0, a0, b0);
                    f2h_split(h1, a1, b1);
                    size_t idx = ((size_t)slot * Ff + col) >> 1;
                    ((uint32_t*)g_Hh)[idx] = (uint32_t)a0 | ((uint32_t)a1 << 16);
                    ((uint32_t*)g_Hl)[idx] = (uint32_t)b0 | ((uint32_t)b1 << 16);
                }
            }
        }
}

// ===================== expert GEMM2 (mma.sync, fp16-split) =====================
// CTA: 128 slots x 64 d-cols. K=2816, 88 chunks. smem: A_hi@0, A_lo@10240, B_hi@20480(5120), B_lo@25600
#define G2_STAGE 30720
#define G2_SMEM (2 * G2_STAGE)

__global__ __launch_bounds__(256, 2) void moe_gemm2(float* __restrict__ out) {
    extern __shared__ char sm[];
    int e = blockIdx.z;
    int cnt = g_cnt[e];
    int r0 = blockIdx.x * 128;
    if (r0 >= cnt) return;
    int off = g_off[e];
    int d0 = blockIdx.y * 64;
    int tid = threadIdx.x, lane = tid & 31, wid = tid >> 5;
    int wy = wid & 3, wx = wid >> 2;

    uint32_t sb0 = smem_u32(sm);

    uint32_t sdst[6];
    const char* gsrc[6];
#pragma unroll
    for (int j = 0; j < 6; j++) {
        int sid = tid + 256 * j;
        const unsigned short* g;
        uint32_t so;
        if (sid < 1024) {
            int hl = sid >> 9;
            int rid = sid & 511;
            int row = rid >> 2, seg = rid & 3;
            so = hl * 10240u + row * 80u + seg * 16u;
            int lr = r0 + row; if (lr >= cnt) lr = cnt - 1;
            g = (hl == 0 ? g_Hh : g_Hl) + (size_t)(off + lr) * Ff + seg * 8;
        } else {
            int rid = sid - 1024;
            int hl = rid >> 8;
            int row = (rid & 255) >> 2, seg = rid & 3;
            so = 20480u + hl * 5120u + row * 80u + seg * 16u;
            g = (hl == 0 ? g_WdH : g_WdL) + ((size_t)e * Dd + d0 + row) * Ff + seg * 8;
        }
        sdst[j] = so;
        gsrc[j] = (const char*)g;
    }

    float acc[2][4][4];
#pragma unroll
    for (int a = 0; a < 2; a++)
#pragma unroll
        for (int b = 0; b < 4; b++)
#pragma unroll
            for (int c = 0; c < 4; c++) acc[a][b][c] = 0.f;

    uint32_t aoff = (uint32_t)((wy * 32 + (lane & 15)) * 80 + (lane >> 4) * 16);
    uint32_t boff = (uint32_t)((wx * 32 + ((lane & 7) | ((lane >> 4) << 3))) * 80 + ((lane >> 3) & 1) * 16);

#pragma unroll
    for (int j = 0; j < 6; j++) CPASYNC16(sb0 + sdst[j], gsrc[j]);
    CP_COMMIT();

    const int NCH = 88;
    for (int ch = 0; ch < NCH; ch++) {
        if (ch + 1 < NCH) {
            uint32_t sbn = sb0 + ((ch + 1) & 1) * G2_STAGE;
            int cb = (ch + 1) * 64;
#pragma unroll
            for (int j = 0; j < 6; j++) CPASYNC16(sbn + sdst[j], gsrc[j] + cb);
            CP_COMMIT();
            CP_WAIT(1);
        } else {
            CP_WAIT(0);
        }
        __syncthreads();
        uint32_t s = sb0 + (ch & 1) * G2_STAGE;
#pragma unroll
        for (int k16 = 0; k16 < 2; k16++) {
            uint32_t kb = k16 * 32;
            uint32_t ah[2][4], al[2][4], bf[2][4];
#pragma unroll
            for (int mt = 0; mt < 2; mt++) {
                LDSM4(ah[mt], s + aoff + mt * (16 * 80) + kb);
                LDSM4(al[mt], s + 10240 + aoff + mt * (16 * 80) + kb);
            }
#pragma unroll
            for (int nt = 0; nt < 2; nt++) LDSM4(bf[nt], s + 20480 + boff + nt * (16 * 80) + kb);
#pragma unroll
            for (int mt = 0; mt < 2; mt++)
#pragma unroll
                for (int nt = 0; nt < 2; nt++)
#pragma unroll
                    for (int h = 0; h < 2; h++) {
                        MMA16816(acc[mt][nt * 2 + h], ah[mt], bf[nt][2 * h], bf[nt][2 * h + 1]);
                        MMA16816(acc[mt][nt * 2 + h], al[mt], bf[nt][2 * h], bf[nt][2 * h + 1]);
                    }
#pragma unroll
            for (int nt = 0; nt < 2; nt++) LDSM4(bf[nt], s + 25600 + boff + nt * (16 * 80) + kb);
#pragma unroll
            for (int mt = 0; mt < 2; mt++)
#pragma unroll
                for (int nt = 0; nt < 2; nt++)
#pragma unroll
                    for (int h = 0; h < 2; h++)
                        MMA16816(acc[mt][nt * 2 + h], ah[mt], bf[nt][2 * h], bf[nt][2 * h + 1]);
        }
        __syncthreads();
    }

#pragma unroll
    for (int mt = 0; mt < 2; mt++)
#pragma unroll
        for (int rh = 0; rh < 2; rh++) {
            int lr = wy * 32 + mt * 16 + (lane >> 2) + rh * 8;
            if (r0 + lr < cnt) {
                int slot = off + r0 + lr;
                int tok = g_ptok[slot];
                float w = g_pw[slot];
                float* op = out + (size_t)tok * Dd + d0 + wx * 32 + (lane & 3) * 2;
#pragma unroll
                for (int nt8 = 0; nt8 < 4; nt8++) {
                    atomicAdd(op + nt8 * 8,     acc[mt][nt8][rh * 2 + 0] * w);
                    atomicAdd(op + nt8 * 8 + 1, acc[mt][nt8][rh * 2 + 1] * w);
                }
            }
        }
}

// ===================== launch =====================
extern "C" void kernel_launch(void* const* d_in, const int* in_sizes, int n_in,
                              void* d_out, int out_size) {
    (void)in_sizes; (void)n_in;
    const float* x       = (const float*)d_in[0];
    const float* hist    = (const float*)d_in[1];
    const float* persona = (const float*)d_in[2];
    const float* W1x     = (const float*)d_in[3];
    const float* W1h     = (const float*)d_in[4];
    const float* W1p     = (const float*)d_in[5];
    const float* b1      = (const float*)d_in[6];
    const float* W2      = (const float*)d_in[7];
    const float* b2      = (const float*)d_in[8];
    const float* ln_g    = (const float*)d_in[9];
    const float* ln_b    = (const float*)d_in[10];
    const float* Wg      = (const float*)d_in[11];
    const float* bg      = (const float*)d_in[12];
    const float* Wgate   = (const float*)d_in[13];
    const float* Wup     = (const float*)d_in[14];
    const float* Wdown   = (const float*)d_in[15];
    const float* Ag      = (const float*)d_in[16];
    const float* Bg      = (const float*)d_in[17];
    const float* Au      = (const float*)d_in[18];
    const float* Bu      = (const float*)d_in[19];
    const float* Ad      = (const float*)d_in[20];
    const float* Bd      = (const float*)d_in[21];
    float* out = (float*)d_out;

    cudaFuncSetAttribute(moe_gemm1, cudaFuncAttributeMaxDynamicSharedMemorySize, G1_SMEM);
    cudaFuncSetAttribute(moe_gemm2, cudaFuncAttributeMaxDynamicSharedMemorySize, G2_SMEM);

    void* cntp = nullptr;
    cudaGetSymbolAddress(&cntp, g_cnt);

    cudaMemsetAsync(out, 0, (size_t)out_size * sizeof(float));
    cudaMemsetAsync(cntp, 0, Ee * sizeof(int));

    prep_kernel<<<13, 128>>>(hist, W1h, b1, persona, W1p, ln_g, ln_b, Wg, bg);
    xconv_kernel<<<(Nn * Dd) / 4 / 256, 256>>>(x);
    base_kernel<<<Nn / 64, 256>>>(x, W1x);
    merge_kernel<<<dim3(1056, Ee), 256>>>(Wgate, Wup, Wdown, Ag, Bg, Au, Bu, Ad, Bd);
    logits_kernel<<<dim3(Nn / 32, Ee), 256>>>(W2, b2);
    route_kernel<<<Nn / 256, 256>>>();
    scan_kernel<<<1, 1>>>();
    scatter_kernel<<<Nn / 256, 256>>>();
    moe_gemm1<<<dim3(NP / 128, Ff / 64, Ee), 256, G1_SMEM>>>();
    moe_gemm2<<<dim3(NP / 128, Dd / 64, Ee), 256, G2_SMEM>>>(out);
}

// round 4
// speedup vs baseline: 3.9068x; 1.4077x over previous
#include <cuda_runtime.h>
#include <cuda_fp16.h>
#include <math.h>
#include <stdint.h>

#define Bb 4
#define Ss 2048
#define Dd 1024
#define Hh 512
#define Ee 8
#define Ff 2816
#define Rr 16
#define HIDk 128
#define Nn 8192
#define NP 16384
#define LN_EPS 1e-5f

// ===================== baseline-PTX helpers =====================
__device__ __forceinline__ uint32_t smem_u32(const void* p) {
    uint32_t a;
    asm("{ .reg .u64 t; cvta.to.shared.u64 t, %1; cvt.u32.u64 %0, t; }" : "=r"(a) : "l"(p));
    return a;
}

#define CPASYNC16(dst, src) \
    asm volatile("cp.async.cg.shared.global [%0], [%1], 16;\n" :: "r"(dst), "l"(src))
#define CP_COMMIT() asm volatile("cp.async.commit_group;\n" ::: "memory")
#define CP_WAIT(N)  asm volatile("cp.async.wait_group %0;\n" :: "n"(N) : "memory")

#define LDSM4(R, addr) \
    asm volatile("ldmatrix.sync.aligned.m8n8.x4.shared.b16 {%0,%1,%2,%3}, [%4];" \
        : "=r"((R)[0]), "=r"((R)[1]), "=r"((R)[2]), "=r"((R)[3]) : "r"(addr))

#define MMA16816(C, A, B0, B1) \
    asm volatile("mma.sync.aligned.m16n8k16.row.col.f32.f16.f16.f32 " \
        "{%0,%1,%2,%3}, {%4,%5,%6,%7}, {%8,%9}, {%0,%1,%2,%3};" \
        : "+f"((C)[0]), "+f"((C)[1]), "+f"((C)[2]), "+f"((C)[3]) \
        : "r"((A)[0]), "r"((A)[1]), "r"((A)[2]), "r"((A)[3]), "r"(B0), "r"(B1))

__device__ __forceinline__ void f2h_split(float v, unsigned short& hi, unsigned short& lo) {
    __half h = __float2half_rn(v);
    hi = __half_as_ushort(h);
    lo = __half_as_ushort(__float2half_rn(v - __half2float(h)));
}

// ===================== static device scratch =====================
__device__ float g_base[Nn * HIDk];
__device__ float g_hb[Bb * HIDk];
__device__ float g_pk[Ee * HIDk];
__device__ float g_cgw[Dd];
__device__ float g_CgCb[2];
__device__ float g_logits[Nn * Ee];
__device__ int   g_cnt[Ee];
__device__ int   g_off[Ee];
__device__ int   g_te[Nn * 2];
__device__ int   g_tp[Nn * 2];
__device__ float g_tw[Nn * 2];
__device__ int   g_ptok[NP];
__device__ float g_pw[NP];
// fp16 hi/lo split storage
__device__ unsigned short g_xh[(size_t)Nn * Dd];
__device__ unsigned short g_xl[(size_t)Nn * Dd];
__device__ unsigned short g_WgH[(size_t)Ee * Ff * Dd];   // [e][f][d]  K-major (hi only)
__device__ unsigned short g_WuH[(size_t)Ee * Ff * Dd];
__device__ unsigned short g_WdH[(size_t)Ee * Dd * Ff];   // [e][d][f]  K-major
__device__ unsigned short g_WdL[(size_t)Ee * Dd * Ff];
__device__ unsigned short g_Hh[(size_t)NP * Ff];
__device__ unsigned short g_Hl[(size_t)NP * Ff];
__device__ unsigned short g_W2TH[(size_t)Dd * HIDk];     // W2^T [d][k] hi
__device__ unsigned short g_W2TL[(size_t)Dd * HIDk];     // lo

// ===================== prep =====================
__global__ void prep_kernel(const float* __restrict__ hist, const float* __restrict__ W1h,
                            const float* __restrict__ b1,
                            const float* __restrict__ persona, const float* __restrict__ W1p,
                            const float* __restrict__ ln_g, const float* __restrict__ ln_b,
                            const float* __restrict__ Wg, const float* __restrict__ bg) {
    int bx = blockIdx.x, tid = threadIdx.x;
    if (bx < 4) {
        float acc = b1[tid];
        const float* hr = hist + bx * Hh;
        for (int k = 0; k < Hh; k++) acc += hr[k] * W1h[k * HIDk + tid];
        g_hb[bx * HIDk + tid] = acc;
    } else if (bx < 12) {
        int e = bx - 4;
        float acc = 0.f;
        const float* pr = persona + e * Dd;
        for (int k = 0; k < Dd; k++) acc += pr[k] * W1p[k * HIDk + tid];
        g_pk[e * HIDk + tid] = acc;
    } else {
        __shared__ float sg[128], sb[128];
        float a = 0.f, b = 0.f;
        for (int d = tid; d < Dd; d += 128) {
            float w = Wg[d];
            float c = ln_g[d] * w;
            g_cgw[d] = c;
            a += c;
            b += ln_b[d] * w;
        }
        sg[tid] = a; sb[tid] = b;
        __syncthreads();
        for (int s = 64; s > 0; s >>= 1) {
            if (tid < s) { sg[tid] += sg[tid + s]; sb[tid] += sb[tid + s]; }
            __syncthreads();
        }
        if (tid == 0) { g_CgCb[0] = sg[0]; g_CgCb[1] = sb[0] + bg[0]; }
    }
}

// ===================== W2 -> W2^T fp16 hi/lo =====================
__global__ void w2t_kernel(const float* __restrict__ W2) {
    __shared__ float T[32][33];
    int d0 = blockIdx.x * 32, k0 = blockIdx.y * 32;
    int tid = threadIdx.x;
#pragma unroll
    for (int i = 0; i < 4; i++) {
        int kk = (tid >> 5) + i * 8, dd = tid & 31;
        T[kk][dd] = W2[(size_t)(k0 + kk) * Dd + d0 + dd];
    }
    __syncthreads();
#pragma unroll
    for (int i = 0; i < 4; i++) {
        int dd = (tid >> 5) + i * 8, kk = tid & 31;
        unsigned short hi, lo;
        f2h_split(T[kk][dd], hi, lo);
        g_W2TH[(size_t)(d0 + dd) * HIDk + k0 + kk] = hi;
        g_W2TL[(size_t)(d0 + dd) * HIDk + k0 + kk] = lo;
    }
}

// ===================== x -> fp16 hi/lo =====================
__global__ void xconv_kernel(const float* __restrict__ x) {
    size_t i = (size_t)blockIdx.x * 256 + threadIdx.x;
    float4 v = ((const float4*)x)[i];
    unsigned short h0, l0, h1, l1, h2, l2, h3, l3;
    f2h_split(v.x, h0, l0); f2h_split(v.y, h1, l1);
    f2h_split(v.z, h2, l2); f2h_split(v.w, h3, l3);
    uint2 ph = make_uint2((uint32_t)h0 | ((uint32_t)h1 << 16), (uint32_t)h2 | ((uint32_t)h3 << 16));
    uint2 pl = make_uint2((uint32_t)l0 | ((uint32_t)l1 << 16), (uint32_t)l2 | ((uint32_t)l3 << 16));
    *(uint2*)(g_xh + i * 4) = ph;
    *(uint2*)(g_xl + i * 4) = pl;
}

// ===================== base = x @ W1x + hb =====================
__global__ __launch_bounds__(256) void base_kernel(const float* __restrict__ x,
                                                   const float* __restrict__ W1x) {
    __shared__ float Xs[64][16];
    __shared__ float Ws[16][128];
    int tid = threadIdx.x;
    int n0 = blockIdx.x * 64;
    int tx = tid & 15, ty = tid >> 4;
    float acc[4][8];
#pragma unroll
    for (int i = 0; i < 4; i++)
#pragma unroll
        for (int j = 0; j < 8; j++) acc[i][j] = 0.f;

    for (int ks = 0; ks < 64; ks++) {
        int k0 = ks * 16;
        {
            int row = tid >> 2, kk = (tid & 3) * 4;
            *(float4*)&Xs[row][kk] = *(const float4*)(x + (size_t)(n0 + row) * Dd + k0 + kk);
        }
        {
            int kk = tid >> 4, j = (tid & 15) * 8;
            const float* s = W1x + (size_t)(k0 + kk) * HIDk + j;
            *(float4*)&Ws[kk][j]     = *(const float4*)s;
            *(float4*)&Ws[kk][j + 4] = *(const float4*)(s + 4);
        }
        __syncthreads();
#pragma unroll
        for (int kk = 0; kk < 16; kk++) {
            float4 w0 = *(float4*)&Ws[kk][tx * 8];
            float4 w1 = *(float4*)&Ws[kk][tx * 8 + 4];
#pragma unroll
            for (int i = 0; i < 4; i++) {
                float xv = Xs[ty * 4 + i][kk];
                acc[i][0] += xv * w0.x; acc[i][1] += xv * w0.y;
                acc[i][2] += xv * w0.z; acc[i][3] += xv * w0.w;
                acc[i][4] += xv * w1.x; acc[i][5] += xv * w1.y;
                acc[i][6] += xv * w1.z; acc[i][7] += xv * w1.w;
            }
        }
        __syncthreads();
    }
    int b = n0 >> 11;
    const float* hb = g_hb + b * HIDk + tx * 8;
#pragma unroll
    for (int i = 0; i < 4; i++) {
        int n = n0 + ty * 4 + i;
        float4 o0 = make_float4(acc[i][0] + hb[0], acc[i][1] + hb[1],
                                acc[i][2] + hb[2], acc[i][3] + hb[3]);
        float4 o1 = make_float4(acc[i][4] + hb[4], acc[i][5] + hb[5],
                                acc[i][6] + hb[6], acc[i][7] + hb[7]);
        *(float4*)&g_base[(size_t)n * HIDk + tx * 8]     = o0;
        *(float4*)&g_base[(size_t)n * HIDk + tx * 8 + 4] = o1;
    }
}

// ===================== merge: W' = W + A@B -> transposed fp16 (hi; +lo for down) =====================
__global__ __launch_bounds__(256) void merge_kernel(
    const float* __restrict__ Wgate, const float* __restrict__ Wup, const float* __restrict__ Wdown,
    const float* __restrict__ Ag, const float* __restrict__ Bg,
    const float* __restrict__ Au, const float* __restrict__ Bu,
    const float* __restrict__ Ad, const float* __restrict__ Bd) {
    __shared__ float As[128][17];
    __shared__ float Bs[16][65];
    __shared__ unsigned short Thi[64][136];
    __shared__ unsigned short Tlo[64][136];
    int e = blockIdx.y, t = blockIdx.x, tid = threadIdx.x;
    const float *src, *Ap, *Bp;
    unsigned short *dhi, *dlo;
    int r0, c0, rowStride, outStride;
    bool isDown = false;
    if (t < 352) {
        int kt = t / 44, ft = t % 44;
        r0 = kt * 128; c0 = ft * 64; rowStride = Ff; outStride = Dd;
        src = Wgate + (size_t)e * Dd * Ff; Ap = Ag + (size_t)e * Dd * Rr; Bp = Bg + (size_t)e * Rr * Ff;
        dhi = g_WgH + (size_t)e * Ff * Dd; dlo = nullptr;
    } else if (t < 704) {
        t -= 352;
        int kt = t / 44, ft = t % 44;
        r0 = kt * 128; c0 = ft * 64; rowStride = Ff; outStride = Dd;
        src = Wup + (size_t)e * Dd * Ff; Ap = Au + (size_t)e * Dd * Rr; Bp = Bu + (size_t)e * Rr * Ff;
        dhi = g_WuH + (size_t)e * Ff * Dd; dlo = nullptr;
    } else {
        t -= 704;
        int kt = t / 16, ft = t % 16;
        r0 = kt * 128; c0 = ft * 64; rowStride = Dd; outStride = Ff;
        src = Wdown + (size_t)e * Ff * Dd; Ap = Ad + (size_t)e * Ff * Rr; Bp = Bd + (size_t)e * Rr * Dd;
        dhi = g_WdH + (size_t)e * Dd * Ff; dlo = g_WdL + (size_t)e * Dd * Ff;
        isDown = true;
    }
    {
        int r = tid >> 1, k0 = (tid & 1) * 8;
#pragma unroll
        for (int kk = 0; kk < 8; kk++)
            As[r][k0 + kk] = Ap[(size_t)(r0 + r) * Rr + k0 + kk];
    }
    for (int i = tid; i < 1024; i += 256) {
        int k = i >> 6, c = i & 63;
        Bs[k][c] = Bp[(size_t)k * rowStride + c0 + c];
    }
    __syncthreads();
    {
        int c = tid & 63, rb = tid >> 6;
        float vbuf[32];
        for (int rr = 0; rr < 32; rr++) {
            int r = rb * 32 + rr;
            float v = src[(size_t)(r0 + r) * rowStride + c0 + c];
#pragma unroll
            for (int k = 0; k < 16; k++) v += As[r][k] * Bs[k][c];
            vbuf[rr] = v;
        }
        // rotated write to break bank conflicts (8-way -> ~2-way)
        for (int w = 0; w < 32; w++) {
            int rr = (w + c) & 31;
            int r = rb * 32 + rr;
            unsigned short hb_, lb_;
            f2h_split(vbuf[rr], hb_, lb_);
            Thi[c][r] = hb_;
            if (isDown) Tlo[c][r] = lb_;
        }
    }
    __syncthreads();
    {
        int c = tid >> 2, qq = tid & 3;
        const uint4* sh = (const uint4*)&Thi[c][qq * 32];
        uint4* dH = (uint4*)(dhi + (size_t)(c0 + c) * outStride + r0 + qq * 32);
#pragma unroll
        for (int m = 0; m < 4; m++) dH[m] = sh[m];
        if (isDown) {
            const uint4* sl = (const uint4*)&Tlo[c][qq * 32];
            uint4* dL = (uint4*)(dlo + (size_t)(c0 + c) * outStride + r0 + qq * 32);
#pragma unroll
            for (int m = 0; m < 4; m++) dL[m] = sl[m];
        }
    }
}

// ===================== fused gate logits via mma.sync =====================
// CTA: 64 tokens x 1 expert, loop 16 chunks of 64 d-cols; K=128. 8 warps (4M x 2N).
// A = relu(base+pk) fp16 hi/lo (pitch 272B). B = W2^T hi/lo double-buffered.
#define LG_AHI 0
#define LG_ALO 17408
#define LG_B0  34816
#define LG_BSTG 34816
#define LG_RED (LG_B0 + 2 * LG_BSTG)
#define LG_B2  (LG_RED + 768)
#define LG_CG  (LG_B2 + 4096)
#define LG_SMEM (LG_CG + 4096)

__global__ __launch_bounds__(256) void logits_kernel(const float* __restrict__ b2) {
    extern __shared__ char sm[];
    uint32_t sb = smem_u32(sm);
    int e = blockIdx.y, n0 = blockIdx.x * 64;
    int tid = threadIdx.x, lane = tid & 31, wid = tid >> 5;
    int wy = wid & 3, wx = wid >> 2;

    if (tid < 192) ((float*)(sm + LG_RED))[tid] = 0.f;
#pragma unroll
    for (int i = 0; i < 4; i++) {
        ((float*)(sm + LG_B2))[tid + 256 * i] = b2[tid + 256 * i];
        ((float*)(sm + LG_CG))[tid + 256 * i] = g_cgw[tid + 256 * i];
    }
    // A staging
    {
        int t = tid >> 2, kq = (tid & 3) * 32;
        const float4* bp = (const float4*)(g_base + (size_t)(n0 + t) * HIDk + kq);
        const float4* pp = (const float4*)(g_pk + e * HIDk + kq);
        unsigned short* ah = (unsigned short*)(sm + LG_AHI) + t * 136 + kq;
        unsigned short* al = (unsigned short*)(sm + LG_ALO) + t * 136 + kq;
#pragma unroll
        for (int q = 0; q < 8; q++) {
            float4 a = bp[q], p = pp[q];
            float v[4] = {fmaxf(a.x + p.x, 0.f), fmaxf(a.y + p.y, 0.f),
                          fmaxf(a.z + p.z, 0.f), fmaxf(a.w + p.w, 0.f)};
#pragma unroll
            for (int c = 0; c < 4; c++) {
                unsigned short hi, lo;
                f2h_split(v[c], hi, lo);
                ah[q * 4 + c] = hi;
                al[q * 4 + c] = lo;
            }
        }
    }
    // B prologue: chunk 0
    uint32_t sdst[8];
    uint32_t gofs[8];
    int ghl[8];
#pragma unroll
    for (int j = 0; j < 8; j++) {
        int sid = tid + 256 * j;
        int hl = sid >> 10;
        int rid = sid & 1023;
        int row = rid >> 4, seg = rid & 15;
        sdst[j] = (uint32_t)(hl * 17408 + row * 272 + seg * 16);
        gofs[j] = (uint32_t)(row * HIDk + seg * 8);
        ghl[j] = hl;
    }
#pragma unroll
    for (int j = 0; j < 8; j++) {
        const unsigned short* g = (ghl[j] ? g_W2TL : g_W2TH) + gofs[j];
        CPASYNC16(sb + LG_B0 + sdst[j], (const char*)g);
    }
    CP_COMMIT();
    __syncthreads();

    float s1[2] = {0.f, 0.f}, s2[2] = {0.f, 0.f}, s3[2] = {0.f, 0.f};
    uint32_t aoff = (uint32_t)((wy * 16 + (lane & 15)) * 272 + (lane >> 4) * 16);
    uint32_t boff = (uint32_t)(((wx * 32 + ((lane & 7) | ((lane >> 4) << 3))) * 272) + ((lane >> 3) & 1) * 16);

    for (int ch = 0; ch < 16; ch++) {
        if (ch + 1 < 16) {
            uint32_t stg = sb + LG_B0 + ((ch + 1) & 1) * LG_BSTG;
            uint32_t dadd = (uint32_t)((ch + 1) * 64 * HIDk);
#pragma unroll
            for (int j = 0; j < 8; j++) {
                const unsigned short* g = (ghl[j] ? g_W2TL : g_W2TH) + gofs[j] + dadd;
                CPASYNC16(stg + sdst[j], (const char*)g);
            }
            CP_COMMIT();
            CP_WAIT(1);
        } else {
            CP_WAIT(0);
        }
        __syncthreads();
        uint32_t sB = sb + LG_B0 + (ch & 1) * LG_BSTG;
        float acc[4][4];
#pragma unroll
        for (int a = 0; a < 4; a++)
#pragma unroll
            for (int c = 0; c < 4; c++) acc[a][c] = 0.f;
#pragma unroll
        for (int k16 = 0; k16 < 8; k16++) {
            uint32_t kb = (uint32_t)(k16 * 32);
            uint32_t ahr[4], alr[4], bh[2][4], bl[2][4];
            LDSM4(ahr, sb + LG_AHI + aoff + kb);
            LDSM4(alr, sb + LG_ALO + aoff + kb);
            LDSM4(bh[0], sB + boff + kb);
            LDSM4(bh[1], sB + boff + 16 * 272 + kb);
            LDSM4(bl[0], sB + 17408 + boff + kb);
            LDSM4(bl[1], sB + 17408 + boff + 16 * 272 + kb);
#pragma unroll
            for (int nt = 0; nt < 2; nt++)
#pragma unroll
                for (int h = 0; h < 2; h++) {
                    MMA16816(acc[nt * 2 + h], ahr, bh[nt][2 * h], bh[nt][2 * h + 1]);
                    MMA16816(acc[nt * 2 + h], alr, bh[nt][2 * h], bh[nt][2 * h + 1]);
                    MMA16816(acc[nt * 2 + h], ahr, bl[nt][2 * h], bl[nt][2 * h + 1]);
                }
        }
        // reduce chunk into s1/s2/s3
#pragma unroll
        for (int nt4 = 0; nt4 < 4; nt4++) {
            int col = ch * 64 + wx * 32 + nt4 * 8 + (lane & 3) * 2;
            float b0 = ((float*)(sm + LG_B2))[col], b1v = ((float*)(sm + LG_B2))[col + 1];
            float c0 = ((float*)(sm + LG_CG))[col], c1v = ((float*)(sm + LG_CG))[col + 1];
            float f;
            f = fmaxf(acc[nt4][0] + b0, 0.f);  s1[0] += f * c0;  s2[0] += f; s3[0] += f * f;
            f = fmaxf(acc[nt4][1] + b1v, 0.f); s1[0] += f * c1v; s2[0] += f; s3[0] += f * f;
            f = fmaxf(acc[nt4][2] + b0, 0.f);  s1[1] += f * c0;  s2[1] += f; s3[1] += f * f;
            f = fmaxf(acc[nt4][3] + b1v, 0.f); s1[1] += f * c1v; s2[1] += f; s3[1] += f * f;
        }
        __syncthreads();
    }
#pragma unroll
    for (int off = 1; off <= 2; off <<= 1) {
#pragma unroll
        for (int i = 0; i < 2; i++) {
            s1[i] += __shfl_xor_sync(0xffffffffu, s1[i], off);
            s2[i] += __shfl_xor_sync(0xffffffffu, s2[i], off);
            s3[i] += __shfl_xor_sync(0xffffffffu, s3[i], off);
        }
    }
    if ((lane & 3) == 0) {
        int row = wy * 16 + (lane >> 2);
        float* red = (float*)(sm + LG_RED);
        atomicAdd(&red[row],           s1[0]);
        atomicAdd(&red[row + 8],       s1[1]);
        atomicAdd(&red[64 + row],      s2[0]);
        atomicAdd(&red[64 + row + 8],  s2[1]);
        atomicAdd(&red[128 + row],     s3[0]);
        atomicAdd(&red[128 + row + 8], s3[1]);
    }
    __syncthreads();
    if (tid < 64) {
        float* red = (float*)(sm + LG_RED);
        float S1 = red[tid], S2 = red[64 + tid], S3 = red[128 + tid];
        float Cg = g_CgCb[0], Cb = g_CgCb[1];
        float mu = S2 * (1.f / (float)Dd);
        float var = S3 * (1.f / (float)Dd) - mu * mu;
        float rstd = rsqrtf(var + LN_EPS);
        g_logits[(size_t)(n0 + tid) * Ee + e] = rstd * (S1 - mu * Cg) + Cb;
    }
}

// ===================== routing =====================
__global__ void route_kernel() {
    int n = blockIdx.x * 256 + threadIdx.x;
    float l[Ee];
    float m = -1e30f;
#pragma unroll
    for (int e = 0; e < Ee; e++) { l[e] = g_logits[(size_t)n * Ee + e]; m = fmaxf(m, l[e]); }
    float s = 0.f;
#pragma unroll
    for (int e = 0; e < Ee; e++) { l[e] = expf(l[e] - m); s += l[e]; }
    float inv = 1.f / s;
#pragma unroll
    for (int e = 0; e < Ee; e++) l[e] *= inv;
    int i0 = 0; float b0 = l[0];
#pragma unroll
    for (int e = 1; e < Ee; e++) if (l[e] > b0) { b0 = l[e]; i0 = e; }
    int i1 = -1; float b1 = -1.f;
#pragma unroll
    for (int e = 0; e < Ee; e++) if (e != i0 && l[e] > b1) { b1 = l[e]; i1 = e; }
    int p0 = atomicAdd(&g_cnt[i0], 1);
    int p1 = atomicAdd(&g_cnt[i1], 1);
    g_te[2 * n] = i0; g_tp[2 * n] = p0; g_tw[2 * n] = b0;
    g_te[2 * n + 1] = i1; g_tp[2 * n + 1] = p1; g_tw[2 * n + 1] = b1;
}

__global__ void scan_kernel() {
    int a = 0;
    for (int e = 0; e < Ee; e++) { g_off[e] = a; a += g_cnt[e]; }
}

__global__ void scatter_kernel() {
    int n = blockIdx.x * 256 + threadIdx.x;
#pragma unroll
    for (int i = 0; i < 2; i++) {
        int slot = g_off[g_te[2 * n + i]] + g_tp[2 * n + i];
        g_ptok[slot] = n;
        g_pw[slot] = g_tw[2 * n + i];
    }
}

// ===================== expert GEMM1 (2-term split: AhBh + AlBh) =====================
// CTA: 128 tokens x 64 f-cols (gate AND up). K=1024, chunks of 32. 8 warps (4M x 2N).
// stage (80B pitch): A_hi@0 (10240), A_lo@10240, B_hi(g64+u64)@20480 (10240)
#define G1_STAGE 30720
#define G1_SMEM (1024 + 2 * G1_STAGE)

__global__ __launch_bounds__(256, 2) void moe_gemm1() {
    extern __shared__ char sm[];
    int e = blockIdx.z;
    int cnt = g_cnt[e];
    int r0 = blockIdx.x * 128;
    if (r0 >= cnt) return;
    int off = g_off[e];
    int f0 = blockIdx.y * 64;
    int tid = threadIdx.x, lane = tid & 31, wid = tid >> 5;
    int wy = wid & 3, wx = wid >> 2;

    int* stok = (int*)sm;
    if (tid < 128) {
        int lr = r0 + tid; if (lr >= cnt) lr = cnt - 1;
        stok[tid] = g_ptok[off + lr];
    }
    __syncthreads();

    uint32_t sb0 = smem_u32(sm) + 1024;

    uint32_t sdst[6];
    const char* gsrc[6];
#pragma unroll
    for (int j = 0; j < 6; j++) {
        int sid = tid + 256 * j;        // 0..1535
        int region = sid >> 9;
        int rid = sid & 511;
        int row = rid >> 2, seg = rid & 3;
        sdst[j] = (uint32_t)(region * 10240 + row * 80 + seg * 16);
        const unsigned short* g;
        if (region == 0)      g = g_xh + (size_t)stok[row] * Dd;
        else if (region == 1) g = g_xl + (size_t)stok[row] * Dd;
        else                  g = (row < 64) ? g_WgH + ((size_t)e * Ff + f0 + row) * Dd
                                             : g_WuH + ((size_t)e * Ff + f0 + row - 64) * Dd;
        gsrc[j] = (const char*)(g + seg * 8);
    }

    float accG[2][4][4], accU[2][4][4];
#pragma unroll
    for (int a = 0; a < 2; a++)
#pragma unroll
        for (int b = 0; b < 4; b++)
#pragma unroll
            for (int c = 0; c < 4; c++) { accG[a][b][c] = 0.f; accU[a][b][c] = 0.f; }

    uint32_t aoff = (uint32_t)((wy * 32 + (lane & 15)) * 80 + (lane >> 4) * 16);
    uint32_t boff = (uint32_t)((wx * 32 + ((lane & 7) | ((lane >> 4) << 3))) * 80 + ((lane >> 3) & 1) * 16);

#pragma unroll
    for (int j = 0; j < 6; j++) CPASYNC16(sb0 + sdst[j], gsrc[j]);
    CP_COMMIT();

    const int NCH = 32;
    for (int ch = 0; ch < NCH; ch++) {
        if (ch + 1 < NCH) {
            uint32_t sbn = sb0 + ((ch + 1) & 1) * G1_STAGE;
            int cb = (ch + 1) * 64;
#pragma unroll
            for (int j = 0; j < 6; j++) CPASYNC16(sbn + sdst[j], gsrc[j] + cb);
            CP_COMMIT();
            CP_WAIT(1);
        } else {
            CP_WAIT(0);
        }
        __syncthreads();
        uint32_t s = sb0 + (ch & 1) * G1_STAGE;
#pragma unroll
        for (int k16 = 0; k16 < 2; k16++) {
            uint32_t kb = k16 * 32;
            uint32_t ah[2][4], al[2][4], bg[2][4], bu[2][4];
#pragma unroll
            for (int mt = 0; mt < 2; mt++) {
                LDSM4(ah[mt], s + aoff + mt * (16 * 80) + kb);
                LDSM4(al[mt], s + 10240 + aoff + mt * (16 * 80) + kb);
            }
#pragma unroll
            for (int nt = 0; nt < 2; nt++) {
                LDSM4(bg[nt], s + 20480 + boff + nt * (16 * 80) + kb);
                LDSM4(bu[nt], s + 20480 + 5120 + boff + nt * (16 * 80) + kb);
            }
#pragma unroll
            for (int mt = 0; mt < 2; mt++)
#pragma unroll
                for (int nt = 0; nt < 2; nt++)
#pragma unroll
                    for (int h = 0; h < 2; h++) {
                        MMA16816(accG[mt][nt * 2 + h], ah[mt], bg[nt][2 * h], bg[nt][2 * h + 1]);
                        MMA16816(accG[mt][nt * 2 + h], al[mt], bg[nt][2 * h], bg[nt][2 * h + 1]);
                        MMA16816(accU[mt][nt * 2 + h], ah[mt], bu[nt][2 * h], bu[nt][2 * h + 1]);
                        MMA16816(accU[mt][nt * 2 + h], al[mt], bu[nt][2 * h], bu[nt][2 * h + 1]);
                    }
        }
        __syncthreads();
    }

#pragma unroll
    for (int mt = 0; mt < 2; mt++)
#pragma unroll
        for (int rh = 0; rh < 2; rh++) {
            int lr = wy * 32 + mt * 16 + (lane >> 2) + rh * 8;
            if (r0 + lr < cnt) {
                int slot = off + r0 + lr;
#pragma unroll
                for (int nt8 = 0; nt8 < 4; nt8++) {
                    int col = f0 + wx * 32 + nt8 * 8 + (lane & 3) * 2;
                    float g0 = accG[mt][nt8][rh * 2 + 0], g1 = accG[mt][nt8][rh * 2 + 1];
                    float u0 = accU[mt][nt8][rh * 2 + 0], u1 = accU[mt][nt8][rh * 2 + 1];
                    float h0 = g0 / (1.f + __expf(-g0)) * u0;
                    float h1 = g1 / (1.f + __expf(-g1)) * u1;
                    unsigned short a0, b0, a1, b1;
                    f2h_split(h0, a0, b0);
                    f2h_split(h1, a1, b1);
                    size_t idx = ((size_t)slot * Ff + col) >> 1;
                    ((uint32_t*)g_Hh)[idx] = (uint32_t)a0 | ((uint32_t)a1 << 16);
                    ((uint32_t*)g_Hl)[idx] = (uint32_t)b0 | ((uint32_t)b1 << 16);
                }
            }
        }
}

// ===================== expert GEMM2 (3-term split) =====================
#define G2_STAGE 30720
#define G2_SMEM (2 * G2_STAGE)

__global__ __launch_bounds__(256, 2) void moe_gemm2(float* __restrict__ out) {
    extern __shared__ char sm[];
    int e = blockIdx.z;
    int cnt = g_cnt[e];
    int r0 = blockIdx.x * 128;
    if (r0 >= cnt) return;
    int off = g_off[e];
    int d0 = blockIdx.y * 64;
    int tid = threadIdx.x, lane = tid & 31, wid = tid >> 5;
    int wy = wid & 3, wx = wid >> 2;

    uint32_t sb0 = smem_u32(sm);

    uint32_t sdst[6];
    const char* gsrc[6];
#pragma unroll
    for (int j = 0; j < 6; j++) {
        int sid = tid + 256 * j;
        const unsigned short* g;
        uint32_t so;
        if (sid < 1024) {
            int hl = sid >> 9;
            int rid = sid & 511;
            int row = rid >> 2, seg = rid & 3;
            so = hl * 10240u + row * 80u + seg * 16u;
            int lr = r0 + row; if (lr >= cnt) lr = cnt - 1;
            g = (hl == 0 ? g_Hh : g_Hl) + (size_t)(off + lr) * Ff + seg * 8;
        } else {
            int rid = sid - 1024;
            int hl = rid >> 8;
            int row = (rid & 255) >> 2, seg = rid & 3;
            so = 20480u + hl * 5120u + row * 80u + seg * 16u;
            g = (hl == 0 ? g_WdH : g_WdL) + ((size_t)e * Dd + d0 + row) * Ff + seg * 8;
        }
        sdst[j] = so;
        gsrc[j] = (const char*)g;
    }

    float acc[2][4][4];
#pragma unroll
    for (int a = 0; a < 2; a++)
#pragma unroll
        for (int b = 0; b < 4; b++)
#pragma unroll
            for (int c = 0; c < 4; c++) acc[a][b][c] = 0.f;

    uint32_t aoff = (uint32_t)((wy * 32 + (lane & 15)) * 80 + (lane >> 4) * 16);
    uint32_t boff = (uint32_t)((wx * 32 + ((lane & 7) | ((lane >> 4) << 3))) * 80 + ((lane >> 3) & 1) * 16);

#pragma unroll
    for (int j = 0; j < 6; j++) CPASYNC16(sb0 + sdst[j], gsrc[j]);
    CP_COMMIT();

    const int NCH = 88;
    for (int ch = 0; ch < NCH; ch++) {
        if (ch + 1 < NCH) {
            uint32_t sbn = sb0 + ((ch + 1) & 1) * G2_STAGE;
            int cb = (ch + 1) * 64;
#pragma unroll
            for (int j = 0; j < 6; j++) CPASYNC16(sbn + sdst[j], gsrc[j] + cb);
            CP_COMMIT();
            CP_WAIT(1);
        } else {
            CP_WAIT(0);
        }
        __syncthreads();
        uint32_t s = sb0 + (ch & 1) * G2_STAGE;
#pragma unroll
        for (int k16 = 0; k16 < 2; k16++) {
            uint32_t kb = k16 * 32;
            uint32_t ah[2][4], al[2][4], bf[2][4];
#pragma unroll
            for (int mt = 0; mt < 2; mt++) {
                LDSM4(ah[mt], s + aoff + mt * (16 * 80) + kb);
                LDSM4(al[mt], s + 10240 + aoff + mt * (16 * 80) + kb);
            }
#pragma unroll
            for (int nt = 0; nt < 2; nt++) LDSM4(bf[nt], s + 20480 + boff + nt * (16 * 80) + kb);
#pragma unroll
            for (int mt = 0; mt < 2; mt++)
#pragma unroll
                for (int nt = 0; nt < 2; nt++)
#pragma unroll
                    for (int h = 0; h < 2; h++) {
                        MMA16816(acc[mt][nt * 2 + h], ah[mt], bf[nt][2 * h], bf[nt][2 * h + 1]);
                        MMA16816(acc[mt][nt * 2 + h], al[mt], bf[nt][2 * h], bf[nt][2 * h + 1]);
                    }
#pragma unroll
            for (int nt = 0; nt < 2; nt++) LDSM4(bf[nt], s + 25600 + boff + nt * (16 * 80) + kb);
#pragma unroll
            for (int mt = 0; mt < 2; mt++)
#pragma unroll
                for (int nt = 0; nt < 2; nt++)
#pragma unroll
                    for (int h = 0; h < 2; h++)
                        MMA16816(acc[mt][nt * 2 + h], ah[mt], bf[nt][2 * h], bf[nt][2 * h + 1]);
        }
        __syncthreads();
    }

#pragma unroll
    for (int mt = 0; mt < 2; mt++)
#pragma unroll
        for (int rh = 0; rh < 2; rh++) {
            int lr = wy * 32 + mt * 16 + (lane >> 2) + rh * 8;
            if (r0 + lr < cnt) {
                int slot = off + r0 + lr;
                int tok = g_ptok[slot];
                float w = g_pw[slot];
                float* op = out + (size_t)tok * Dd + d0 + wx * 32 + (lane & 3) * 2;
#pragma unroll
                for (int nt8 = 0; nt8 < 4; nt8++) {
                    atomicAdd(op + nt8 * 8,     acc[mt][nt8][rh * 2 + 0] * w);
                    atomicAdd(op + nt8 * 8 + 1, acc[mt][nt8][rh * 2 + 1] * w);
                }
            }
        }
}

// ===================== launch =====================
extern "C" void kernel_launch(void* const* d_in, const int* in_sizes, int n_in,
                              void* d_out, int out_size) {
    (void)in_sizes; (void)n_in;
    const float* x       = (const float*)d_in[0];
    const float* hist    = (const float*)d_in[1];
    const float* persona = (const float*)d_in[2];
    const float* W1x     = (const float*)d_in[3];
    const float* W1h     = (const float*)d_in[4];
    const float* W1p     = (const float*)d_in[5];
    const float* b1      = (const float*)d_in[6];
    const float* W2      = (const float*)d_in[7];
    const float* b2      = (const float*)d_in[8];
    const float* ln_g    = (const float*)d_in[9];
    const float* ln_b    = (const float*)d_in[10];
    const float* Wg      = (const float*)d_in[11];
    const float* bg      = (const float*)d_in[12];
    const float* Wgate   = (const float*)d_in[13];
    const float* Wup     = (const float*)d_in[14];
    const float* Wdown   = (const float*)d_in[15];
    const float* Ag      = (const float*)d_in[16];
    const float* Bg      = (const float*)d_in[17];
    const float* Au      = (const float*)d_in[18];
    const float* Bu      = (const float*)d_in[19];
    const float* Ad      = (const float*)d_in[20];
    const float* Bd      = (const float*)d_in[21];
    float* out = (float*)d_out;

    cudaFuncSetAttribute(moe_gemm1, cudaFuncAttributeMaxDynamicSharedMemorySize, G1_SMEM);
    cudaFuncSetAttribute(moe_gemm2, cudaFuncAttributeMaxDynamicSharedMemorySize, G2_SMEM);
    cudaFuncSetAttribute(logits_kernel, cudaFuncAttributeMaxDynamicSharedMemorySize, LG_SMEM);

    void* cntp = nullptr;
    cudaGetSymbolAddress(&cntp, g_cnt);

    cudaMemsetAsync(out, 0, (size_t)out_size * sizeof(float));
    cudaMemsetAsync(cntp, 0, Ee * sizeof(int));

    prep_kernel<<<13, 128>>>(hist, W1h, b1, persona, W1p, ln_g, ln_b, Wg, bg);
    w2t_kernel<<<dim3(Dd / 32, HIDk / 32), 256>>>(W2);
    xconv_kernel<<<(Nn * Dd) / 4 / 256, 256>>>(x);
    base_kernel<<<Nn / 64, 256>>>(x, W1x);
    merge_kernel<<<dim3(1056, Ee), 256>>>(Wgate, Wup, Wdown, Ag, Bg, Au, Bu, Ad, Bd);
    logits_kernel<<<dim3(Nn / 64, Ee), 256, LG_SMEM>>>(b2);
    route_kernel<<<Nn / 256, 256>>>();
    scan_kernel<<<1, 1>>>();
    scatter_kernel<<<Nn / 256, 256>>>();
    moe_gemm1<<<dim3(NP / 128, Ff / 64, Ee), 256, G1_SMEM>>>();
    moe_gemm2<<<dim3(NP / 128, Dd / 64, Ee), 256, G2_SMEM>>>(out);
}

// round 5
// speedup vs baseline: 4.5518x; 1.1651x over previous
#include <cuda_runtime.h>
#include <cuda_fp16.h>
#include <math.h>
#include <stdint.h>

#define Bb 4
#define Ss 2048
#define Dd 1024
#define Hh 512
#define Ee 8
#define Ff 2816
#define Rr 16
#define HIDk 128
#define Nn 8192
#define NP 16384
#define LN_EPS 1e-5f

// ===================== baseline-PTX helpers =====================
__device__ __forceinline__ uint32_t smem_u32(const void* p) {
    uint32_t a;
    asm("{ .reg .u64 t; cvta.to.shared.u64 t, %1; cvt.u32.u64 %0, t; }" : "=r"(a) : "l"(p));
    return a;
}

#define CPASYNC16(dst, src) \
    asm volatile("cp.async.cg.shared.global [%0], [%1], 16;\n" :: "r"(dst), "l"(src))
#define CP_COMMIT() asm volatile("cp.async.commit_group;\n" ::: "memory")
#define CP_WAIT(N)  asm volatile("cp.async.wait_group %0;\n" :: "n"(N) : "memory")

#define LDSM4(R, addr) \
    asm volatile("ldmatrix.sync.aligned.m8n8.x4.shared.b16 {%0,%1,%2,%3}, [%4];" \
        : "=r"((R)[0]), "=r"((R)[1]), "=r"((R)[2]), "=r"((R)[3]) : "r"(addr))

#define MMA16816(C, A, B0, B1) \
    asm volatile("mma.sync.aligned.m16n8k16.row.col.f32.f16.f16.f32 " \
        "{%0,%1,%2,%3}, {%4,%5,%6,%7}, {%8,%9}, {%0,%1,%2,%3};" \
        : "+f"((C)[0]), "+f"((C)[1]), "+f"((C)[2]), "+f"((C)[3]) \
        : "r"((A)[0]), "r"((A)[1]), "r"((A)[2]), "r"((A)[3]), "r"(B0), "r"(B1))

__device__ __forceinline__ void f2h_split(float v, unsigned short& hi, unsigned short& lo) {
    __half h = __float2half_rn(v);
    hi = __half_as_ushort(h);
    lo = __half_as_ushort(__float2half_rn(v - __half2float(h)));
}

// ===================== static device scratch =====================
__device__ float g_base[Nn * HIDk];
__device__ float g_hb[Bb * HIDk];
__device__ float g_pk[Ee * HIDk];
__device__ float g_cgw[Dd];
__device__ float g_CgCb[2];
__device__ float g_logits[Nn * Ee];
__device__ int   g_cnt[Ee];
__device__ int   g_off[Ee];
__device__ int   g_te[Nn * 2];
__device__ int   g_tp[Nn * 2];
__device__ float g_tw[Nn * 2];
__device__ int   g_ptok[NP];
__device__ float g_pw[NP];
// fp16 hi/lo split storage
__device__ unsigned short g_xh[(size_t)Nn * Dd];
__device__ unsigned short g_WgH[(size_t)Ee * Ff * Dd];   // [e][f][d]  K-major (hi only)
__device__ unsigned short g_WuH[(size_t)Ee * Ff * Dd];
__device__ unsigned short g_WdH[(size_t)Ee * Dd * Ff];   // [e][d][f]  K-major hi
__device__ unsigned short g_WdL[(size_t)Ee * Dd * Ff];   // lo
__device__ unsigned short g_Hh[(size_t)NP * Ff];
__device__ unsigned short g_Hl[(size_t)NP * Ff];
__device__ unsigned short g_W2TH[(size_t)Dd * HIDk];     // W2^T [d][k] hi
__device__ unsigned short g_W2TL[(size_t)Dd * HIDk];     // lo

// ===================== prep =====================
__global__ void prep_kernel(const float* __restrict__ hist, const float* __restrict__ W1h,
                            const float* __restrict__ b1,
                            const float* __restrict__ persona, const float* __restrict__ W1p,
                            const float* __restrict__ ln_g, const float* __restrict__ ln_b,
                            const float* __restrict__ Wg, const float* __restrict__ bg) {
    int bx = blockIdx.x, tid = threadIdx.x;
    if (bx < 4) {
        float acc = b1[tid];
        const float* hr = hist + bx * Hh;
        for (int k = 0; k < Hh; k++) acc += hr[k] * W1h[k * HIDk + tid];
        g_hb[bx * HIDk + tid] = acc;
    } else if (bx < 12) {
        int e = bx - 4;
        float acc = 0.f;
        const float* pr = persona + e * Dd;
        for (int k = 0; k < Dd; k++) acc += pr[k] * W1p[k * HIDk + tid];
        g_pk[e * HIDk + tid] = acc;
    } else {
        __shared__ float sg[128], sb[128];
        float a = 0.f, b = 0.f;
        for (int d = tid; d < Dd; d += 128) {
            float w = Wg[d];
            float c = ln_g[d] * w;
            g_cgw[d] = c;
            a += c;
            b += ln_b[d] * w;
        }
        sg[tid] = a; sb[tid] = b;
        __syncthreads();
        for (int s = 64; s > 0; s >>= 1) {
            if (tid < s) { sg[tid] += sg[tid + s]; sb[tid] += sb[tid + s]; }
            __syncthreads();
        }
        if (tid == 0) { g_CgCb[0] = sg[0]; g_CgCb[1] = sb[0] + bg[0]; }
    }
}

// ===================== W2 -> W2^T fp16 hi/lo =====================
__global__ void w2t_kernel(const float* __restrict__ W2) {
    __shared__ float T[32][33];
    int d0 = blockIdx.x * 32, k0 = blockIdx.y * 32;
    int tid = threadIdx.x;
#pragma unroll
    for (int i = 0; i < 4; i++) {
        int kk = (tid >> 5) + i * 8, dd = tid & 31;
        T[kk][dd] = W2[(size_t)(k0 + kk) * Dd + d0 + dd];
    }
    __syncthreads();
#pragma unroll
    for (int i = 0; i < 4; i++) {
        int dd = (tid >> 5) + i * 8, kk = tid & 31;
        unsigned short hi, lo;
        f2h_split(T[kk][dd], hi, lo);
        g_W2TH[(size_t)(d0 + dd) * HIDk + k0 + kk] = hi;
        g_W2TL[(size_t)(d0 + dd) * HIDk + k0 + kk] = lo;
    }
}

// ===================== x -> fp16 hi =====================
__global__ void xconv_kernel(const float* __restrict__ x) {
    size_t i = (size_t)blockIdx.x * 256 + threadIdx.x;
    float4 v = ((const float4*)x)[i];
    unsigned short h0 = __half_as_ushort(__float2half_rn(v.x));
    unsigned short h1 = __half_as_ushort(__float2half_rn(v.y));
    unsigned short h2 = __half_as_ushort(__float2half_rn(v.z));
    unsigned short h3 = __half_as_ushort(__float2half_rn(v.w));
    uint2 ph = make_uint2((uint32_t)h0 | ((uint32_t)h1 << 16), (uint32_t)h2 | ((uint32_t)h3 << 16));
    *(uint2*)(g_xh + i * 4) = ph;
}

// ===================== base = x @ W1x + hb  (32-row tiles, 256 CTAs) =====================
__global__ __launch_bounds__(256) void base_kernel(const float* __restrict__ x,
                                                   const float* __restrict__ W1x) {
    __shared__ float Xs[32][16];
    __shared__ float Ws[16][128];
    int tid = threadIdx.x;
    int n0 = blockIdx.x * 32;
    int tx = tid & 15, ty = tid >> 4;
    float acc[2][8];
#pragma unroll
    for (int i = 0; i < 2; i++)
#pragma unroll
        for (int j = 0; j < 8; j++) acc[i][j] = 0.f;

    for (int ks = 0; ks < 64; ks++) {
        int k0 = ks * 16;
        if (tid < 128) {
            int row = tid >> 2, kk = (tid & 3) * 4;
            *(float4*)&Xs[row][kk] = *(const float4*)(x + (size_t)(n0 + row) * Dd + k0 + kk);
        }
        {
            int kk = tid >> 4, j = (tid & 15) * 8;
            const float* s = W1x + (size_t)(k0 + kk) * HIDk + j;
            *(float4*)&Ws[kk][j]     = *(const float4*)s;
            *(float4*)&Ws[kk][j + 4] = *(const float4*)(s + 4);
        }
        __syncthreads();
#pragma unroll
        for (int kk = 0; kk < 16; kk++) {
            float4 w0 = *(float4*)&Ws[kk][tx * 8];
            float4 w1 = *(float4*)&Ws[kk][tx * 8 + 4];
#pragma unroll
            for (int i = 0; i < 2; i++) {
                float xv = Xs[ty * 2 + i][kk];
                acc[i][0] += xv * w0.x; acc[i][1] += xv * w0.y;
                acc[i][2] += xv * w0.z; acc[i][3] += xv * w0.w;
                acc[i][4] += xv * w1.x; acc[i][5] += xv * w1.y;
                acc[i][6] += xv * w1.z; acc[i][7] += xv * w1.w;
            }
        }
        __syncthreads();
    }
    int b = n0 >> 11;
    const float* hb = g_hb + b * HIDk + tx * 8;
#pragma unroll
    for (int i = 0; i < 2; i++) {
        int n = n0 + ty * 2 + i;
        float4 o0 = make_float4(acc[i][0] + hb[0], acc[i][1] + hb[1],
                                acc[i][2] + hb[2], acc[i][3] + hb[3]);
        float4 o1 = make_float4(acc[i][4] + hb[4], acc[i][5] + hb[5],
                                acc[i][6] + hb[6], acc[i][7] + hb[7]);
        *(float4*)&g_base[(size_t)n * HIDk + tx * 8]     = o0;
        *(float4*)&g_base[(size_t)n * HIDk + tx * 8 + 4] = o1;
    }
}

// ===================== merge: W' = W + A@B -> transposed fp16 (hi; +lo for down) =====================
__global__ __launch_bounds__(256) void merge_kernel(
    const float* __restrict__ Wgate, const float* __restrict__ Wup, const float* __restrict__ Wdown,
    const float* __restrict__ Ag, const float* __restrict__ Bg,
    const float* __restrict__ Au, const float* __restrict__ Bu,
    const float* __restrict__ Ad, const float* __restrict__ Bd) {
    __shared__ float As[128][17];
    __shared__ float Bs[16][65];
    __shared__ unsigned short Thi[64][136];
    __shared__ unsigned short Tlo[64][136];
    int e = blockIdx.y, t = blockIdx.x, tid = threadIdx.x;
    const float *src, *Ap, *Bp;
    unsigned short *dhi, *dlo;
    int r0, c0, rowStride, outStride;
    bool isDown = false;
    if (t < 352) {
        int kt = t / 44, ft = t % 44;
        r0 = kt * 128; c0 = ft * 64; rowStride = Ff; outStride = Dd;
        src = Wgate + (size_t)e * Dd * Ff; Ap = Ag + (size_t)e * Dd * Rr; Bp = Bg + (size_t)e * Rr * Ff;
        dhi = g_WgH + (size_t)e * Ff * Dd; dlo = nullptr;
    } else if (t < 704) {
        t -= 352;
        int kt = t / 44, ft = t % 44;
        r0 = kt * 128; c0 = ft * 64; rowStride = Ff; outStride = Dd;
        src = Wup + (size_t)e * Dd * Ff; Ap = Au + (size_t)e * Dd * Rr; Bp = Bu + (size_t)e * Rr * Ff;
        dhi = g_WuH + (size_t)e * Ff * Dd; dlo = nullptr;
    } else {
        t -= 704;
        int kt = t / 16, ft = t % 16;
        r0 = kt * 128; c0 = ft * 64; rowStride = Dd; outStride = Ff;
        src = Wdown + (size_t)e * Ff * Dd; Ap = Ad + (size_t)e * Ff * Rr; Bp = Bd + (size_t)e * Rr * Dd;
        dhi = g_WdH + (size_t)e * Dd * Ff; dlo = g_WdL + (size_t)e * Dd * Ff;
        isDown = true;
    }
    {
        int r = tid >> 1, k0 = (tid & 1) * 8;
#pragma unroll
        for (int kk = 0; kk < 8; kk++)
            As[r][k0 + kk] = Ap[(size_t)(r0 + r) * Rr + k0 + kk];
    }
    for (int i = tid; i < 1024; i += 256) {
        int k = i >> 6, c = i & 63;
        Bs[k][c] = Bp[(size_t)k * rowStride + c0 + c];
    }
    __syncthreads();
    {
        int c = tid & 63, rb = tid >> 6;
        float vbuf[32];
        for (int rr = 0; rr < 32; rr++) {
            int r = rb * 32 + rr;
            float v = src[(size_t)(r0 + r) * rowStride + c0 + c];
#pragma unroll
            for (int k = 0; k < 16; k++) v += As[r][k] * Bs[k][c];
            vbuf[rr] = v;
        }
        for (int w = 0; w < 32; w++) {
            int rr = (w + c) & 31;
            int r = rb * 32 + rr;
            unsigned short hb_, lb_;
            f2h_split(vbuf[rr], hb_, lb_);
            Thi[c][r] = hb_;
            if (isDown) Tlo[c][r] = lb_;
        }
    }
    __syncthreads();
    {
        int c = tid >> 2, qq = tid & 3;
        const uint4* sh = (const uint4*)&Thi[c][qq * 32];
        uint4* dH = (uint4*)(dhi + (size_t)(c0 + c) * outStride + r0 + qq * 32);
#pragma unroll
        for (int m = 0; m < 4; m++) dH[m] = sh[m];
        if (isDown) {
            const uint4* sl = (const uint4*)&Tlo[c][qq * 32];
            uint4* dL = (uint4*)(dlo + (size_t)(c0 + c) * outStride + r0 + qq * 32);
#pragma unroll
            for (int m = 0; m < 4; m++) dL[m] = sl[m];
        }
    }
}

// ===================== fused gate logits via mma.sync =====================
#define LG_AHI 0
#define LG_ALO 17408
#define LG_B0  34816
#define LG_BSTG 34816
#define LG_RED (LG_B0 + 2 * LG_BSTG)
#define LG_B2  (LG_RED + 768)
#define LG_CG  (LG_B2 + 4096)
#define LG_SMEM (LG_CG + 4096)

__global__ __launch_bounds__(256) void logits_kernel(const float* __restrict__ b2) {
    extern __shared__ char sm[];
    uint32_t sb = smem_u32(sm);
    int e = blockIdx.y, n0 = blockIdx.x * 64;
    int tid = threadIdx.x, lane = tid & 31, wid = tid >> 5;
    int wy = wid & 3, wx = wid >> 2;

    if (tid < 192) ((float*)(sm + LG_RED))[tid] = 0.f;
#pragma unroll
    for (int i = 0; i < 4; i++) {
        ((float*)(sm + LG_B2))[tid + 256 * i] = b2[tid + 256 * i];
        ((float*)(sm + LG_CG))[tid + 256 * i] = g_cgw[tid + 256 * i];
    }
    {
        int t = tid >> 2, kq = (tid & 3) * 32;
        const float4* bp = (const float4*)(g_base + (size_t)(n0 + t) * HIDk + kq);
        const float4* pp = (const float4*)(g_pk + e * HIDk + kq);
        unsigned short* ah = (unsigned short*)(sm + LG_AHI) + t * 136 + kq;
        unsigned short* al = (unsigned short*)(sm + LG_ALO) + t * 136 + kq;
#pragma unroll
        for (int q = 0; q < 8; q++) {
            float4 a = bp[q], p = pp[q];
            float v[4] = {fmaxf(a.x + p.x, 0.f), fmaxf(a.y + p.y, 0.f),
                          fmaxf(a.z + p.z, 0.f), fmaxf(a.w + p.w, 0.f)};
#pragma unroll
            for (int c = 0; c < 4; c++) {
                unsigned short hi, lo;
                f2h_split(v[c], hi, lo);
                ah[q * 4 + c] = hi;
                al[q * 4 + c] = lo;
            }
        }
    }
    uint32_t sdst[8];
    uint32_t gofs[8];
    int ghl[8];
#pragma unroll
    for (int j = 0; j < 8; j++) {
        int sid = tid + 256 * j;
        int hl = sid >> 10;
        int rid = sid & 1023;
        int row = rid >> 4, seg = rid & 15;
        sdst[j] = (uint32_t)(hl * 17408 + row * 272 + seg * 16);
        gofs[j] = (uint32_t)(row * HIDk + seg * 8);
        ghl[j] = hl;
    }
#pragma unroll
    for (int j = 0; j < 8; j++) {
        const unsigned short* g = (ghl[j] ? g_W2TL : g_W2TH) + gofs[j];
        CPASYNC16(sb + LG_B0 + sdst[j], (const char*)g);
    }
    CP_COMMIT();
    __syncthreads();

    float s1[2] = {0.f, 0.f}, s2[2] = {0.f, 0.f}, s3[2] = {0.f, 0.f};
    uint32_t aoff = (uint32_t)((wy * 16 + (lane & 15)) * 272 + (lane >> 4) * 16);
    uint32_t boff = (uint32_t)(((wx * 32 + ((lane & 7) | ((lane >> 4) << 3))) * 272) + ((lane >> 3) & 1) * 16);

    for (int ch = 0; ch < 16; ch++) {
        if (ch + 1 < 16) {
            uint32_t stg = sb + LG_B0 + ((ch + 1) & 1) * LG_BSTG;
            uint32_t dadd = (uint32_t)((ch + 1) * 64 * HIDk);
#pragma unroll
            for (int j = 0; j < 8; j++) {
                const unsigned short* g = (ghl[j] ? g_W2TL : g_W2TH) + gofs[j] + dadd;
                CPASYNC16(stg + sdst[j], (const char*)g);
            }
            CP_COMMIT();
            CP_WAIT(1);
        } else {
            CP_WAIT(0);
        }
        __syncthreads();
        uint32_t sB = sb + LG_B0 + (ch & 1) * LG_BSTG;
        float acc[4][4];
#pragma unroll
        for (int a = 0; a < 4; a++)
#pragma unroll
            for (int c = 0; c < 4; c++) acc[a][c] = 0.f;
#pragma unroll
        for (int k16 = 0; k16 < 8; k16++) {
            uint32_t kb = (uint32_t)(k16 * 32);
            uint32_t ahr[4], alr[4], bh[2][4], bl[2][4];
            LDSM4(ahr, sb + LG_AHI + aoff + kb);
            LDSM4(alr, sb + LG_ALO + aoff + kb);
            LDSM4(bh[0], sB + boff + kb);
            LDSM4(bh[1], sB + boff + 16 * 272 + kb);
            LDSM4(bl[0], sB + 17408 + boff + kb);
            LDSM4(bl[1], sB + 17408 + boff + 16 * 272 + kb);
#pragma unroll
            for (int nt = 0; nt < 2; nt++)
#pragma unroll
                for (int h = 0; h < 2; h++) {
                    MMA16816(acc[nt * 2 + h], ahr, bh[nt][2 * h], bh[nt][2 * h + 1]);
                    MMA16816(acc[nt * 2 + h], alr, bh[nt][2 * h], bh[nt][2 * h + 1]);
                    MMA16816(acc[nt * 2 + h], ahr, bl[nt][2 * h], bl[nt][2 * h + 1]);
                }
        }
#pragma unroll
        for (int nt4 = 0; nt4 < 4; nt4++) {
            int col = ch * 64 + wx * 32 + nt4 * 8 + (lane & 3) * 2;
            float b0 = ((float*)(sm + LG_B2))[col], b1v = ((float*)(sm + LG_B2))[col + 1];
            float c0 = ((float*)(sm + LG_CG))[col], c1v = ((float*)(sm + LG_CG))[col + 1];
            float f;
            f = fmaxf(acc[nt4][0] + b0, 0.f);  s1[0] += f * c0;  s2[0] += f; s3[0] += f * f;
            f = fmaxf(acc[nt4][1] + b1v, 0.f); s1[0] += f * c1v; s2[0] += f; s3[0] += f * f;
            f = fmaxf(acc[nt4][2] + b0, 0.f);  s1[1] += f * c0;  s2[1] += f; s3[1] += f * f;
            f = fmaxf(acc[nt4][3] + b1v, 0.f); s1[1] += f * c1v; s2[1] += f; s3[1] += f * f;
        }
        __syncthreads();
    }
#pragma unroll
    for (int off = 1; off <= 2; off <<= 1) {
#pragma unroll
        for (int i = 0; i < 2; i++) {
            s1[i] += __shfl_xor_sync(0xffffffffu, s1[i], off);
            s2[i] += __shfl_xor_sync(0xffffffffu, s2[i], off);
            s3[i] += __shfl_xor_sync(0xffffffffu, s3[i], off);
        }
    }
    if ((lane & 3) == 0) {
        int row = wy * 16 + (lane >> 2);
        float* red = (float*)(sm + LG_RED);
        atomicAdd(&red[row],           s1[0]);
        atomicAdd(&red[row + 8],       s1[1]);
        atomicAdd(&red[64 + row],      s2[0]);
        atomicAdd(&red[64 + row + 8],  s2[1]);
        atomicAdd(&red[128 + row],     s3[0]);
        atomicAdd(&red[128 + row + 8], s3[1]);
    }
    __syncthreads();
    if (tid < 64) {
        float* red = (float*)(sm + LG_RED);
        float S1 = red[tid], S2 = red[64 + tid], S3 = red[128 + tid];
        float Cg = g_CgCb[0], Cb = g_CgCb[1];
        float mu = S2 * (1.f / (float)Dd);
        float var = S3 * (1.f / (float)Dd) - mu * mu;
        float rstd = rsqrtf(var + LN_EPS);
        g_logits[(size_t)(n0 + tid) * Ee + e] = rstd * (S1 - mu * Cg) + Cb;
    }
}

// ===================== routing =====================
__global__ void route_kernel() {
    int n = blockIdx.x * 256 + threadIdx.x;
    float l[Ee];
    float m = -1e30f;
#pragma unroll
    for (int e = 0; e < Ee; e++) { l[e] = g_logits[(size_t)n * Ee + e]; m = fmaxf(m, l[e]); }
    float s = 0.f;
#pragma unroll
    for (int e = 0; e < Ee; e++) { l[e] = expf(l[e] - m); s += l[e]; }
    float inv = 1.f / s;
#pragma unroll
    for (int e = 0; e < Ee; e++) l[e] *= inv;
    int i0 = 0; float b0 = l[0];
#pragma unroll
    for (int e = 1; e < Ee; e++) if (l[e] > b0) { b0 = l[e]; i0 = e; }
    int i1 = -1; float b1 = -1.f;
#pragma unroll
    for (int e = 0; e < Ee; e++) if (e != i0 && l[e] > b1) { b1 = l[e]; i1 = e; }
    int p0 = atomicAdd(&g_cnt[i0], 1);
    int p1 = atomicAdd(&g_cnt[i1], 1);
    g_te[2 * n] = i0; g_tp[2 * n] = p0; g_tw[2 * n] = b0;
    g_te[2 * n + 1] = i1; g_tp[2 * n + 1] = p1; g_tw[2 * n + 1] = b1;
}

__global__ void scan_kernel() {
    int a = 0;
    for (int e = 0; e < Ee; e++) { g_off[e] = a; a += g_cnt[e]; }
}

__global__ void scatter_kernel() {
    int n = blockIdx.x * 256 + threadIdx.x;
#pragma unroll
    for (int i = 0; i < 2; i++) {
        int slot = g_off[g_te[2 * n + i]] + g_tp[2 * n + i];
        g_ptok[slot] = n;
        g_pw[slot] = g_tw[2 * n + i];
    }
}

// ===================== expert GEMM1 (1-term: AhBh; gate+up) =====================
// CTA: 128 tokens x 64 f-cols (gate AND up). K=1024, chunks of 32. 8 warps (4M x 2N).
// stage (80B pitch): A_hi@0 (10240), B_hi(g64+u64)@10240 (10240)
#define G1_STAGE 20480
#define G1_SMEM (1024 + 2 * G1_STAGE)

__global__ __launch_bounds__(256, 2) void moe_gemm1() {
    extern __shared__ char sm[];
    int e = blockIdx.z;
    int cnt = g_cnt[e];
    int r0 = blockIdx.x * 128;
    if (r0 >= cnt) return;
    int off = g_off[e];
    int f0 = blockIdx.y * 64;
    int tid = threadIdx.x, lane = tid & 31, wid = tid >> 5;
    int wy = wid & 3, wx = wid >> 2;

    int* stok = (int*)sm;
    if (tid < 128) {
        int lr = r0 + tid; if (lr >= cnt) lr = cnt - 1;
        stok[tid] = g_ptok[off + lr];
    }
    __syncthreads();

    uint32_t sb0 = smem_u32(sm) + 1024;

    uint32_t sdst[4];
    const char* gsrc[4];
#pragma unroll
    for (int j = 0; j < 4; j++) {
        int sid = tid + 256 * j;        // 0..1023
        int region = sid >> 9;
        int rid = sid & 511;
        int row = rid >> 2, seg = rid & 3;
        sdst[j] = (uint32_t)(region * 10240 + row * 80 + seg * 16);
        const unsigned short* g;
        if (region == 0) g = g_xh + (size_t)stok[row] * Dd;
        else             g = (row < 64) ? g_WgH + ((size_t)e * Ff + f0 + row) * Dd
                                        : g_WuH + ((size_t)e * Ff + f0 + row - 64) * Dd;
        gsrc[j] = (const char*)(g + seg * 8);
    }

    float accG[2][4][4], accU[2][4][4];
#pragma unroll
    for (int a = 0; a < 2; a++)
#pragma unroll
        for (int b = 0; b < 4; b++)
#pragma unroll
            for (int c = 0; c < 4; c++) { accG[a][b][c] = 0.f; accU[a][b][c] = 0.f; }

    uint32_t aoff = (uint32_t)((wy * 32 + (lane & 15)) * 80 + (lane >> 4) * 16);
    uint32_t boff = (uint32_t)((wx * 32 + ((lane & 7) | ((lane >> 4) << 3))) * 80 + ((lane >> 3) & 1) * 16);

#pragma unroll
    for (int j = 0; j < 4; j++) CPASYNC16(sb0 + sdst[j], gsrc[j]);
    CP_COMMIT();

    const int NCH = 32;
    for (int ch = 0; ch < NCH; ch++) {
        if (ch + 1 < NCH) {
            uint32_t sbn = sb0 + ((ch + 1) & 1) * G1_STAGE;
            int cb = (ch + 1) * 64;
#pragma unroll
            for (int j = 0; j < 4; j++) CPASYNC16(sbn + sdst[j], gsrc[j] + cb);
            CP_COMMIT();
            CP_WAIT(1);
        } else {
            CP_WAIT(0);
        }
        __syncthreads();
        uint32_t s = sb0 + (ch & 1) * G1_STAGE;
#pragma unroll
        for (int k16 = 0; k16 < 2; k16++) {
            uint32_t kb = k16 * 32;
            uint32_t ah[2][4], bg[2][4], bu[2][4];
#pragma unroll
            for (int mt = 0; mt < 2; mt++)
                LDSM4(ah[mt], s + aoff + mt * (16 * 80) + kb);
#pragma unroll
            for (int nt = 0; nt < 2; nt++) {
                LDSM4(bg[nt], s + 10240 + boff + nt * (16 * 80) + kb);
                LDSM4(bu[nt], s + 10240 + 5120 + boff + nt * (16 * 80) + kb);
            }
#pragma unroll
            for (int mt = 0; mt < 2; mt++)
#pragma unroll
                for (int nt = 0; nt < 2; nt++)
#pragma unroll
                    for (int h = 0; h < 2; h++) {
                        MMA16816(accG[mt][nt * 2 + h], ah[mt], bg[nt][2 * h], bg[nt][2 * h + 1]);
                        MMA16816(accU[mt][nt * 2 + h], ah[mt], bu[nt][2 * h], bu[nt][2 * h + 1]);
                    }
        }
        __syncthreads();
    }

#pragma unroll
    for (int mt = 0; mt < 2; mt++)
#pragma unroll
        for (int rh = 0; rh < 2; rh++) {
            int lr = wy * 32 + mt * 16 + (lane >> 2) + rh * 8;
            if (r0 + lr < cnt) {
                int slot = off + r0 + lr;
#pragma unroll
                for (int nt8 = 0; nt8 < 4; nt8++) {
                    int col = f0 + wx * 32 + nt8 * 8 + (lane & 3) * 2;
                    float g0 = accG[mt][nt8][rh * 2 + 0], g1 = accG[mt][nt8][rh * 2 + 1];
                    float u0 = accU[mt][nt8][rh * 2 + 0], u1 = accU[mt][nt8][rh * 2 + 1];
                    float h0 = g0 / (1.f + __expf(-g0)) * u0;
                    float h1 = g1 / (1.f + __expf(-g1)) * u1;
                    unsigned short a0, b0, a1, b1;
                    f2h_split(h0, a0, b0);
                    f2h_split(h1, a1, b1);
                    size_t idx = ((size_t)slot * Ff + col) >> 1;
                    ((uint32_t*)g_Hh)[idx] = (uint32_t)a0 | ((uint32_t)a1 << 16);
                    ((uint32_t*)g_Hl)[idx] = (uint32_t)b0 | ((uint32_t)b1 << 16);
                }
            }
        }
}

// ===================== expert GEMM2 (3-term; grid: dtile fastest for H L2 reuse) =====================
#define G2_STAGE 30720
#define G2_SMEM (2 * G2_STAGE)

__global__ __launch_bounds__(256, 2) void moe_gemm2(float* __restrict__ out) {
    extern __shared__ char sm[];
    int e = blockIdx.z;
    int cnt = g_cnt[e];
    int r0 = blockIdx.y * 128;
    if (r0 >= cnt) return;
    int off = g_off[e];
    int d0 = blockIdx.x * 64;
    int tid = threadIdx.x, lane = tid & 31, wid = tid >> 5;
    int wy = wid & 3, wx = wid >> 2;

    uint32_t sb0 = smem_u32(sm);

    uint32_t sdst[6];
    const char* gsrc[6];
#pragma unroll
    for (int j = 0; j < 6; j++) {
        int sid = tid + 256 * j;
        const unsigned short* g;
        uint32_t so;
        if (sid < 1024) {
            int hl = sid >> 9;
            int rid = sid & 511;
            int row = rid >> 2, seg = rid & 3;
            so = hl * 10240u + row * 80u + seg * 16u;
            int lr = r0 + row; if (lr >= cnt) lr = cnt - 1;
            g = (hl == 0 ? g_Hh : g_Hl) + (size_t)(off + lr) * Ff + seg * 8;
        } else {
            int rid = sid - 1024;
            int hl = rid >> 8;
            int row = (rid & 255) >> 2, seg = rid & 3;
            so = 20480u + hl * 5120u + row * 80u + seg * 16u;
            g = (hl == 0 ? g_WdH : g_WdL) + ((size_t)e * Dd + d0 + row) * Ff + seg * 8;
        }
        sdst[j] = so;
        gsrc[j] = (const char*)g;
    }

    float acc[2][4][4];
#pragma unroll
    for (int a = 0; a < 2; a++)
#pragma unroll
        for (int b = 0; b < 4; b++)
#pragma unroll
            for (int c = 0; c < 4; c++) acc[a][b][c] = 0.f;

    uint32_t aoff = (uint32_t)((wy * 32 + (lane & 15)) * 80 + (lane >> 4) * 16);
    uint32_t boff = (uint32_t)((wx * 32 + ((lane & 7) | ((lane >> 4) << 3))) * 80 + ((lane >> 3) & 1) * 16);

#pragma unroll
    for (int j = 0; j < 6; j++) CPASYNC16(sb0 + sdst[j], gsrc[j]);
    CP_COMMIT();

    const int NCH = 88;
    for (int ch = 0; ch < NCH; ch++) {
        if (ch + 1 < NCH) {
            uint32_t sbn = sb0 + ((ch + 1) & 1) * G2_STAGE;
            int cb = (ch + 1) * 64;
#pragma unroll
            for (int j = 0; j < 6; j++) CPASYNC16(sbn + sdst[j], gsrc[j] + cb);
            CP_COMMIT();
            CP_WAIT(1);
        } else {
            CP_WAIT(0);
        }
        __syncthreads();
        uint32_t s = sb0 + (ch & 1) * G2_STAGE;
#pragma unroll
        for (int k16 = 0; k16 < 2; k16++) {
            uint32_t kb = k16 * 32;
            uint32_t ah[2][4], al[2][4], bf[2][4];
#pragma unroll
            for (int mt = 0; mt < 2; mt++) {
                LDSM4(ah[mt], s + aoff + mt * (16 * 80) + kb);
                LDSM4(al[mt], s + 10240 + aoff + mt * (16 * 80) + kb);
            }
#pragma unroll
            for (int nt = 0; nt < 2; nt++) LDSM4(bf[nt], s + 20480 + boff + nt * (16 * 80) + kb);
#pragma unroll
            for (int mt = 0; mt < 2; mt++)
#pragma unroll
                for (int nt = 0; nt < 2; nt++)
#pragma unroll
                    for (int h = 0; h < 2; h++) {
                        MMA16816(acc[mt][nt * 2 + h], ah[mt], bf[nt][2 * h], bf[nt][2 * h + 1]);
                        MMA16816(acc[mt][nt * 2 + h], al[mt], bf[nt][2 * h], bf[nt][2 * h + 1]);
                    }
#pragma unroll
            for (int nt = 0; nt < 2; nt++) LDSM4(bf[nt], s + 25600 + boff + nt * (16 * 80) + kb);
#pragma unroll
            for (int mt = 0; mt < 2; mt++)
#pragma unroll
                for (int nt = 0; nt < 2; nt++)
#pragma unroll
                    for (int h = 0; h < 2; h++)
                        MMA16816(acc[mt][nt * 2 + h], ah[mt], bf[nt][2 * h], bf[nt][2 * h + 1]);
        }
        __syncthreads();
    }

#pragma unroll
    for (int mt = 0; mt < 2; mt++)
#pragma unroll
        for (int rh = 0; rh < 2; rh++) {
            int lr = wy * 32 + mt * 16 + (lane >> 2) + rh * 8;
            if (r0 + lr < cnt) {
                int slot = off + r0 + lr;
                int tok = g_ptok[slot];
                float w = g_pw[slot];
                float* op = out + (size_t)tok * Dd + d0 + wx * 32 + (lane & 3) * 2;
#pragma unroll
                for (int nt8 = 0; nt8 < 4; nt8++) {
                    atomicAdd(op + nt8 * 8,     acc[mt][nt8][rh * 2 + 0] * w);
                    atomicAdd(op + nt8 * 8 + 1, acc[mt][nt8][rh * 2 + 1] * w);
                }
            }
        }
}

// ===================== launch =====================
extern "C" void kernel_launch(void* const* d_in, const int* in_sizes, int n_in,
                              void* d_out, int out_size) {
    (void)in_sizes; (void)n_in;
    const float* x       = (const float*)d_in[0];
    const float* hist    = (const float*)d_in[1];
    const float* persona = (const float*)d_in[2];
    const float* W1x     = (const float*)d_in[3];
    const float* W1h     = (const float*)d_in[4];
    const float* W1p     = (const float*)d_in[5];
    const float* b1      = (const float*)d_in[6];
    const float* W2      = (const float*)d_in[7];
    const float* b2      = (const float*)d_in[8];
    const float* ln_g    = (const float*)d_in[9];
    const float* ln_b    = (const float*)d_in[10];
    const float* Wg      = (const float*)d_in[11];
    const float* bg      = (const float*)d_in[12];
    const float* Wgate   = (const float*)d_in[13];
    const float* Wup     = (const float*)d_in[14];
    const float* Wdown   = (const float*)d_in[15];
    const float* Ag      = (const float*)d_in[16];
    const float* Bg      = (const float*)d_in[17];
    const float* Au      = (const float*)d_in[18];
    const float* Bu      = (const float*)d_in[19];
    const float* Ad      = (const float*)d_in[20];
    const float* Bd      = (const float*)d_in[21];
    float* out = (float*)d_out;

    cudaFuncSetAttribute(moe_gemm1, cudaFuncAttributeMaxDynamicSharedMemorySize, G1_SMEM);
    cudaFuncSetAttribute(moe_gemm2, cudaFuncAttributeMaxDynamicSharedMemorySize, G2_SMEM);
    cudaFuncSetAttribute(logits_kernel, cudaFuncAttributeMaxDynamicSharedMemorySize, LG_SMEM);

    void* cntp = nullptr;
    cudaGetSymbolAddress(&cntp, g_cnt);

    cudaMemsetAsync(out, 0, (size_t)out_size * sizeof(float));
    cudaMemsetAsync(cntp, 0, Ee * sizeof(int));

    prep_kernel<<<13, 128>>>(hist, W1h, b1, persona, W1p, ln_g, ln_b, Wg, bg);
    w2t_kernel<<<dim3(Dd / 32, HIDk / 32), 256>>>(W2);
    xconv_kernel<<<(Nn * Dd) / 4 / 256, 256>>>(x);
    base_kernel<<<Nn / 32, 256>>>(x, W1x);
    merge_kernel<<<dim3(1056, Ee), 256>>>(Wgate, Wup, Wdown, Ag, Bg, Au, Bu, Ad, Bd);
    logits_kernel<<<dim3(Nn / 64, Ee), 256, LG_SMEM>>>(b2);
    route_kernel<<<Nn / 256, 256>>>();
    scan_kernel<<<1, 1>>>();
    scatter_kernel<<<Nn / 256, 256>>>();
    moe_gemm1<<<dim3(NP / 128, Ff / 64, Ee), 256, G1_SMEM>>>();
    moe_gemm2<<<dim3(Dd / 64, NP / 128, Ee), 256, G2_SMEM>>>(out);
}

// round 7
// speedup vs baseline: 5.3614x; 1.1779x over previous
#include <cuda_runtime.h>
#include <cuda_fp16.h>
#include <math.h>
#include <stdint.h>

#define Bb 4
#define Ss 2048
#define Dd 1024
#define Hh 512
#define Ee 8
#define Ff 2816
#define Rr 16
#define HIDk 128
#define Nn 8192
#define NP 16384
#define LN_EPS 1e-5f

// ===================== baseline-PTX helpers =====================
__device__ __forceinline__ uint32_t smem_u32(const void* p) {
    uint32_t a;
    asm("{ .reg .u64 t; cvta.to.shared.u64 t, %1; cvt.u32.u64 %0, t; }" : "=r"(a) : "l"(p));
    return a;
}

#define CPASYNC16(dst, src) \
    asm volatile("cp.async.cg.shared.global [%0], [%1], 16;\n" :: "r"(dst), "l"(src))
#define CP_COMMIT() asm volatile("cp.async.commit_group;\n" ::: "memory")
#define CP_WAIT(N)  asm volatile("cp.async.wait_group %0;\n" :: "n"(N) : "memory")

#define LDSM4(R, addr) \
    asm volatile("ldmatrix.sync.aligned.m8n8.x4.shared.b16 {%0,%1,%2,%3}, [%4];" \
        : "=r"((R)[0]), "=r"((R)[1]), "=r"((R)[2]), "=r"((R)[3]) : "r"(addr))

#define MMA16816(C, A, B0, B1) \
    asm volatile("mma.sync.aligned.m16n8k16.row.col.f32.f16.f16.f32 " \
        "{%0,%1,%2,%3}, {%4,%5,%6,%7}, {%8,%9}, {%0,%1,%2,%3};" \
        : "+f"((C)[0]), "+f"((C)[1]), "+f"((C)[2]), "+f"((C)[3]) \
        : "r"((A)[0]), "r"((A)[1]), "r"((A)[2]), "r"((A)[3]), "r"(B0), "r"(B1))

__device__ __forceinline__ void f2h_split(float v, unsigned short& hi, unsigned short& lo) {
    __half h = __float2half_rn(v);
    hi = __half_as_ushort(h);
    lo = __half_as_ushort(__float2half_rn(v - __half2float(h)));
}

// ===================== static device scratch =====================
__device__ float g_base[Nn * HIDk];
__device__ float g_hb[Bb * HIDk];
__device__ float g_pk[Ee * HIDk];
__device__ float g_cgw[Dd];
__device__ float g_CgCb[2];
__device__ float g_logits[Nn * Ee];
__device__ int   g_cnt[Ee];
__device__ int   g_off[Ee];
__device__ int   g_te[Nn * 2];
__device__ int   g_tp[Nn * 2];
__device__ float g_tw[Nn * 2];
__device__ int   g_ptok[NP];
__device__ float g_pw[NP];
// fp16 split storage
__device__ unsigned short g_xh[(size_t)Nn * Dd];
__device__ unsigned short g_xl[(size_t)Nn * Dd];
__device__ unsigned short g_WgH[(size_t)Ee * Ff * Dd];   // [e][f][d]  K-major (hi)
__device__ unsigned short g_WuH[(size_t)Ee * Ff * Dd];
__device__ unsigned short g_WdH[(size_t)Ee * Dd * Ff];   // [e][d][f]  K-major (hi)
__device__ unsigned short g_Hh[(size_t)NP * Ff];
__device__ unsigned short g_Hl[(size_t)NP * Ff];
__device__ unsigned short g_W2TH[(size_t)Dd * HIDk];     // W2^T [d][k] hi
__device__ unsigned short g_W2TL[(size_t)Dd * HIDk];     // lo
__device__ unsigned short g_W1TH[(size_t)HIDk * Dd];     // W1x^T [k][d] hi
__device__ unsigned short g_W1TL[(size_t)HIDk * Dd];     // lo

// ===================== prep =====================
__global__ void prep_kernel(const float* __restrict__ hist, const float* __restrict__ W1h,
                            const float* __restrict__ b1,
                            const float* __restrict__ persona, const float* __restrict__ W1p,
                            const float* __restrict__ ln_g, const float* __restrict__ ln_b,
                            const float* __restrict__ Wg, const float* __restrict__ bg) {
    int bx = blockIdx.x, tid = threadIdx.x;
    if (bx < 4) {
        float acc = b1[tid];
        const float* hr = hist + bx * Hh;
        for (int k = 0; k < Hh; k++) acc += hr[k] * W1h[k * HIDk + tid];
        g_hb[bx * HIDk + tid] = acc;
    } else if (bx < 12) {
        int e = bx - 4;
        float acc = 0.f;
        const float* pr = persona + e * Dd;
        for (int k = 0; k < Dd; k++) acc += pr[k] * W1p[k * HIDk + tid];
        g_pk[e * HIDk + tid] = acc;
    } else {
        __shared__ float sg[128], sb[128];
        float a = 0.f, b = 0.f;
        for (int d = tid; d < Dd; d += 128) {
            float w = Wg[d];
            float c = ln_g[d] * w;
            g_cgw[d] = c;
            a += c;
            b += ln_b[d] * w;
        }
        sg[tid] = a; sb[tid] = b;
        __syncthreads();
        for (int s = 64; s > 0; s >>= 1) {
            if (tid < s) { sg[tid] += sg[tid + s]; sb[tid] += sb[tid + s]; }
            __syncthreads();
        }
        if (tid == 0) { g_CgCb[0] = sg[0]; g_CgCb[1] = sb[0] + bg[0]; }
    }
}

// ===================== W2 -> W2^T fp16 hi/lo =====================
__global__ void w2t_kernel(const float* __restrict__ W2) {
    __shared__ float T[32][33];
    int d0 = blockIdx.x * 32, k0 = blockIdx.y * 32;
    int tid = threadIdx.x;
#pragma unroll
    for (int i = 0; i < 4; i++) {
        int kk = (tid >> 5) + i * 8, dd = tid & 31;
        T[kk][dd] = W2[(size_t)(k0 + kk) * Dd + d0 + dd];
    }
    __syncthreads();
#pragma unroll
    for (int i = 0; i < 4; i++) {
        int dd = (tid >> 5) + i * 8, kk = tid & 31;
        unsigned short hi, lo;
        f2h_split(T[kk][dd], hi, lo);
        g_W2TH[(size_t)(d0 + dd) * HIDk + k0 + kk] = hi;
        g_W2TL[(size_t)(d0 + dd) * HIDk + k0 + kk] = lo;
    }
}

// ===================== W1x -> W1x^T fp16 hi/lo =====================
__global__ void w1t_kernel(const float* __restrict__ W1x) {
    __shared__ float T[32][33];
    int k0 = blockIdx.x * 32, d0 = blockIdx.y * 32;
    int tid = threadIdx.x;
#pragma unroll
    for (int i = 0; i < 4; i++) {
        int dd = (tid >> 5) + i * 8, kk = tid & 31;
        T[dd][kk] = W1x[(size_t)(d0 + dd) * HIDk + k0 + kk];
    }
    __syncthreads();
#pragma unroll
    for (int i = 0; i < 4; i++) {
        int kk = (tid >> 5) + i * 8, dd = tid & 31;
        unsigned short hi, lo;
        f2h_split(T[dd][kk], hi, lo);
        g_W1TH[(size_t)(k0 + kk) * Dd + d0 + dd] = hi;
        g_W1TL[(size_t)(k0 + kk) * Dd + d0 + dd] = lo;
    }
}

// ===================== x -> fp16 hi/lo =====================
__global__ void xconv_kernel(const float* __restrict__ x) {
    size_t i = (size_t)blockIdx.x * 256 + threadIdx.x;
    float4 v = ((const float4*)x)[i];
    unsigned short h0, l0, h1, l1, h2, l2, h3, l3;
    f2h_split(v.x, h0, l0); f2h_split(v.y, h1, l1);
    f2h_split(v.z, h2, l2); f2h_split(v.w, h3, l3);
    uint2 ph = make_uint2((uint32_t)h0 | ((uint32_t)h1 << 16), (uint32_t)h2 | ((uint32_t)h3 << 16));
    uint2 pl = make_uint2((uint32_t)l0 | ((uint32_t)l1 << 16), (uint32_t)l2 | ((uint32_t)l3 << 16));
    *(uint2*)(g_xh + i * 4) = ph;
    *(uint2*)(g_xl + i * 4) = pl;
}

// ===================== base = x @ W1x + hb (tensor-core, 3-term: AhBh+AhBl+AlBh) =====================
// CTA: 64 tokens x 128 cols. K=1024, 32 chunks of 32, 3-stage pipeline.
// stage (80B pitch): Ah@0 (5120), Al@5120 (5120), Bh@10240 (10240), Bl@20480 (10240)
#define BM_STAGE 30720
#define BM_SMEM (3 * BM_STAGE)

__global__ __launch_bounds__(256, 2) void base_mma() {
    extern __shared__ char sm[];
    int n0 = blockIdx.x * 64;
    int tid = threadIdx.x, lane = tid & 31, wid = tid >> 5;
    int wy = wid & 1, wx = wid >> 1;
    uint32_t sb0 = smem_u32(sm);

    uint32_t sdst[6];
    const char* gsrc[6];
#pragma unroll
    for (int j = 0; j < 6; j++) {
        int sid = tid + 256 * j;
        const unsigned short* g;
        uint32_t so;
        if (sid < 256) {
            int row = sid >> 2, seg = sid & 3;
            so = row * 80u + seg * 16u;
            g = g_xh + (size_t)(n0 + row) * Dd + seg * 8;
        } else if (sid < 512) {
            int rid = sid - 256;
            int row = rid >> 2, seg = rid & 3;
            so = 5120u + row * 80u + seg * 16u;
            g = g_xl + (size_t)(n0 + row) * Dd + seg * 8;
        } else if (sid < 1024) {
            int rid = sid - 512;
            int row = rid >> 2, seg = rid & 3;
            so = 10240u + row * 80u + seg * 16u;
            g = g_W1TH + (size_t)row * Dd + seg * 8;
        } else {
            int rid = sid - 1024;
            int row = rid >> 2, seg = rid & 3;
            so = 20480u + row * 80u + seg * 16u;
            g = g_W1TL + (size_t)row * Dd + seg * 8;
        }
        sdst[j] = so;
        gsrc[j] = (const char*)g;
    }

    float acc[2][4][4];
#pragma unroll
    for (int a = 0; a < 2; a++)
#pragma unroll
        for (int b = 0; b < 4; b++)
#pragma unroll
            for (int c = 0; c < 4; c++) acc[a][b][c] = 0.f;

    uint32_t aoff = (uint32_t)((wy * 32 + (lane & 15)) * 80 + (lane >> 4) * 16);
    uint32_t boff = (uint32_t)((wx * 32 + ((lane & 7) | ((lane >> 4) << 3))) * 80 + ((lane >> 3) & 1) * 16);

    const int NCH = 32;
#pragma unroll
    for (int j = 0; j < 6; j++) CPASYNC16(sb0 + sdst[j], gsrc[j]);
    CP_COMMIT();
#pragma unroll
    for (int j = 0; j < 6; j++) CPASYNC16(sb0 + BM_STAGE + sdst[j], gsrc[j] + 64);
    CP_COMMIT();

    for (int ch = 0; ch < NCH; ch++) {
        if (ch == NCH - 1) { CP_WAIT(0); } else { CP_WAIT(1); }
        __syncthreads();
        if (ch + 2 < NCH) {
            uint32_t stg = sb0 + ((ch + 2) % 3) * BM_STAGE;
            int cb = (ch + 2) * 64;
#pragma unroll
            for (int j = 0; j < 6; j++) CPASYNC16(stg + sdst[j], gsrc[j] + cb);
            CP_COMMIT();
        }
        uint32_t s = sb0 + (ch % 3) * BM_STAGE;
#pragma unroll
        for (int k16 = 0; k16 < 2; k16++) {
            uint32_t kb = k16 * 32;
            uint32_t ah[2][4], al[2][4], bh[2][4], bl[2][4];
#pragma unroll
            for (int mt = 0; mt < 2; mt++) {
                LDSM4(ah[mt], s + aoff + mt * (16 * 80) + kb);
                LDSM4(al[mt], s + 5120 + aoff + mt * (16 * 80) + kb);
            }
#pragma unroll
            for (int nt = 0; nt < 2; nt++) {
                LDSM4(bh[nt], s + 10240 + boff + nt * (16 * 80) + kb);
                LDSM4(bl[nt], s + 20480 + boff + nt * (16 * 80) + kb);
            }
#pragma unroll
            for (int mt = 0; mt < 2; mt++)
#pragma unroll
                for (int nt = 0; nt < 2; nt++)
#pragma unroll
                    for (int h = 0; h < 2; h++) {
                        MMA16816(acc[mt][nt * 2 + h], ah[mt], bh[nt][2 * h], bh[nt][2 * h + 1]);
                        MMA16816(acc[mt][nt * 2 + h], ah[mt], bl[nt][2 * h], bl[nt][2 * h + 1]);
                        MMA16816(acc[mt][nt * 2 + h], al[mt], bh[nt][2 * h], bh[nt][2 * h + 1]);
                    }
        }
    }

#pragma unroll
    for (int mt = 0; mt < 2; mt++)
#pragma unroll
        for (int rh = 0; rh < 2; rh++) {
            int row = n0 + wy * 32 + mt * 16 + (lane >> 2) + rh * 8;
            const float* hb = g_hb + (row >> 11) * HIDk;
#pragma unroll
            for (int nq = 0; nq < 4; nq++) {
                int col = wx * 32 + nq * 8 + (lane & 3) * 2;
                g_base[(size_t)row * HIDk + col]     = acc[mt][nq][rh * 2]     + hb[col];
                g_base[(size_t)row * HIDk + col + 1] = acc[mt][nq][rh * 2 + 1] + hb[col + 1];
            }
        }
}

// ===================== merge: W' = W + A@B -> transposed fp16 hi =====================
__global__ __launch_bounds__(256) void merge_kernel(
    const float* __restrict__ Wgate, const float* __restrict__ Wup, const float* __restrict__ Wdown,
    const float* __restrict__ Ag, const float* __restrict__ Bg,
    const float* __restrict__ Au, const float* __restrict__ Bu,
    const float* __restrict__ Ad, const float* __restrict__ Bd) {
    __shared__ float As[128][17];
    __shared__ float Bs[16][65];
    __shared__ unsigned short Thi[64][136];
    int e = blockIdx.y, t = blockIdx.x, tid = threadIdx.x;
    const float *src, *Ap, *Bp;
    unsigned short *dhi;
    int r0, c0, rowStride, outStride;
    if (t < 352) {
        int kt = t / 44, ft = t % 44;
        r0 = kt * 128; c0 = ft * 64; rowStride = Ff; outStride = Dd;
        src = Wgate + (size_t)e * Dd * Ff; Ap = Ag + (size_t)e * Dd * Rr; Bp = Bg + (size_t)e * Rr * Ff;
        dhi = g_WgH + (size_t)e * Ff * Dd;
    } else if (t < 704) {
        t -= 352;
        int kt = t / 44, ft = t % 44;
        r0 = kt * 128; c0 = ft * 64; rowStride = Ff; outStride = Dd;
        src = Wup + (size_t)e * Dd * Ff; Ap = Au + (size_t)e * Dd * Rr; Bp = Bu + (size_t)e * Rr * Ff;
        dhi = g_WuH + (size_t)e * Ff * Dd;
    } else {
        t -= 704;
        int kt = t / 16, ft = t % 16;
        r0 = kt * 128; c0 = ft * 64; rowStride = Dd; outStride = Ff;
        src = Wdown + (size_t)e * Ff * Dd; Ap = Ad + (size_t)e * Ff * Rr; Bp = Bd + (size_t)e * Rr * Dd;
        dhi = g_WdH + (size_t)e * Dd * Ff;
    }
    {
        int r = tid >> 1, k0 = (tid & 1) * 8;
#pragma unroll
        for (int kk = 0; kk < 8; kk++)
            As[r][k0 + kk] = Ap[(size_t)(r0 + r) * Rr + k0 + kk];
    }
    for (int i = tid; i < 1024; i += 256) {
        int k = i >> 6, c = i & 63;
        Bs[k][c] = Bp[(size_t)k * rowStride + c0 + c];
    }
    __syncthreads();
    {
        int c = tid & 63, rb = tid >> 6;
        float vbuf[32];
        for (int rr = 0; rr < 32; rr++) {
            int r = rb * 32 + rr;
            float v = src[(size_t)(r0 + r) * rowStride + c0 + c];
#pragma unroll
            for (int k = 0; k < 16; k++) v += As[r][k] * Bs[k][c];
            vbuf[rr] = v;
        }
        for (int w = 0; w < 32; w++) {
            int rr = (w + c) & 31;
            Thi[c][rb * 32 + rr] = __half_as_ushort(__float2half_rn(vbuf[rr]));
        }
    }
    __syncthreads();
    {
        int c = tid >> 2, qq = tid & 3;
        const uint4* sh = (const uint4*)&Thi[c][qq * 32];
        uint4* dH = (uint4*)(dhi + (size_t)(c0 + c) * outStride + r0 + qq * 32);
#pragma unroll
        for (int m = 0; m < 4; m++) dH[m] = sh[m];
    }
}

// ===================== fused gate logits via mma.sync =====================
#define LG_AHI 0
#define LG_ALO 17408
#define LG_B0  34816
#define LG_BSTG 34816
#define LG_RED (LG_B0 + 2 * LG_BSTG)
#define LG_B2  (LG_RED + 768)
#define LG_CG  (LG_B2 + 4096)
#define LG_SMEM (LG_CG + 4096)

__global__ __launch_bounds__(256) void logits_kernel(const float* __restrict__ b2) {
    extern __shared__ char sm[];
    uint32_t sb = smem_u32(sm);
    int e = blockIdx.y, n0 = blockIdx.x * 64;
    int tid = threadIdx.x, lane = tid & 31, wid = tid >> 5;
    int wy = wid & 3, wx = wid >> 2;

    if (tid < 192) ((float*)(sm + LG_RED))[tid] = 0.f;
#pragma unroll
    for (int i = 0; i < 4; i++) {
        ((float*)(sm + LG_B2))[tid + 256 * i] = b2[tid + 256 * i];
        ((float*)(sm + LG_CG))[tid + 256 * i] = g_cgw[tid + 256 * i];
    }
    {
        int t = tid >> 2, kq = (tid & 3) * 32;
        const float4* bp = (const float4*)(g_base + (size_t)(n0 + t) * HIDk + kq);
        const float4* pp = (const float4*)(g_pk + e * HIDk + kq);
        unsigned short* ah = (unsigned short*)(sm + LG_AHI) + t * 136 + kq;
        unsigned short* al = (unsigned short*)(sm + LG_ALO) + t * 136 + kq;
#pragma unroll
        for (int q = 0; q < 8; q++) {
            float4 a = bp[q], p = pp[q];
            float v[4] = {fmaxf(a.x + p.x, 0.f), fmaxf(a.y + p.y, 0.f),
                          fmaxf(a.z + p.z, 0.f), fmaxf(a.w + p.w, 0.f)};
#pragma unroll
            for (int c = 0; c < 4; c++) {
                unsigned short hi, lo;
                f2h_split(v[c], hi, lo);
                ah[q * 4 + c] = hi;
                al[q * 4 + c] = lo;
            }
        }
    }
    uint32_t sdst[8];
    uint32_t gofs[8];
    int ghl[8];
#pragma unroll
    for (int j = 0; j < 8; j++) {
        int sid = tid + 256 * j;
        int hl = sid >> 10;
        int rid = sid & 1023;
        int row = rid >> 4, seg = rid & 15;
        sdst[j] = (uint32_t)(hl * 17408 + row * 272 + seg * 16);
        gofs[j] = (uint32_t)(row * HIDk + seg * 8);
        ghl[j] = hl;
    }
#pragma unroll
    for (int j = 0; j < 8; j++) {
        const unsigned short* g = (ghl[j] ? g_W2TL : g_W2TH) + gofs[j];
        CPASYNC16(sb + LG_B0 + sdst[j], (const char*)g);
    }
    CP_COMMIT();
    __syncthreads();

    float s1[2] = {0.f, 0.f}, s2[2] = {0.f, 0.f}, s3[2] = {0.f, 0.f};
    uint32_t aoff = (uint32_t)((wy * 16 + (lane & 15)) * 272 + (lane >> 4) * 16);
    uint32_t boff = (uint32_t)(((wx * 32 + ((lane & 7) | ((lane >> 4) << 3))) * 272) + ((lane >> 3) & 1) * 16);

    for (int ch = 0; ch < 16; ch++) {
        if (ch + 1 < 16) {
            uint32_t stg = sb + LG_B0 + ((ch + 1) & 1) * LG_BSTG;
            uint32_t dadd = (uint32_t)((ch + 1) * 64 * HIDk);
#pragma unroll
            for (int j = 0; j < 8; j++) {
                const unsigned short* g = (ghl[j] ? g_W2TL : g_W2TH) + gofs[j] + dadd;
                CPASYNC16(stg + sdst[j], (const char*)g);
            }
            CP_COMMIT();
            CP_WAIT(1);
        } else {
            CP_WAIT(0);
        }
        __syncthreads();
        uint32_t sB = sb + LG_B0 + (ch & 1) * LG_BSTG;
        float acc[4][4];
#pragma unroll
        for (int a = 0; a < 4; a++)
#pragma unroll
            for (int c = 0; c < 4; c++) acc[a][c] = 0.f;
#pragma unroll
        for (int k16 = 0; k16 < 8; k16++) {
            uint32_t kb = (uint32_t)(k16 * 32);
            uint32_t ahr[4], alr[4], bh[2][4], bl[2][4];
            LDSM4(ahr, sb + LG_AHI + aoff + kb);
            LDSM4(alr, sb + LG_ALO + aoff + kb);
            LDSM4(bh[0], sB + boff + kb);
            LDSM4(bh[1], sB + boff + 16 * 272 + kb);
            LDSM4(bl[0], sB + 17408 + boff + kb);
            LDSM4(bl[1], sB + 17408 + boff + 16 * 272 + kb);
#pragma unroll
            for (int nt = 0; nt < 2; nt++)
#pragma unroll
                for (int h = 0; h < 2; h++) {
                    MMA16816(acc[nt * 2 + h], ahr, bh[nt][2 * h], bh[nt][2 * h + 1]);
                    MMA16816(acc[nt * 2 + h], alr, bh[nt][2 * h], bh[nt][2 * h + 1]);
                    MMA16816(acc[nt * 2 + h], ahr, bl[nt][2 * h], bl[nt][2 * h + 1]);
                }
        }
#pragma unroll
        for (int nt4 = 0; nt4 < 4; nt4++) {
            int col = ch * 64 + wx * 32 + nt4 * 8 + (lane & 3) * 2;
            float b0 = ((float*)(sm + LG_B2))[col], b1v = ((float*)(sm + LG_B2))[col + 1];
            float c0 = ((float*)(sm + LG_CG))[col], c1v = ((float*)(sm + LG_CG))[col + 1];
            float f;
            f = fmaxf(acc[nt4][0] + b0, 0.f);  s1[0] += f * c0;  s2[0] += f; s3[0] += f * f;
            f = fmaxf(acc[nt4][1] + b1v, 0.f); s1[0] += f * c1v; s2[0] += f; s3[0] += f * f;
            f = fmaxf(acc[nt4][2] + b0, 0.f);  s1[1] += f * c0;  s2[1] += f; s3[1] += f * f;
            f = fmaxf(acc[nt4][3] + b1v, 0.f); s1[1] += f * c1v; s2[1] += f; s3[1] += f * f;
        }
        __syncthreads();
    }
#pragma unroll
    for (int off = 1; off <= 2; off <<= 1) {
#pragma unroll
        for (int i = 0; i < 2; i++) {
            s1[i] += __shfl_xor_sync(0xffffffffu, s1[i], off);
            s2[i] += __shfl_xor_sync(0xffffffffu, s2[i], off);
            s3[i] += __shfl_xor_sync(0xffffffffu, s3[i], off);
        }
    }
    if ((lane & 3) == 0) {
        int row = wy * 16 + (lane >> 2);
        float* red = (float*)(sm + LG_RED);
        atomicAdd(&red[row],           s1[0]);
        atomicAdd(&red[row + 8],       s1[1]);
        atomicAdd(&red[64 + row],      s2[0]);
        atomicAdd(&red[64 + row + 8],  s2[1]);
        atomicAdd(&red[128 + row],     s3[0]);
        atomicAdd(&red[128 + row + 8], s3[1]);
    }
    __syncthreads();
    if (tid < 64) {
        float* red = (float*)(sm + LG_RED);
        float S1 = red[tid], S2 = red[64 + tid], S3 = red[128 + tid];
        float Cg = g_CgCb[0], Cb = g_CgCb[1];
        float mu = S2 * (1.f / (float)Dd);
        float var = S3 * (1.f / (float)Dd) - mu * mu;
        float rstd = rsqrtf(var + LN_EPS);
        g_logits[(size_t)(n0 + tid) * Ee + e] = rstd * (S1 - mu * Cg) + Cb;
    }
}

// ===================== routing =====================
__global__ void route_kernel() {
    int n = blockIdx.x * 256 + threadIdx.x;
    float l[Ee];
    float m = -1e30f;
#pragma unroll
    for (int e = 0; e < Ee; e++) { l[e] = g_logits[(size_t)n * Ee + e]; m = fmaxf(m, l[e]); }
    float s = 0.f;
#pragma unroll
    for (int e = 0; e < Ee; e++) { l[e] = expf(l[e] - m); s += l[e]; }
    float inv = 1.f / s;
#pragma unroll
    for (int e = 0; e < Ee; e++) l[e] *= inv;
    int i0 = 0; float b0 = l[0];
#pragma unroll
    for (int e = 1; e < Ee; e++) if (l[e] > b0) { b0 = l[e]; i0 = e; }
    int i1 = -1; float b1 = -1.f;
#pragma unroll
    for (int e = 0; e < Ee; e++) if (e != i0 && l[e] > b1) { b1 = l[e]; i1 = e; }
    int p0 = atomicAdd(&g_cnt[i0], 1);
    int p1 = atomicAdd(&g_cnt[i1], 1);
    g_te[2 * n] = i0; g_tp[2 * n] = p0; g_tw[2 * n] = b0;
    g_te[2 * n + 1] = i1; g_tp[2 * n + 1] = p1; g_tw[2 * n + 1] = b1;
}

__global__ void scan_kernel() {
    int a = 0;
    for (int e = 0; e < Ee; e++) { g_off[e] = a; a += g_cnt[e]; }
}

__global__ void scatter_kernel() {
    int n = blockIdx.x * 256 + threadIdx.x;
#pragma unroll
    for (int i = 0; i < 2; i++) {
        int slot = g_off[g_te[2 * n + i]] + g_tp[2 * n + i];
        g_ptok[slot] = n;
        g_pw[slot] = g_tw[2 * n + i];
    }
}

// ===================== expert GEMM1 (1-term; gate+up; 3-stage) =====================
#define G1_STAGE 20480
#define G1_SMEM (1024 + 3 * G1_STAGE)

__global__ __launch_bounds__(256, 2) void moe_gemm1() {
    extern __shared__ char sm[];
    int e = blockIdx.z;
    int cnt = g_cnt[e];
    int r0 = blockIdx.x * 128;
    if (r0 >= cnt) return;
    int off = g_off[e];
    int f0 = blockIdx.y * 64;
    int tid = threadIdx.x, lane = tid & 31, wid = tid >> 5;
    int wy = wid & 3, wx = wid >> 2;

    int* stok = (int*)sm;
    if (tid < 128) {
        int lr = r0 + tid; if (lr >= cnt) lr = cnt - 1;
        stok[tid] = g_ptok[off + lr];
    }
    __syncthreads();

    uint32_t sb0 = smem_u32(sm) + 1024;

    uint32_t sdst[4];
    const char* gsrc[4];
#pragma unroll
    for (int j = 0; j < 4; j++) {
        int sid = tid + 256 * j;
        int region = sid >> 9;
        int rid = sid & 511;
        int row = rid >> 2, seg = rid & 3;
        sdst[j] = (uint32_t)(region * 10240 + row * 80 + seg * 16);
        const unsigned short* g;
        if (region == 0) g = g_xh + (size_t)stok[row] * Dd;
        else             g = (row < 64) ? g_WgH + ((size_t)e * Ff + f0 + row) * Dd
                                        : g_WuH + ((size_t)e * Ff + f0 + row - 64) * Dd;
        gsrc[j] = (const char*)(g + seg * 8);
    }

    float accG[2][4][4], accU[2][4][4];
#pragma unroll
    for (int a = 0; a < 2; a++)
#pragma unroll
        for (int b = 0; b < 4; b++)
#pragma unroll
            for (int c = 0; c < 4; c++) { accG[a][b][c] = 0.f; accU[a][b][c] = 0.f; }

    uint32_t aoff = (uint32_t)((wy * 32 + (lane & 15)) * 80 + (lane >> 4) * 16);
    uint32_t boff = (uint32_t)((wx * 32 + ((lane & 7) | ((lane >> 4) << 3))) * 80 + ((lane >> 3) & 1) * 16);

    const int NCH = 32;
#pragma unroll
    for (int j = 0; j < 4; j++) CPASYNC16(sb0 + sdst[j], gsrc[j]);
    CP_COMMIT();
#pragma unroll
    for (int j = 0; j < 4; j++) CPASYNC16(sb0 + G1_STAGE + sdst[j], gsrc[j] + 64);
    CP_COMMIT();

    for (int ch = 0; ch < NCH; ch++) {
        if (ch == NCH - 1) { CP_WAIT(0); } else { CP_WAIT(1); }
        __syncthreads();
        if (ch + 2 < NCH) {
            uint32_t stg = sb0 + ((ch + 2) % 3) * G1_STAGE;
            int cb = (ch + 2) * 64;
#pragma unroll
            for (int j = 0; j < 4; j++) CPASYNC16(stg + sdst[j], gsrc[j] + cb);
            CP_COMMIT();
        }
        uint32_t s = sb0 + (ch % 3) * G1_STAGE;
#pragma unroll
        for (int k16 = 0; k16 < 2; k16++) {
            uint32_t kb = k16 * 32;
            uint32_t ah[2][4], bg[2][4], bu[2][4];
#pragma unroll
            for (int mt = 0; mt < 2; mt++)
                LDSM4(ah[mt], s + aoff + mt * (16 * 80) + kb);
#pragma unroll
            for (int nt = 0; nt < 2; nt++) {
                LDSM4(bg[nt], s + 10240 + boff + nt * (16 * 80) + kb);
                LDSM4(bu[nt], s + 10240 + 5120 + boff + nt * (16 * 80) + kb);
            }
#pragma unroll
            for (int mt = 0; mt < 2; mt++)
#pragma unroll
                for (int nt = 0; nt < 2; nt++)
#pragma unroll
                    for (int h = 0; h < 2; h++) {
                        MMA16816(accG[mt][nt * 2 + h], ah[mt], bg[nt][2 * h], bg[nt][2 * h + 1]);
                        MMA16816(accU[mt][nt * 2 + h], ah[mt], bu[nt][2 * h], bu[nt][2 * h + 1]);
                    }
        }
    }

#pragma unroll
    for (int mt = 0; mt < 2; mt++)
#pragma unroll
        for (int rh = 0; rh < 2; rh++) {
            int lr = wy * 32 + mt * 16 + (lane >> 2) + rh * 8;
            if (r0 + lr < cnt) {
                int slot = off + r0 + lr;
#pragma unroll
                for (int nt8 = 0; nt8 < 4; nt8++) {
                    int col = f0 + wx * 32 + nt8 * 8 + (lane & 3) * 2;
                    float g0 = accG[mt][nt8][rh * 2 + 0], g1 = accG[mt][nt8][rh * 2 + 1];
                    float u0 = accU[mt][nt8][rh * 2 + 0], u1 = accU[mt][nt8][rh * 2 + 1];
                    float h0 = g0 / (1.f + __expf(-g0)) * u0;
                    float h1 = g1 / (1.f + __expf(-g1)) * u1;
                    unsigned short a0, b0, a1, b1;
                    f2h_split(h0, a0, b0);
                    f2h_split(h1, a1, b1);
                    size_t idx = ((size_t)slot * Ff + col) >> 1;
                    ((uint32_t*)g_Hh)[idx] = (uint32_t)a0 | ((uint32_t)a1 << 16);
                    ((uint32_t*)g_Hl)[idx] = (uint32_t)b0 | ((uint32_t)b1 << 16);
                }
            }
        }
}

// ===================== expert GEMM2 (2-term: AhBh + AlBh; 3-stage) =====================
#define G2_STAGE 25600
#define G2_SMEM (3 * G2_STAGE)

__global__ __launch_bounds__(256, 2) void moe_gemm2(float* __restrict__ out) {
    extern __shared__ char sm[];
    int e = blockIdx.z;
    int cnt = g_cnt[e];
    int r0 = blockIdx.y * 128;
    if (r0 >= cnt) return;
    int off = g_off[e];
    int d0 = blockIdx.x * 64;
    int tid = threadIdx.x, lane = tid & 31, wid = tid >> 5;
    int wy = wid & 3, wx = wid >> 2;

    uint32_t sb0 = smem_u32(sm);

    uint32_t sdst[5];
    const char* gsrc[5];
#pragma unroll
    for (int j = 0; j < 5; j++) {
        int sid = tid + 256 * j;
        const unsigned short* g;
        uint32_t so;
        if (sid < 1024) {
            int hl = sid >> 9;
            int rid = sid & 511;
            int row = rid >> 2, seg = rid & 3;
            so = hl * 10240u + row * 80u + seg * 16u;
            int lr = r0 + row; if (lr >= cnt) lr = cnt - 1;
            g = (hl == 0 ? g_Hh : g_Hl) + (size_t)(off + lr) * Ff + seg * 8;
        } else {
            int rid = sid - 1024;
            int row = rid >> 2, seg = rid & 3;
            so = 20480u + row * 80u + seg * 16u;
            g = g_WdH + ((size_t)e * Dd + d0 + row) * Ff + seg * 8;
        }
        sdst[j] = so;
        gsrc[j] = (const char*)g;
    }

    float acc[2][4][4];
#pragma unroll
    for (int a = 0; a < 2; a++)
#pragma unroll
        for (int b = 0; b < 4; b++)
#pragma unroll
            for (int c = 0; c < 4; c++) acc[a][b][c] = 0.f;

    uint32_t aoff = (uint32_t)((wy * 32 + (lane & 15)) * 80 + (lane >> 4) * 16);
    uint32_t boff = (uint32_t)((wx * 32 + ((lane & 7) | ((lane >> 4) << 3))) * 80 + ((lane >> 3) & 1) * 16);

    const int NCH = 88;
#pragma unroll
    for (int j = 0; j < 5; j++) CPASYNC16(sb0 + sdst[j], gsrc[j]);
    CP_COMMIT();
#pragma unroll
    for (int j = 0; j < 5; j++) CPASYNC16(sb0 + G2_STAGE + sdst[j], gsrc[j] + 64);
    CP_COMMIT();

    for (int ch = 0; ch < NCH; ch++) {
        if (ch == NCH - 1) { CP_WAIT(0); } else { CP_WAIT(1); }
        __syncthreads();
        if (ch + 2 < NCH) {
            uint32_t stg = sb0 + ((ch + 2) % 3) * G2_STAGE;
            int cb = (ch + 2) * 64;
#pragma unroll
            for (int j = 0; j < 5; j++) CPASYNC16(stg + sdst[j], gsrc[j] + cb);
            CP_COMMIT();
        }
        uint32_t s = sb0 + (ch % 3) * G2_STAGE;
#pragma unroll
        for (int k16 = 0; k16 < 2; k16++) {
            uint32_t kb = k16 * 32;
            uint32_t ah[2][4], al[2][4], bf[2][4];
#pragma unroll
            for (int mt = 0; mt < 2; mt++) {
                LDSM4(ah[mt], s + aoff + mt * (16 * 80) + kb);
                LDSM4(al[mt], s + 10240 + aoff + mt * (16 * 80) + kb);
            }
#pragma unroll
            for (int nt = 0; nt < 2; nt++) LDSM4(bf[nt], s + 20480 + boff + nt * (16 * 80) + kb);
#pragma unroll
            for (int mt = 0; mt < 2; mt++)
#pragma unroll
                for (int nt = 0; nt < 2; nt++)
#pragma unroll
                    for (int h = 0; h < 2; h++) {
                        MMA16816(acc[mt][nt * 2 + h], ah[mt], bf[nt][2 * h], bf[nt][2 * h + 1]);
                        MMA16816(acc[mt][nt * 2 + h], al[mt], bf[nt][2 * h], bf[nt][2 * h + 1]);
                    }
        }
    }

#pragma unroll
    for (int mt = 0; mt < 2; mt++)
#pragma unroll
        for (int rh = 0; rh < 2; rh++) {
            int lr = wy * 32 + mt * 16 + (lane >> 2) + rh * 8;
            if (r0 + lr < cnt) {
                int slot = off + r0 + lr;
                int tok = g_ptok[slot];
                float w = g_pw[slot];
                float* op = out + (size_t)tok * Dd + d0 + wx * 32 + (lane & 3) * 2;
#pragma unroll
                for (int nt8 = 0; nt8 < 4; nt8++) {
                    atomicAdd(op + nt8 * 8,     acc[mt][nt8][rh * 2 + 0] * w);
                    atomicAdd(op + nt8 * 8 + 1, acc[mt][nt8][rh * 2 + 1] * w);
                }
            }
        }
}

// ===================== launch =====================
extern "C" void kernel_launch(void* const* d_in, const int* in_sizes, int n_in,
                              void* d_out, int out_size) {
    (void)in_sizes; (void)n_in;
    const float* x       = (const float*)d_in[0];
    const float* hist    = (const float*)d_in[1];
    const float* persona = (const float*)d_in[2];
    const float* W1x     = (const float*)d_in[3];
    const float* W1h     = (const float*)d_in[4];
    const float* W1p     = (const float*)d_in[5];
    const float* b1      = (const float*)d_in[6];
    const float* W2      = (const float*)d_in[7];
    const float* b2      = (const float*)d_in[8];
    const float* ln_g    = (const float*)d_in[9];
    const float* ln_b    = (const float*)d_in[10];
    const float* Wg      = (const float*)d_in[11];
    const float* bg      = (const float*)d_in[12];
    const float* Wgate   = (const float*)d_in[13];
    const float* Wup     = (const float*)d_in[14];
    const float* Wdown   = (const float*)d_in[15];
    const float* Ag      = (const float*)d_in[16];
    const float* Bg      = (const float*)d_in[17];
    const float* Au      = (const float*)d_in[18];
    const float* Bu      = (const float*)d_in[19];
    const float* Ad      = (const float*)d_in[20];
    const float* Bd      = (const float*)d_in[21];
    float* out = (float*)d_out;

    cudaFuncSetAttribute(moe_gemm1, cudaFuncAttributeMaxDynamicSharedMemorySize, G1_SMEM);
    cudaFuncSetAttribute(moe_gemm2, cudaFuncAttributeMaxDynamicSharedMemorySize, G2_SMEM);
    cudaFuncSetAttribute(logits_kernel, cudaFuncAttributeMaxDynamicSharedMemorySize, LG_SMEM);
    cudaFuncSetAttribute(base_mma, cudaFuncAttributeMaxDynamicSharedMemorySize, BM_SMEM);

    void* cntp = nullptr;
    cudaGetSymbolAddress(&cntp, g_cnt);

    cudaMemsetAsync(out, 0, (size_t)out_size * sizeof(float));
    cudaMemsetAsync(cntp, 0, Ee * sizeof(int));

    prep_kernel<<<13, 128>>>(hist, W1h, b1, persona, W1p, ln_g, ln_b, Wg, bg);
    w2t_kernel<<<dim3(Dd / 32, HIDk / 32), 256>>>(W2);
    w1t_kernel<<<dim3(HIDk / 32, Dd / 32), 256>>>(W1x);
    xconv_kernel<<<(Nn * Dd) / 4 / 256, 256>>>(x);
    base_mma<<<Nn / 64, 256, BM_SMEM>>>();
    merge_kernel<<<dim3(1056, Ee), 256>>>(Wgate, Wup, Wdown, Ag, Bg, Au, Bu, Ad, Bd);
    logits_kernel<<<dim3(Nn / 64, Ee), 256, LG_SMEM>>>(b2);
    route_kernel<<<Nn / 256, 256>>>();
    scan_kernel<<<1, 1>>>();
    scatter_kernel<<<Nn / 256, 256>>>();
    moe_gemm1<<<dim3(NP / 128, Ff / 64, Ee), 256, G1_SMEM>>>();
    moe_gemm2<<<dim3(Dd / 64, NP / 128, Ee), 256, G2_SMEM>>>(out);
}

// round 8
// speedup vs baseline: 6.1041x; 1.1385x over previous
#include <cuda_runtime.h>
#include <cuda_fp16.h>
#include <math.h>
#include <stdint.h>

#define Bb 4
#define Ss 2048
#define Dd 1024
#define Hh 512
#define Ee 8
#define Ff 2816
#define Rr 16
#define HIDk 128
#define Nn 8192
#define NP 16384
#define LN_EPS 1e-5f

// ===================== baseline-PTX helpers =====================
__device__ __forceinline__ uint32_t smem_u32(const void* p) {
    uint32_t a;
    asm("{ .reg .u64 t; cvta.to.shared.u64 t, %1; cvt.u32.u64 %0, t; }" : "=r"(a) : "l"(p));
    return a;
}

#define CPASYNC16(dst, src) \
    asm volatile("cp.async.cg.shared.global [%0], [%1], 16;\n" :: "r"(dst), "l"(src))
#define CP_COMMIT() asm volatile("cp.async.commit_group;\n" ::: "memory")
#define CP_WAIT(N)  asm volatile("cp.async.wait_group %0;\n" :: "n"(N) : "memory")

#define LDSM4(R, addr) \
    asm volatile("ldmatrix.sync.aligned.m8n8.x4.shared.b16 {%0,%1,%2,%3}, [%4];" \
        : "=r"((R)[0]), "=r"((R)[1]), "=r"((R)[2]), "=r"((R)[3]) : "r"(addr))

#define MMA16816(C, A, B0, B1) \
    asm volatile("mma.sync.aligned.m16n8k16.row.col.f32.f16.f16.f32 " \
        "{%0,%1,%2,%3}, {%4,%5,%6,%7}, {%8,%9}, {%0,%1,%2,%3};" \
        : "+f"((C)[0]), "+f"((C)[1]), "+f"((C)[2]), "+f"((C)[3]) \
        : "r"((A)[0]), "r"((A)[1]), "r"((A)[2]), "r"((A)[3]), "r"(B0), "r"(B1))

__device__ __forceinline__ void f2h_split(float v, unsigned short& hi, unsigned short& lo) {
    __half h = __float2half_rn(v);
    hi = __half_as_ushort(h);
    lo = __half_as_ushort(__float2half_rn(v - __half2float(h)));
}

// ===================== static device scratch =====================
__device__ float g_base[Nn * HIDk];
__device__ float g_hb[Bb * HIDk];
__device__ float g_pk[Ee * HIDk];
__device__ float g_cgw[Dd];
__device__ float g_CgCb[2];
__device__ float g_logits[Nn * Ee];
__device__ int   g_cnt[Ee];
__device__ int   g_off[Ee];
__device__ int   g_te[Nn * 2];
__device__ int   g_tp[Nn * 2];
__device__ float g_tw[Nn * 2];
__device__ int   g_ptok[NP];
__device__ float g_pw[NP];
// fp16 split storage
__device__ unsigned short g_xh[(size_t)Nn * Dd];
__device__ unsigned short g_xl[(size_t)Nn * Dd];
__device__ unsigned short g_WgH[(size_t)Ee * Ff * Dd];   // [e][f][d]  K-major (hi)
__device__ unsigned short g_WuH[(size_t)Ee * Ff * Dd];
__device__ unsigned short g_WdH[(size_t)Ee * Dd * Ff];   // [e][d][f]  K-major (hi)
__device__ unsigned short g_Hh[(size_t)NP * Ff];
__device__ unsigned short g_W2TH[(size_t)Dd * HIDk];     // W2^T [d][k] hi
__device__ unsigned short g_W2TL[(size_t)Dd * HIDk];     // lo
__device__ unsigned short g_W1TH[(size_t)HIDk * Dd];     // W1x^T [k][d] hi
__device__ unsigned short g_W1TL[(size_t)HIDk * Dd];     // lo

// ===================== prep =====================
__global__ void prep_kernel(const float* __restrict__ hist, const float* __restrict__ W1h,
                            const float* __restrict__ b1,
                            const float* __restrict__ persona, const float* __restrict__ W1p,
                            const float* __restrict__ ln_g, const float* __restrict__ ln_b,
                            const float* __restrict__ Wg, const float* __restrict__ bg) {
    int bx = blockIdx.x, tid = threadIdx.x;
    if (bx < 4) {
        float acc = b1[tid];
        const float* hr = hist + bx * Hh;
        for (int k = 0; k < Hh; k++) acc += hr[k] * W1h[k * HIDk + tid];
        g_hb[bx * HIDk + tid] = acc;
    } else if (bx < 12) {
        int e = bx - 4;
        float acc = 0.f;
        const float* pr = persona + e * Dd;
        for (int k = 0; k < Dd; k++) acc += pr[k] * W1p[k * HIDk + tid];
        g_pk[e * HIDk + tid] = acc;
    } else {
        __shared__ float sg[128], sb[128];
        float a = 0.f, b = 0.f;
        for (int d = tid; d < Dd; d += 128) {
            float w = Wg[d];
            float c = ln_g[d] * w;
            g_cgw[d] = c;
            a += c;
            b += ln_b[d] * w;
        }
        sg[tid] = a; sb[tid] = b;
        __syncthreads();
        for (int s = 64; s > 0; s >>= 1) {
            if (tid < s) { sg[tid] += sg[tid + s]; sb[tid] += sb[tid + s]; }
            __syncthreads();
        }
        if (tid == 0) { g_CgCb[0] = sg[0]; g_CgCb[1] = sb[0] + bg[0]; }
    }
}

// ===================== W2 -> W2^T fp16 hi/lo =====================
__global__ void w2t_kernel(const float* __restrict__ W2) {
    __shared__ float T[32][33];
    int d0 = blockIdx.x * 32, k0 = blockIdx.y * 32;
    int tid = threadIdx.x;
#pragma unroll
    for (int i = 0; i < 4; i++) {
        int kk = (tid >> 5) + i * 8, dd = tid & 31;
        T[kk][dd] = W2[(size_t)(k0 + kk) * Dd + d0 + dd];
    }
    __syncthreads();
#pragma unroll
    for (int i = 0; i < 4; i++) {
        int dd = (tid >> 5) + i * 8, kk = tid & 31;
        unsigned short hi, lo;
        f2h_split(T[kk][dd], hi, lo);
        g_W2TH[(size_t)(d0 + dd) * HIDk + k0 + kk] = hi;
        g_W2TL[(size_t)(d0 + dd) * HIDk + k0 + kk] = lo;
    }
}

// ===================== W1x -> W1x^T fp16 hi/lo =====================
__global__ void w1t_kernel(const float* __restrict__ W1x) {
    __shared__ float T[32][33];
    int k0 = blockIdx.x * 32, d0 = blockIdx.y * 32;
    int tid = threadIdx.x;
#pragma unroll
    for (int i = 0; i < 4; i++) {
        int dd = (tid >> 5) + i * 8, kk = tid & 31;
        T[dd][kk] = W1x[(size_t)(d0 + dd) * HIDk + k0 + kk];
    }
    __syncthreads();
#pragma unroll
    for (int i = 0; i < 4; i++) {
        int kk = (tid >> 5) + i * 8, dd = tid & 31;
        unsigned short hi, lo;
        f2h_split(T[dd][kk], hi, lo);
        g_W1TH[(size_t)(k0 + kk) * Dd + d0 + dd] = hi;
        g_W1TL[(size_t)(k0 + kk) * Dd + d0 + dd] = lo;
    }
}

// ===================== x -> fp16 hi/lo =====================
__global__ void xconv_kernel(const float* __restrict__ x) {
    size_t i = (size_t)blockIdx.x * 256 + threadIdx.x;
    float4 v = ((const float4*)x)[i];
    unsigned short h0, l0, h1, l1, h2, l2, h3, l3;
    f2h_split(v.x, h0, l0); f2h_split(v.y, h1, l1);
    f2h_split(v.z, h2, l2); f2h_split(v.w, h3, l3);
    uint2 ph = make_uint2((uint32_t)h0 | ((uint32_t)h1 << 16), (uint32_t)h2 | ((uint32_t)h3 << 16));
    uint2 pl = make_uint2((uint32_t)l0 | ((uint32_t)l1 << 16), (uint32_t)l2 | ((uint32_t)l3 << 16));
    *(uint2*)(g_xh + i * 4) = ph;
    *(uint2*)(g_xl + i * 4) = pl;
}

// ===================== base = x @ W1x + hb (tensor-core, 3-term) =====================
#define BM_STAGE 30720
#define BM_SMEM (3 * BM_STAGE)

__global__ __launch_bounds__(256, 2) void base_mma() {
    extern __shared__ char sm[];
    int n0 = blockIdx.x * 64;
    int tid = threadIdx.x, lane = tid & 31, wid = tid >> 5;
    int wy = wid & 1, wx = wid >> 1;
    uint32_t sb0 = smem_u32(sm);

    uint32_t sdst[6];
    const char* gsrc[6];
#pragma unroll
    for (int j = 0; j < 6; j++) {
        int sid = tid + 256 * j;
        const unsigned short* g;
        uint32_t so;
        if (sid < 256) {
            int row = sid >> 2, seg = sid & 3;
            so = row * 80u + seg * 16u;
            g = g_xh + (size_t)(n0 + row) * Dd + seg * 8;
        } else if (sid < 512) {
            int rid = sid - 256;
            int row = rid >> 2, seg = rid & 3;
            so = 5120u + row * 80u + seg * 16u;
            g = g_xl + (size_t)(n0 + row) * Dd + seg * 8;
        } else if (sid < 1024) {
            int rid = sid - 512;
            int row = rid >> 2, seg = rid & 3;
            so = 10240u + row * 80u + seg * 16u;
            g = g_W1TH + (size_t)row * Dd + seg * 8;
        } else {
            int rid = sid - 1024;
            int row = rid >> 2, seg = rid & 3;
            so = 20480u + row * 80u + seg * 16u;
            g = g_W1TL + (size_t)row * Dd + seg * 8;
        }
        sdst[j] = so;
        gsrc[j] = (const char*)g;
    }

    float acc[2][4][4];
#pragma unroll
    for (int a = 0; a < 2; a++)
#pragma unroll
        for (int b = 0; b < 4; b++)
#pragma unroll
            for (int c = 0; c < 4; c++) acc[a][b][c] = 0.f;

    uint32_t aoff = (uint32_t)((wy * 32 + (lane & 15)) * 80 + (lane >> 4) * 16);
    uint32_t boff = (uint32_t)((wx * 32 + ((lane & 7) | ((lane >> 4) << 3))) * 80 + ((lane >> 3) & 1) * 16);

    const int NCH = 32;
#pragma unroll
    for (int j = 0; j < 6; j++) CPASYNC16(sb0 + sdst[j], gsrc[j]);
    CP_COMMIT();
#pragma unroll
    for (int j = 0; j < 6; j++) CPASYNC16(sb0 + BM_STAGE + sdst[j], gsrc[j] + 64);
    CP_COMMIT();

    for (int ch = 0; ch < NCH; ch++) {
        if (ch == NCH - 1) { CP_WAIT(0); } else { CP_WAIT(1); }
        __syncthreads();
        if (ch + 2 < NCH) {
            uint32_t stg = sb0 + ((ch + 2) % 3) * BM_STAGE;
            int cb = (ch + 2) * 64;
#pragma unroll
            for (int j = 0; j < 6; j++) CPASYNC16(stg + sdst[j], gsrc[j] + cb);
            CP_COMMIT();
        }
        uint32_t s = sb0 + (ch % 3) * BM_STAGE;
#pragma unroll
        for (int k16 = 0; k16 < 2; k16++) {
            uint32_t kb = k16 * 32;
            uint32_t ah[2][4], al[2][4], bh[2][4], bl[2][4];
#pragma unroll
            for (int mt = 0; mt < 2; mt++) {
                LDSM4(ah[mt], s + aoff + mt * (16 * 80) + kb);
                LDSM4(al[mt], s + 5120 + aoff + mt * (16 * 80) + kb);
            }
#pragma unroll
            for (int nt = 0; nt < 2; nt++) {
                LDSM4(bh[nt], s + 10240 + boff + nt * (16 * 80) + kb);
                LDSM4(bl[nt], s + 20480 + boff + nt * (16 * 80) + kb);
            }
#pragma unroll
            for (int mt = 0; mt < 2; mt++)
#pragma unroll
                for (int nt = 0; nt < 2; nt++)
#pragma unroll
                    for (int h = 0; h < 2; h++) {
                        MMA16816(acc[mt][nt * 2 + h], ah[mt], bh[nt][2 * h], bh[nt][2 * h + 1]);
                        MMA16816(acc[mt][nt * 2 + h], ah[mt], bl[nt][2 * h], bl[nt][2 * h + 1]);
                        MMA16816(acc[mt][nt * 2 + h], al[mt], bh[nt][2 * h], bh[nt][2 * h + 1]);
                    }
        }
    }

#pragma unroll
    for (int mt = 0; mt < 2; mt++)
#pragma unroll
        for (int rh = 0; rh < 2; rh++) {
            int row = n0 + wy * 32 + mt * 16 + (lane >> 2) + rh * 8;
            const float* hb = g_hb + (row >> 11) * HIDk;
#pragma unroll
            for (int nq = 0; nq < 4; nq++) {
                int col = wx * 32 + nq * 8 + (lane & 3) * 2;
                g_base[(size_t)row * HIDk + col]     = acc[mt][nq][rh * 2]     + hb[col];
                g_base[(size_t)row * HIDk + col + 1] = acc[mt][nq][rh * 2 + 1] + hb[col + 1];
            }
        }
}

// ===================== merge: W' = W + A@B -> transposed fp16 hi =====================
__global__ __launch_bounds__(256) void merge_kernel(
    const float* __restrict__ Wgate, const float* __restrict__ Wup, const float* __restrict__ Wdown,
    const float* __restrict__ Ag, const float* __restrict__ Bg,
    const float* __restrict__ Au, const float* __restrict__ Bu,
    const float* __restrict__ Ad, const float* __restrict__ Bd) {
    __shared__ float As[128][17];
    __shared__ float Bs[16][65];
    __shared__ unsigned short Thi[64][136];
    int e = blockIdx.y, t = blockIdx.x, tid = threadIdx.x;
    const float *src, *Ap, *Bp;
    unsigned short *dhi;
    int r0, c0, rowStride, outStride;
    if (t < 352) {
        int kt = t / 44, ft = t % 44;
        r0 = kt * 128; c0 = ft * 64; rowStride = Ff; outStride = Dd;
        src = Wgate + (size_t)e * Dd * Ff; Ap = Ag + (size_t)e * Dd * Rr; Bp = Bg + (size_t)e * Rr * Ff;
        dhi = g_WgH + (size_t)e * Ff * Dd;
    } else if (t < 704) {
        t -= 352;
        int kt = t / 44, ft = t % 44;
        r0 = kt * 128; c0 = ft * 64; rowStride = Ff; outStride = Dd;
        src = Wup + (size_t)e * Dd * Ff; Ap = Au + (size_t)e * Dd * Rr; Bp = Bu + (size_t)e * Rr * Ff;
        dhi = g_WuH + (size_t)e * Ff * Dd;
    } else {
        t -= 704;
        int kt = t / 16, ft = t % 16;
        r0 = kt * 128; c0 = ft * 64; rowStride = Dd; outStride = Ff;
        src = Wdown + (size_t)e * Ff * Dd; Ap = Ad + (size_t)e * Ff * Rr; Bp = Bd + (size_t)e * Rr * Dd;
        dhi = g_WdH + (size_t)e * Dd * Ff;
    }
    {
        int r = tid >> 1, k0 = (tid & 1) * 8;
#pragma unroll
        for (int kk = 0; kk < 8; kk++)
            As[r][k0 + kk] = Ap[(size_t)(r0 + r) * Rr + k0 + kk];
    }
    for (int i = tid; i < 1024; i += 256) {
        int k = i >> 6, c = i & 63;
        Bs[k][c] = Bp[(size_t)k * rowStride + c0 + c];
    }
    __syncthreads();
    {
        int c = tid & 63, rb = tid >> 6;
        float vbuf[32];
        for (int rr = 0; rr < 32; rr++) {
            int r = rb * 32 + rr;
            float v = src[(size_t)(r0 + r) * rowStride + c0 + c];
#pragma unroll
            for (int k = 0; k < 16; k++) v += As[r][k] * Bs[k][c];
            vbuf[rr] = v;
        }
        for (int w = 0; w < 32; w++) {
            int rr = (w + c) & 31;
            Thi[c][rb * 32 + rr] = __half_as_ushort(__float2half_rn(vbuf[rr]));
        }
    }
    __syncthreads();
    {
        int c = tid >> 2, qq = tid & 3;
        const uint4* sh = (const uint4*)&Thi[c][qq * 32];
        uint4* dH = (uint4*)(dhi + (size_t)(c0 + c) * outStride + r0 + qq * 32);
#pragma unroll
        for (int m = 0; m < 4; m++) dH[m] = sh[m];
    }
}

// ===================== fused gate logits via mma.sync =====================
#define LG_AHI 0
#define LG_ALO 17408
#define LG_B0  34816
#define LG_BSTG 34816
#define LG_RED (LG_B0 + 2 * LG_BSTG)
#define LG_B2  (LG_RED + 768)
#define LG_CG  (LG_B2 + 4096)
#define LG_SMEM (LG_CG + 4096)

__global__ __launch_bounds__(256) void logits_kernel(const float* __restrict__ b2) {
    extern __shared__ char sm[];
    uint32_t sb = smem_u32(sm);
    int e = blockIdx.y, n0 = blockIdx.x * 64;
    int tid = threadIdx.x, lane = tid & 31, wid = tid >> 5;
    int wy = wid & 3, wx = wid >> 2;

    if (tid < 192) ((float*)(sm + LG_RED))[tid] = 0.f;
#pragma unroll
    for (int i = 0; i < 4; i++) {
        ((float*)(sm + LG_B2))[tid + 256 * i] = b2[tid + 256 * i];
        ((float*)(sm + LG_CG))[tid + 256 * i] = g_cgw[tid + 256 * i];
    }
    {
        int t = tid >> 2, kq = (tid & 3) * 32;
        const float4* bp = (const float4*)(g_base + (size_t)(n0 + t) * HIDk + kq);
        const float4* pp = (const float4*)(g_pk + e * HIDk + kq);
        unsigned short* ah = (unsigned short*)(sm + LG_AHI) + t * 136 + kq;
        unsigned short* al = (unsigned short*)(sm + LG_ALO) + t * 136 + kq;
#pragma unroll
        for (int q = 0; q < 8; q++) {
            float4 a = bp[q], p = pp[q];
            float v[4] = {fmaxf(a.x + p.x, 0.f), fmaxf(a.y + p.y, 0.f),
                          fmaxf(a.z + p.z, 0.f), fmaxf(a.w + p.w, 0.f)};
#pragma unroll
            for (int c = 0; c < 4; c++) {
                unsigned short hi, lo;
                f2h_split(v[c], hi, lo);
                ah[q * 4 + c] = hi;
                al[q * 4 + c] = lo;
            }
        }
    }
    uint32_t sdst[8];
    uint32_t gofs[8];
    int ghl[8];
#pragma unroll
    for (int j = 0; j < 8; j++) {
        int sid = tid + 256 * j;
        int hl = sid >> 10;
        int rid = sid & 1023;
        int row = rid >> 4, seg = rid & 15;
        sdst[j] = (uint32_t)(hl * 17408 + row * 272 + seg * 16);
        gofs[j] = (uint32_t)(row * HIDk + seg * 8);
        ghl[j] = hl;
    }
#pragma unroll
    for (int j = 0; j < 8; j++) {
        const unsigned short* g = (ghl[j] ? g_W2TL : g_W2TH) + gofs[j];
        CPASYNC16(sb + LG_B0 + sdst[j], (const char*)g);
    }
    CP_COMMIT();
    __syncthreads();

    float s1[2] = {0.f, 0.f}, s2[2] = {0.f, 0.f}, s3[2] = {0.f, 0.f};
    uint32_t aoff = (uint32_t)((wy * 16 + (lane & 15)) * 272 + (lane >> 4) * 16);
    uint32_t boff = (uint32_t)(((wx * 32 + ((lane & 7) | ((lane >> 4) << 3))) * 272) + ((lane >> 3) & 1) * 16);

    for (int ch = 0; ch < 16; ch++) {
        if (ch + 1 < 16) {
            uint32_t stg = sb + LG_B0 + ((ch + 1) & 1) * LG_BSTG;
            uint32_t dadd = (uint32_t)((ch + 1) * 64 * HIDk);
#pragma unroll
            for (int j = 0; j < 8; j++) {
                const unsigned short* g = (ghl[j] ? g_W2TL : g_W2TH) + gofs[j] + dadd;
                CPASYNC16(stg + sdst[j], (const char*)g);
            }
            CP_COMMIT();
            CP_WAIT(1);
        } else {
            CP_WAIT(0);
        }
        __syncthreads();
        uint32_t sB = sb + LG_B0 + (ch & 1) * LG_BSTG;
        float acc[4][4];
#pragma unroll
        for (int a = 0; a < 4; a++)
#pragma unroll
            for (int c = 0; c < 4; c++) acc[a][c] = 0.f;
#pragma unroll
        for (int k16 = 0; k16 < 8; k16++) {
            uint32_t kb = (uint32_t)(k16 * 32);
            uint32_t ahr[4], alr[4], bh[2][4], bl[2][4];
            LDSM4(ahr, sb + LG_AHI + aoff + kb);
            LDSM4(alr, sb + LG_ALO + aoff + kb);
            LDSM4(bh[0], sB + boff + kb);
            LDSM4(bh[1], sB + boff + 16 * 272 + kb);
            LDSM4(bl[0], sB + 17408 + boff + kb);
            LDSM4(bl[1], sB + 17408 + boff + 16 * 272 + kb);
#pragma unroll
            for (int nt = 0; nt < 2; nt++)
#pragma unroll
                for (int h = 0; h < 2; h++) {
                    MMA16816(acc[nt * 2 + h], ahr, bh[nt][2 * h], bh[nt][2 * h + 1]);
                    MMA16816(acc[nt * 2 + h], alr, bh[nt][2 * h], bh[nt][2 * h + 1]);
                    MMA16816(acc[nt * 2 + h], ahr, bl[nt][2 * h], bl[nt][2 * h + 1]);
                }
        }
#pragma unroll
        for (int nt4 = 0; nt4 < 4; nt4++) {
            int col = ch * 64 + wx * 32 + nt4 * 8 + (lane & 3) * 2;
            float b0 = ((float*)(sm + LG_B2))[col], b1v = ((float*)(sm + LG_B2))[col + 1];
            float c0 = ((float*)(sm + LG_CG))[col], c1v = ((float*)(sm + LG_CG))[col + 1];
            float f;
            f = fmaxf(acc[nt4][0] + b0, 0.f);  s1[0] += f * c0;  s2[0] += f; s3[0] += f * f;
            f = fmaxf(acc[nt4][1] + b1v, 0.f); s1[0] += f * c1v; s2[0] += f; s3[0] += f * f;
            f = fmaxf(acc[nt4][2] + b0, 0.f);  s1[1] += f * c0;  s2[1] += f; s3[1] += f * f;
            f = fmaxf(acc[nt4][3] + b1v, 0.f); s1[1] += f * c1v; s2[1] += f; s3[1] += f * f;
        }
        __syncthreads();
    }
#pragma unroll
    for (int off = 1; off <= 2; off <<= 1) {
#pragma unroll
        for (int i = 0; i < 2; i++) {
            s1[i] += __shfl_xor_sync(0xffffffffu, s1[i], off);
            s2[i] += __shfl_xor_sync(0xffffffffu, s2[i], off);
            s3[i] += __shfl_xor_sync(0xffffffffu, s3[i], off);
        }
    }
    if ((lane & 3) == 0) {
        int row = wy * 16 + (lane >> 2);
        float* red = (float*)(sm + LG_RED);
        atomicAdd(&red[row],           s1[0]);
        atomicAdd(&red[row + 8],       s1[1]);
        atomicAdd(&red[64 + row],      s2[0]);
        atomicAdd(&red[64 + row + 8],  s2[1]);
        atomicAdd(&red[128 + row],     s3[0]);
        atomicAdd(&red[128 + row + 8], s3[1]);
    }
    __syncthreads();
    if (tid < 64) {
        float* red = (float*)(sm + LG_RED);
        float S1 = red[tid], S2 = red[64 + tid], S3 = red[128 + tid];
        float Cg = g_CgCb[0], Cb = g_CgCb[1];
        float mu = S2 * (1.f / (float)Dd);
        float var = S3 * (1.f / (float)Dd) - mu * mu;
        float rstd = rsqrtf(var + LN_EPS);
        g_logits[(size_t)(n0 + tid) * Ee + e] = rstd * (S1 - mu * Cg) + Cb;
    }
}

// ===================== routing =====================
__global__ void route_kernel() {
    int n = blockIdx.x * 256 + threadIdx.x;
    float l[Ee];
    float m = -1e30f;
#pragma unroll
    for (int e = 0; e < Ee; e++) { l[e] = g_logits[(size_t)n * Ee + e]; m = fmaxf(m, l[e]); }
    float s = 0.f;
#pragma unroll
    for (int e = 0; e < Ee; e++) { l[e] = expf(l[e] - m); s += l[e]; }
    float inv = 1.f / s;
#pragma unroll
    for (int e = 0; e < Ee; e++) l[e] *= inv;
    int i0 = 0; float b0 = l[0];
#pragma unroll
    for (int e = 1; e < Ee; e++) if (l[e] > b0) { b0 = l[e]; i0 = e; }
    int i1 = -1; float b1 = -1.f;
#pragma unroll
    for (int e = 0; e < Ee; e++) if (e != i0 && l[e] > b1) { b1 = l[e]; i1 = e; }
    int p0 = atomicAdd(&g_cnt[i0], 1);
    int p1 = atomicAdd(&g_cnt[i1], 1);
    g_te[2 * n] = i0; g_tp[2 * n] = p0; g_tw[2 * n] = b0;
    g_te[2 * n + 1] = i1; g_tp[2 * n + 1] = p1; g_tw[2 * n + 1] = b1;
}

__global__ void scan_kernel() {
    int a = 0;
    for (int e = 0; e < Ee; e++) { g_off[e] = a; a += g_cnt[e]; }
}

__global__ void scatter_kernel() {
    int n = blockIdx.x * 256 + threadIdx.x;
#pragma unroll
    for (int i = 0; i < 2; i++) {
        int slot = g_off[g_te[2 * n + i]] + g_tp[2 * n + i];
        g_ptok[slot] = n;
        g_pw[slot] = g_tw[2 * n + i];
    }
}

// ===================== expert GEMM1 (1-term; gate+up; 3-stage; ftile-fastest grid) =====================
#define G1_STAGE 20480
#define G1_SMEM (1024 + 3 * G1_STAGE)

__global__ __launch_bounds__(256, 2) void moe_gemm1() {
    extern __shared__ char sm[];
    int e = blockIdx.z;
    int cnt = g_cnt[e];
    int r0 = blockIdx.y * 128;
    if (r0 >= cnt) return;
    int off = g_off[e];
    int f0 = blockIdx.x * 64;
    int tid = threadIdx.x, lane = tid & 31, wid = tid >> 5;
    int wy = wid & 3, wx = wid >> 2;

    int* stok = (int*)sm;
    if (tid < 128) {
        int lr = r0 + tid; if (lr >= cnt) lr = cnt - 1;
        stok[tid] = g_ptok[off + lr];
    }
    __syncthreads();

    uint32_t sb0 = smem_u32(sm) + 1024;

    uint32_t sdst[4];
    const char* gsrc[4];
#pragma unroll
    for (int j = 0; j < 4; j++) {
        int sid = tid + 256 * j;
        int region = sid >> 9;
        int rid = sid & 511;
        int row = rid >> 2, seg = rid & 3;
        sdst[j] = (uint32_t)(region * 10240 + row * 80 + seg * 16);
        const unsigned short* g;
        if (region == 0) g = g_xh + (size_t)stok[row] * Dd;
        else             g = (row < 64) ? g_WgH + ((size_t)e * Ff + f0 + row) * Dd
                                        : g_WuH + ((size_t)e * Ff + f0 + row - 64) * Dd;
        gsrc[j] = (const char*)(g + seg * 8);
    }

    float accG[2][4][4], accU[2][4][4];
#pragma unroll
    for (int a = 0; a < 2; a++)
#pragma unroll
        for (int b = 0; b < 4; b++)
#pragma unroll
            for (int c = 0; c < 4; c++) { accG[a][b][c] = 0.f; accU[a][b][c] = 0.f; }

    uint32_t aoff = (uint32_t)((wy * 32 + (lane & 15)) * 80 + (lane >> 4) * 16);
    uint32_t boff = (uint32_t)((wx * 32 + ((lane & 7) | ((lane >> 4) << 3))) * 80 + ((lane >> 3) & 1) * 16);

    const int NCH = 32;
#pragma unroll
    for (int j = 0; j < 4; j++) CPASYNC16(sb0 + sdst[j], gsrc[j]);
    CP_COMMIT();
#pragma unroll
    for (int j = 0; j < 4; j++) CPASYNC16(sb0 + G1_STAGE + sdst[j], gsrc[j] + 64);
    CP_COMMIT();

    for (int ch = 0; ch < NCH; ch++) {
        if (ch == NCH - 1) { CP_WAIT(0); } else { CP_WAIT(1); }
        __syncthreads();
        if (ch + 2 < NCH) {
            uint32_t stg = sb0 + ((ch + 2) % 3) * G1_STAGE;
            int cb = (ch + 2) * 64;
#pragma unroll
            for (int j = 0; j < 4; j++) CPASYNC16(stg + sdst[j], gsrc[j] + cb);
            CP_COMMIT();
        }
        uint32_t s = sb0 + (ch % 3) * G1_STAGE;
#pragma unroll
        for (int k16 = 0; k16 < 2; k16++) {
            uint32_t kb = k16 * 32;
            uint32_t ah[2][4], bg[2][4], bu[2][4];
#pragma unroll
            for (int mt = 0; mt < 2; mt++)
                LDSM4(ah[mt], s + aoff + mt * (16 * 80) + kb);
#pragma unroll
            for (int nt = 0; nt < 2; nt++) {
                LDSM4(bg[nt], s + 10240 + boff + nt * (16 * 80) + kb);
                LDSM4(bu[nt], s + 10240 + 5120 + boff + nt * (16 * 80) + kb);
            }
#pragma unroll
            for (int mt = 0; mt < 2; mt++)
#pragma unroll
                for (int nt = 0; nt < 2; nt++)
#pragma unroll
                    for (int h = 0; h < 2; h++) {
                        MMA16816(accG[mt][nt * 2 + h], ah[mt], bg[nt][2 * h], bg[nt][2 * h + 1]);
                        MMA16816(accU[mt][nt * 2 + h], ah[mt], bu[nt][2 * h], bu[nt][2 * h + 1]);
                    }
        }
    }

#pragma unroll
    for (int mt = 0; mt < 2; mt++)
#pragma unroll
        for (int rh = 0; rh < 2; rh++) {
            int lr = wy * 32 + mt * 16 + (lane >> 2) + rh * 8;
            if (r0 + lr < cnt) {
                int slot = off + r0 + lr;
#pragma unroll
                for (int nt8 = 0; nt8 < 4; nt8++) {
                    int col = f0 + wx * 32 + nt8 * 8 + (lane & 3) * 2;
                    float g0 = accG[mt][nt8][rh * 2 + 0], g1 = accG[mt][nt8][rh * 2 + 1];
                    float u0 = accU[mt][nt8][rh * 2 + 0], u1 = accU[mt][nt8][rh * 2 + 1];
                    float h0 = g0 / (1.f + __expf(-g0)) * u0;
                    float h1 = g1 / (1.f + __expf(-g1)) * u1;
                    unsigned short a0 = __half_as_ushort(__float2half_rn(h0));
                    unsigned short a1 = __half_as_ushort(__float2half_rn(h1));
                    size_t idx = ((size_t)slot * Ff + col) >> 1;
                    ((uint32_t*)g_Hh)[idx] = (uint32_t)a0 | ((uint32_t)a1 << 16);
                }
            }
        }
}

// ===================== expert GEMM2 (1-term: AhBh; 3-stage; dtile-fastest grid) =====================
// stage: A_hi@0 (10240), B_hi@10240 (5120) = 15360
#define G2_STAGE 15360
#define G2_SMEM (3 * G2_STAGE)

__global__ __launch_bounds__(256, 2) void moe_gemm2(float* __restrict__ out) {
    extern __shared__ char sm[];
    int e = blockIdx.z;
    int cnt = g_cnt[e];
    int r0 = blockIdx.y * 128;
    if (r0 >= cnt) return;
    int off = g_off[e];
    int d0 = blockIdx.x * 64;
    int tid = threadIdx.x, lane = tid & 31, wid = tid >> 5;
    int wy = wid & 3, wx = wid >> 2;

    uint32_t sb0 = smem_u32(sm);

    uint32_t sdst[3];
    const char* gsrc[3];
#pragma unroll
    for (int j = 0; j < 3; j++) {
        int sid = tid + 256 * j;   // 0..767
        const unsigned short* g;
        uint32_t so;
        if (sid < 512) {
            int row = sid >> 2, seg = sid & 3;
            so = row * 80u + seg * 16u;
            int lr = r0 + row; if (lr >= cnt) lr = cnt - 1;
            g = g_Hh + (size_t)(off + lr) * Ff + seg * 8;
        } else {
            int rid = sid - 512;
            int row = rid >> 2, seg = rid & 3;
            so = 10240u + row * 80u + seg * 16u;
            g = g_WdH + ((size_t)e * Dd + d0 + row) * Ff + seg * 8;
        }
        sdst[j] = so;
        gsrc[j] = (const char*)g;
    }

    float acc[2][4][4];
#pragma unroll
    for (int a = 0; a < 2; a++)
#pragma unroll
        for (int b = 0; b < 4; b++)
#pragma unroll
            for (int c = 0; c < 4; c++) acc[a][b][c] = 0.f;

    uint32_t aoff = (uint32_t)((wy * 32 + (lane & 15)) * 80 + (lane >> 4) * 16);
    uint32_t boff = (uint32_t)((wx * 32 + ((lane & 7) | ((lane >> 4) << 3))) * 80 + ((lane >> 3) & 1) * 16);

    const int NCH = 88;
#pragma unroll
    for (int j = 0; j < 3; j++) CPASYNC16(sb0 + sdst[j], gsrc[j]);
    CP_COMMIT();
#pragma unroll
    for (int j = 0; j < 3; j++) CPASYNC16(sb0 + G2_STAGE + sdst[j], gsrc[j] + 64);
    CP_COMMIT();

    for (int ch = 0; ch < NCH; ch++) {
        if (ch == NCH - 1) { CP_WAIT(0); } else { CP_WAIT(1); }
        __syncthreads();
        if (ch + 2 < NCH) {
            uint32_t stg = sb0 + ((ch + 2) % 3) * G2_STAGE;
            int cb = (ch + 2) * 64;
#pragma unroll
            for (int j = 0; j < 3; j++) CPASYNC16(stg + sdst[j], gsrc[j] + cb);
            CP_COMMIT();
        }
        uint32_t s = sb0 + (ch % 3) * G2_STAGE;
#pragma unroll
        for (int k16 = 0; k16 < 2; k16++) {
            uint32_t kb = k16 * 32;
            uint32_t ah[2][4], bf[2][4];
#pragma unroll
            for (int mt = 0; mt < 2; mt++)
                LDSM4(ah[mt], s + aoff + mt * (16 * 80) + kb);
#pragma unroll
            for (int nt = 0; nt < 2; nt++) LDSM4(bf[nt], s + 10240 + boff + nt * (16 * 80) + kb);
#pragma unroll
            for (int mt = 0; mt < 2; mt++)
#pragma unroll
                for (int nt = 0; nt < 2; nt++)
#pragma unroll
                    for (int h = 0; h < 2; h++)
                        MMA16816(acc[mt][nt * 2 + h], ah[mt], bf[nt][2 * h], bf[nt][2 * h + 1]);
        }
    }

#pragma unroll
    for (int mt = 0; mt < 2; mt++)
#pragma unroll
        for (int rh = 0; rh < 2; rh++) {
            int lr = wy * 32 + mt * 16 + (lane >> 2) + rh * 8;
            if (r0 + lr < cnt) {
                int slot = off + r0 + lr;
                int tok = g_ptok[slot];
                float w = g_pw[slot];
                float* op = out + (size_t)tok * Dd + d0 + wx * 32 + (lane & 3) * 2;
#pragma unroll
                for (int nt8 = 0; nt8 < 4; nt8++) {
                    atomicAdd(op + nt8 * 8,     acc[mt][nt8][rh * 2 + 0] * w);
                    atomicAdd(op + nt8 * 8 + 1, acc[mt][nt8][rh * 2 + 1] * w);
                }
            }
        }
}

// ===================== launch =====================
extern "C" void kernel_launch(void* const* d_in, const int* in_sizes, int n_in,
                              void* d_out, int out_size) {
    (void)in_sizes; (void)n_in;
    const float* x       = (const float*)d_in[0];
    const float* hist    = (const float*)d_in[1];
    const float* persona = (const float*)d_in[2];
    const float* W1x     = (const float*)d_in[3];
    const float* W1h     = (const float*)d_in[4];
    const float* W1p     = (const float*)d_in[5];
    const float* b1      = (const float*)d_in[6];
    const float* W2      = (const float*)d_in[7];
    const float* b2      = (const float*)d_in[8];
    const float* ln_g    = (const float*)d_in[9];
    const float* ln_b    = (const float*)d_in[10];
    const float* Wg      = (const float*)d_in[11];
    const float* bg      = (const float*)d_in[12];
    const float* Wgate   = (const float*)d_in[13];
    const float* Wup     = (const float*)d_in[14];
    const float* Wdown   = (const float*)d_in[15];
    const float* Ag      = (const float*)d_in[16];
    const float* Bg      = (const float*)d_in[17];
    const float* Au      = (const float*)d_in[18];
    const float* Bu      = (const float*)d_in[19];
    const float* Ad      = (const float*)d_in[20];
    const float* Bd      = (const float*)d_in[21];
    float* out = (float*)d_out;

    cudaFuncSetAttribute(moe_gemm1, cudaFuncAttributeMaxDynamicSharedMemorySize, G1_SMEM);
    cudaFuncSetAttribute(moe_gemm2, cudaFuncAttributeMaxDynamicSharedMemorySize, G2_SMEM);
    cudaFuncSetAttribute(logits_kernel, cudaFuncAttributeMaxDynamicSharedMemorySize, LG_SMEM);
    cudaFuncSetAttribute(base_mma, cudaFuncAttributeMaxDynamicSharedMemorySize, BM_SMEM);

    void* cntp = nullptr;
    cudaGetSymbolAddress(&cntp, g_cnt);

    cudaMemsetAsync(out, 0, (size_t)out_size * sizeof(float));
    cudaMemsetAsync(cntp, 0, Ee * sizeof(int));

    prep_kernel<<<13, 128>>>(hist, W1h, b1, persona, W1p, ln_g, ln_b, Wg, bg);
    w2t_kernel<<<dim3(Dd / 32, HIDk / 32), 256>>>(W2);
    w1t_kernel<<<dim3(HIDk / 32, Dd / 32), 256>>>(W1x);
    xconv_kernel<<<(Nn * Dd) / 4 / 256, 256>>>(x);
    base_mma<<<Nn / 64, 256, BM_SMEM>>>();
    merge_kernel<<<dim3(1056, Ee), 256>>>(Wgate, Wup, Wdown, Ag, Bg, Au, Bu, Ad, Bd);
    logits_kernel<<<dim3(Nn / 64, Ee), 256, LG_SMEM>>>(b2);
    route_kernel<<<Nn / 256, 256>>>();
    scan_kernel<<<1, 1>>>();
    scatter_kernel<<<Nn / 256, 256>>>();
    moe_gemm1<<<dim3(Ff / 64, NP / 128, Ee), 256, G1_SMEM>>>();
    moe_gemm2<<<dim3(Dd / 64, NP / 128, Ee), 256, G2_SMEM>>>(out);
}

// round 9
// speedup vs baseline: 6.5841x; 1.0786x over previous
#include <cuda_runtime.h>
#include <cuda_fp16.h>
#include <math.h>
#include <stdint.h>

#define Bb 4
#define Ss 2048
#define Dd 1024
#define Hh 512
#define Ee 8
#define Ff 2816
#define Rr 16
#define HIDk 128
#define Nn 8192
#define NP 16384
#define LN_EPS 1e-5f

// ===================== baseline-PTX helpers =====================
__device__ __forceinline__ uint32_t smem_u32(const void* p) {
    uint32_t a;
    asm("{ .reg .u64 t; cvta.to.shared.u64 t, %1; cvt.u32.u64 %0, t; }" : "=r"(a) : "l"(p));
    return a;
}

#define CPASYNC16(dst, src) \
    asm volatile("cp.async.cg.shared.global [%0], [%1], 16;\n" :: "r"(dst), "l"(src))
#define CP_COMMIT() asm volatile("cp.async.commit_group;\n" ::: "memory")
#define CP_WAIT(N)  asm volatile("cp.async.wait_group %0;\n" :: "n"(N) : "memory")

#define LDSM4(R, addr) \
    asm volatile("ldmatrix.sync.aligned.m8n8.x4.shared.b16 {%0,%1,%2,%3}, [%4];" \
        : "=r"((R)[0]), "=r"((R)[1]), "=r"((R)[2]), "=r"((R)[3]) : "r"(addr))

#define MMA16816(C, A, B0, B1) \
    asm volatile("mma.sync.aligned.m16n8k16.row.col.f32.f16.f16.f32 " \
        "{%0,%1,%2,%3}, {%4,%5,%6,%7}, {%8,%9}, {%0,%1,%2,%3};" \
        : "+f"((C)[0]), "+f"((C)[1]), "+f"((C)[2]), "+f"((C)[3]) \
        : "r"((A)[0]), "r"((A)[1]), "r"((A)[2]), "r"((A)[3]), "r"(B0), "r"(B1))

__device__ __forceinline__ void f2h_split(float v, unsigned short& hi, unsigned short& lo) {
    __half h = __float2half_rn(v);
    hi = __half_as_ushort(h);
    lo = __half_as_ushort(__float2half_rn(v - __half2float(h)));
}

// ===================== static device scratch =====================
__device__ float g_base[Nn * HIDk];
__device__ float g_hb[Bb * HIDk];
__device__ float g_pk[Ee * HIDk];
__device__ float g_cgw[Dd];
__device__ float g_CgCb[2];
__device__ float g_logits[Nn * Ee];
__device__ int   g_cnt[Ee];
__device__ int   g_off[Ee];
__device__ int   g_te[Nn * 2];
__device__ int   g_tp[Nn * 2];
__device__ float g_tw[Nn * 2];
__device__ int   g_ptok[NP];
__device__ float g_pw[NP];
// fp16 split storage
__device__ unsigned short g_xh[(size_t)Nn * Dd];
__device__ unsigned short g_xl[(size_t)Nn * Dd];
__device__ unsigned short g_WgH[(size_t)Ee * Ff * Dd];   // [e][f][d]  K-major (hi)
__device__ unsigned short g_WuH[(size_t)Ee * Ff * Dd];
__device__ unsigned short g_WdH[(size_t)Ee * Dd * Ff];   // [e][d][f]  K-major (hi)
__device__ unsigned short g_Hh[(size_t)NP * Ff];
__device__ unsigned short g_W2TH[(size_t)Dd * HIDk];     // W2^T [d][k] hi
__device__ unsigned short g_W2TL[(size_t)Dd * HIDk];     // lo
__device__ unsigned short g_W1TH[(size_t)HIDk * Dd];     // W1x^T [k][d] hi
__device__ unsigned short g_W1TL[(size_t)HIDk * Dd];     // lo

// ===================== prep =====================
__global__ void prep_kernel(const float* __restrict__ hist, const float* __restrict__ W1h,
                            const float* __restrict__ b1,
                            const float* __restrict__ persona, const float* __restrict__ W1p,
                            const float* __restrict__ ln_g, const float* __restrict__ ln_b,
                            const float* __restrict__ Wg, const float* __restrict__ bg) {
    int bx = blockIdx.x, tid = threadIdx.x;
    if (bx < 4) {
        float acc = b1[tid];
        const float* hr = hist + bx * Hh;
        for (int k = 0; k < Hh; k++) acc += hr[k] * W1h[k * HIDk + tid];
        g_hb[bx * HIDk + tid] = acc;
    } else if (bx < 12) {
        int e = bx - 4;
        float acc = 0.f;
        const float* pr = persona + e * Dd;
        for (int k = 0; k < Dd; k++) acc += pr[k] * W1p[k * HIDk + tid];
        g_pk[e * HIDk + tid] = acc;
    } else {
        __shared__ float sg[128], sb[128];
        float a = 0.f, b = 0.f;
        for (int d = tid; d < Dd; d += 128) {
            float w = Wg[d];
            float c = ln_g[d] * w;
            g_cgw[d] = c;
            a += c;
            b += ln_b[d] * w;
        }
        sg[tid] = a; sb[tid] = b;
        __syncthreads();
        for (int s = 64; s > 0; s >>= 1) {
            if (tid < s) { sg[tid] += sg[tid + s]; sb[tid] += sb[tid + s]; }
            __syncthreads();
        }
        if (tid == 0) { g_CgCb[0] = sg[0]; g_CgCb[1] = sb[0] + bg[0]; }
    }
}

// ===================== W2 -> W2^T fp16 hi/lo =====================
__global__ void w2t_kernel(const float* __restrict__ W2) {
    __shared__ float T[32][33];
    int d0 = blockIdx.x * 32, k0 = blockIdx.y * 32;
    int tid = threadIdx.x;
#pragma unroll
    for (int i = 0; i < 4; i++) {
        int kk = (tid >> 5) + i * 8, dd = tid & 31;
        T[kk][dd] = W2[(size_t)(k0 + kk) * Dd + d0 + dd];
    }
    __syncthreads();
#pragma unroll
    for (int i = 0; i < 4; i++) {
        int dd = (tid >> 5) + i * 8, kk = tid & 31;
        unsigned short hi, lo;
        f2h_split(T[kk][dd], hi, lo);
        g_W2TH[(size_t)(d0 + dd) * HIDk + k0 + kk] = hi;
        g_W2TL[(size_t)(d0 + dd) * HIDk + k0 + kk] = lo;
    }
}

// ===================== W1x -> W1x^T fp16 hi/lo =====================
__global__ void w1t_kernel(const float* __restrict__ W1x) {
    __shared__ float T[32][33];
    int k0 = blockIdx.x * 32, d0 = blockIdx.y * 32;
    int tid = threadIdx.x;
#pragma unroll
    for (int i = 0; i < 4; i++) {
        int dd = (tid >> 5) + i * 8, kk = tid & 31;
        T[dd][kk] = W1x[(size_t)(d0 + dd) * HIDk + k0 + kk];
    }
    __syncthreads();
#pragma unroll
    for (int i = 0; i < 4; i++) {
        int kk = (tid >> 5) + i * 8, dd = tid & 31;
        unsigned short hi, lo;
        f2h_split(T[dd][kk], hi, lo);
        g_W1TH[(size_t)(k0 + kk) * Dd + d0 + dd] = hi;
        g_W1TL[(size_t)(k0 + kk) * Dd + d0 + dd] = lo;
    }
}

// ===================== x -> fp16 hi/lo =====================
__global__ void xconv_kernel(const float* __restrict__ x) {
    size_t i = (size_t)blockIdx.x * 256 + threadIdx.x;
    float4 v = ((const float4*)x)[i];
    unsigned short h0, l0, h1, l1, h2, l2, h3, l3;
    f2h_split(v.x, h0, l0); f2h_split(v.y, h1, l1);
    f2h_split(v.z, h2, l2); f2h_split(v.w, h3, l3);
    uint2 ph = make_uint2((uint32_t)h0 | ((uint32_t)h1 << 16), (uint32_t)h2 | ((uint32_t)h3 << 16));
    uint2 pl = make_uint2((uint32_t)l0 | ((uint32_t)l1 << 16), (uint32_t)l2 | ((uint32_t)l3 << 16));
    *(uint2*)(g_xh + i * 4) = ph;
    *(uint2*)(g_xl + i * 4) = pl;
}

// ===================== base = x @ W1x + hb (tensor-core, 3-term) =====================
#define BM_STAGE 30720
#define BM_SMEM (3 * BM_STAGE)

__global__ __launch_bounds__(256, 2) void base_mma() {
    extern __shared__ char sm[];
    int n0 = blockIdx.x * 64;
    int tid = threadIdx.x, lane = tid & 31, wid = tid >> 5;
    int wy = wid & 1, wx = wid >> 1;
    uint32_t sb0 = smem_u32(sm);

    uint32_t sdst[6];
    const char* gsrc[6];
#pragma unroll
    for (int j = 0; j < 6; j++) {
        int sid = tid + 256 * j;
        const unsigned short* g;
        uint32_t so;
        if (sid < 256) {
            int row = sid >> 2, seg = sid & 3;
            so = row * 80u + seg * 16u;
            g = g_xh + (size_t)(n0 + row) * Dd + seg * 8;
        } else if (sid < 512) {
            int rid = sid - 256;
            int row = rid >> 2, seg = rid & 3;
            so = 5120u + row * 80u + seg * 16u;
            g = g_xl + (size_t)(n0 + row) * Dd + seg * 8;
        } else if (sid < 1024) {
            int rid = sid - 512;
            int row = rid >> 2, seg = rid & 3;
            so = 10240u + row * 80u + seg * 16u;
            g = g_W1TH + (size_t)row * Dd + seg * 8;
        } else {
            int rid = sid - 1024;
            int row = rid >> 2, seg = rid & 3;
            so = 20480u + row * 80u + seg * 16u;
            g = g_W1TL + (size_t)row * Dd + seg * 8;
        }
        sdst[j] = so;
        gsrc[j] = (const char*)g;
    }

    float acc[2][4][4];
#pragma unroll
    for (int a = 0; a < 2; a++)
#pragma unroll
        for (int b = 0; b < 4; b++)
#pragma unroll
            for (int c = 0; c < 4; c++) acc[a][b][c] = 0.f;

    uint32_t aoff = (uint32_t)((wy * 32 + (lane & 15)) * 80 + (lane >> 4) * 16);
    uint32_t boff = (uint32_t)((wx * 32 + ((lane & 7) | ((lane >> 4) << 3))) * 80 + ((lane >> 3) & 1) * 16);

    const int NCH = 32;
#pragma unroll
    for (int j = 0; j < 6; j++) CPASYNC16(sb0 + sdst[j], gsrc[j]);
    CP_COMMIT();
#pragma unroll
    for (int j = 0; j < 6; j++) CPASYNC16(sb0 + BM_STAGE + sdst[j], gsrc[j] + 64);
    CP_COMMIT();

    for (int ch = 0; ch < NCH; ch++) {
        if (ch == NCH - 1) { CP_WAIT(0); } else { CP_WAIT(1); }
        __syncthreads();
        if (ch + 2 < NCH) {
            uint32_t stg = sb0 + ((ch + 2) % 3) * BM_STAGE;
            int cb = (ch + 2) * 64;
#pragma unroll
            for (int j = 0; j < 6; j++) CPASYNC16(stg + sdst[j], gsrc[j] + cb);
            CP_COMMIT();
        }
        uint32_t s = sb0 + (ch % 3) * BM_STAGE;
#pragma unroll
        for (int k16 = 0; k16 < 2; k16++) {
            uint32_t kb = k16 * 32;
            uint32_t ah[2][4], al[2][4], bh[2][4], bl[2][4];
#pragma unroll
            for (int mt = 0; mt < 2; mt++) {
                LDSM4(ah[mt], s + aoff + mt * (16 * 80) + kb);
                LDSM4(al[mt], s + 5120 + aoff + mt * (16 * 80) + kb);
            }
#pragma unroll
            for (int nt = 0; nt < 2; nt++) {
                LDSM4(bh[nt], s + 10240 + boff + nt * (16 * 80) + kb);
                LDSM4(bl[nt], s + 20480 + boff + nt * (16 * 80) + kb);
            }
#pragma unroll
            for (int mt = 0; mt < 2; mt++)
#pragma unroll
                for (int nt = 0; nt < 2; nt++)
#pragma unroll
                    for (int h = 0; h < 2; h++) {
                        MMA16816(acc[mt][nt * 2 + h], ah[mt], bh[nt][2 * h], bh[nt][2 * h + 1]);
                        MMA16816(acc[mt][nt * 2 + h], ah[mt], bl[nt][2 * h], bl[nt][2 * h + 1]);
                        MMA16816(acc[mt][nt * 2 + h], al[mt], bh[nt][2 * h], bh[nt][2 * h + 1]);
                    }
        }
    }

#pragma unroll
    for (int mt = 0; mt < 2; mt++)
#pragma unroll
        for (int rh = 0; rh < 2; rh++) {
            int row = n0 + wy * 32 + mt * 16 + (lane >> 2) + rh * 8;
            const float* hb = g_hb + (row >> 11) * HIDk;
#pragma unroll
            for (int nq = 0; nq < 4; nq++) {
                int col = wx * 32 + nq * 8 + (lane & 3) * 2;
                g_base[(size_t)row * HIDk + col]     = acc[mt][nq][rh * 2]     + hb[col];
                g_base[(size_t)row * HIDk + col + 1] = acc[mt][nq][rh * 2 + 1] + hb[col + 1];
            }
        }
}

// ===================== merge: W' = W + A@B -> transposed fp16 hi =====================
__global__ __launch_bounds__(256) void merge_kernel(
    const float* __restrict__ Wgate, const float* __restrict__ Wup, const float* __restrict__ Wdown,
    const float* __restrict__ Ag, const float* __restrict__ Bg,
    const float* __restrict__ Au, const float* __restrict__ Bu,
    const float* __restrict__ Ad, const float* __restrict__ Bd) {
    __shared__ float As[128][17];
    __shared__ float Bs[16][65];
    __shared__ unsigned short Thi[64][136];
    int e = blockIdx.y, t = blockIdx.x, tid = threadIdx.x;
    const float *src, *Ap, *Bp;
    unsigned short *dhi;
    int r0, c0, rowStride, outStride;
    if (t < 352) {
        int kt = t / 44, ft = t % 44;
        r0 = kt * 128; c0 = ft * 64; rowStride = Ff; outStride = Dd;
        src = Wgate + (size_t)e * Dd * Ff; Ap = Ag + (size_t)e * Dd * Rr; Bp = Bg + (size_t)e * Rr * Ff;
        dhi = g_WgH + (size_t)e * Ff * Dd;
    } else if (t < 704) {
        t -= 352;
        int kt = t / 44, ft = t % 44;
        r0 = kt * 128; c0 = ft * 64; rowStride = Ff; outStride = Dd;
        src = Wup + (size_t)e * Dd * Ff; Ap = Au + (size_t)e * Dd * Rr; Bp = Bu + (size_t)e * Rr * Ff;
        dhi = g_WuH + (size_t)e * Ff * Dd;
    } else {
        t -= 704;
        int kt = t / 16, ft = t % 16;
        r0 = kt * 128; c0 = ft * 64; rowStride = Dd; outStride = Ff;
        src = Wdown + (size_t)e * Ff * Dd; Ap = Ad + (size_t)e * Ff * Rr; Bp = Bd + (size_t)e * Rr * Dd;
        dhi = g_WdH + (size_t)e * Dd * Ff;
    }
    {
        int r = tid >> 1, k0 = (tid & 1) * 8;
#pragma unroll
        for (int kk = 0; kk < 8; kk++)
            As[r][k0 + kk] = Ap[(size_t)(r0 + r) * Rr + k0 + kk];
    }
    for (int i = tid; i < 1024; i += 256) {
        int k = i >> 6, c = i & 63;
        Bs[k][c] = Bp[(size_t)k * rowStride + c0 + c];
    }
    __syncthreads();
    {
        int c = tid & 63, rb = tid >> 6;
        float vbuf[32];
        for (int rr = 0; rr < 32; rr++) {
            int r = rb * 32 + rr;
            float v = src[(size_t)(r0 + r) * rowStride + c0 + c];
#pragma unroll
            for (int k = 0; k < 16; k++) v += As[r][k] * Bs[k][c];
            vbuf[rr] = v;
        }
        for (int w = 0; w < 32; w++) {
            int rr = (w + c) & 31;
            Thi[c][rb * 32 + rr] = __half_as_ushort(__float2half_rn(vbuf[rr]));
        }
    }
    __syncthreads();
    {
        int c = tid >> 2, qq = tid & 3;
        const uint4* sh = (const uint4*)&Thi[c][qq * 32];
        uint4* dH = (uint4*)(dhi + (size_t)(c0 + c) * outStride + r0 + qq * 32);
#pragma unroll
        for (int m = 0; m < 4; m++) dH[m] = sh[m];
    }
}

// ===================== fused gate logits via mma.sync =====================
#define LG_AHI 0
#define LG_ALO 17408
#define LG_B0  34816
#define LG_BSTG 34816
#define LG_RED (LG_B0 + 2 * LG_BSTG)
#define LG_B2  (LG_RED + 768)
#define LG_CG  (LG_B2 + 4096)
#define LG_SMEM (LG_CG + 4096)

__global__ __launch_bounds__(256) void logits_kernel(const float* __restrict__ b2) {
    extern __shared__ char sm[];
    uint32_t sb = smem_u32(sm);
    int e = blockIdx.y, n0 = blockIdx.x * 64;
    int tid = threadIdx.x, lane = tid & 31, wid = tid >> 5;
    int wy = wid & 3, wx = wid >> 2;

    if (tid < 192) ((float*)(sm + LG_RED))[tid] = 0.f;
#pragma unroll
    for (int i = 0; i < 4; i++) {
        ((float*)(sm + LG_B2))[tid + 256 * i] = b2[tid + 256 * i];
        ((float*)(sm + LG_CG))[tid + 256 * i] = g_cgw[tid + 256 * i];
    }
    {
        int t = tid >> 2, kq = (tid & 3) * 32;
        const float4* bp = (const float4*)(g_base + (size_t)(n0 + t) * HIDk + kq);
        const float4* pp = (const float4*)(g_pk + e * HIDk + kq);
        unsigned short* ah = (unsigned short*)(sm + LG_AHI) + t * 136 + kq;
        unsigned short* al = (unsigned short*)(sm + LG_ALO) + t * 136 + kq;
#pragma unroll
        for (int q = 0; q < 8; q++) {
            float4 a = bp[q], p = pp[q];
            float v[4] = {fmaxf(a.x + p.x, 0.f), fmaxf(a.y + p.y, 0.f),
                          fmaxf(a.z + p.z, 0.f), fmaxf(a.w + p.w, 0.f)};
#pragma unroll
            for (int c = 0; c < 4; c++) {
                unsigned short hi, lo;
                f2h_split(v[c], hi, lo);
                ah[q * 4 + c] = hi;
                al[q * 4 + c] = lo;
            }
        }
    }
    uint32_t sdst[8];
    uint32_t gofs[8];
    int ghl[8];
#pragma unroll
    for (int j = 0; j < 8; j++) {
        int sid = tid + 256 * j;
        int hl = sid >> 10;
        int rid = sid & 1023;
        int row = rid >> 4, seg = rid & 15;
        sdst[j] = (uint32_t)(hl * 17408 + row * 272 + seg * 16);
        gofs[j] = (uint32_t)(row * HIDk + seg * 8);
        ghl[j] = hl;
    }
#pragma unroll
    for (int j = 0; j < 8; j++) {
        const unsigned short* g = (ghl[j] ? g_W2TL : g_W2TH) + gofs[j];
        CPASYNC16(sb + LG_B0 + sdst[j], (const char*)g);
    }
    CP_COMMIT();
    __syncthreads();

    float s1[2] = {0.f, 0.f}, s2[2] = {0.f, 0.f}, s3[2] = {0.f, 0.f};
    uint32_t aoff = (uint32_t)((wy * 16 + (lane & 15)) * 272 + (lane >> 4) * 16);
    uint32_t boff = (uint32_t)(((wx * 32 + ((lane & 7) | ((lane >> 4) << 3))) * 272) + ((lane >> 3) & 1) * 16);

    for (int ch = 0; ch < 16; ch++) {
        if (ch + 1 < 16) {
            uint32_t stg = sb + LG_B0 + ((ch + 1) & 1) * LG_BSTG;
            uint32_t dadd = (uint32_t)((ch + 1) * 64 * HIDk);
#pragma unroll
            for (int j = 0; j < 8; j++) {
                const unsigned short* g = (ghl[j] ? g_W2TL : g_W2TH) + gofs[j] + dadd;
                CPASYNC16(stg + sdst[j], (const char*)g);
            }
            CP_COMMIT();
            CP_WAIT(1);
        } else {
            CP_WAIT(0);
        }
        __syncthreads();
        uint32_t sB = sb + LG_B0 + (ch & 1) * LG_BSTG;
        float acc[4][4];
#pragma unroll
        for (int a = 0; a < 4; a++)
#pragma unroll
            for (int c = 0; c < 4; c++) acc[a][c] = 0.f;
#pragma unroll
        for (int k16 = 0; k16 < 8; k16++) {
            uint32_t kb = (uint32_t)(k16 * 32);
            uint32_t ahr[4], alr[4], bh[2][4], bl[2][4];
            LDSM4(ahr, sb + LG_AHI + aoff + kb);
            LDSM4(alr, sb + LG_ALO + aoff + kb);
            LDSM4(bh[0], sB + boff + kb);
            LDSM4(bh[1], sB + boff + 16 * 272 + kb);
            LDSM4(bl[0], sB + 17408 + boff + kb);
            LDSM4(bl[1], sB + 17408 + boff + 16 * 272 + kb);
#pragma unroll
            for (int nt = 0; nt < 2; nt++)
#pragma unroll
                for (int h = 0; h < 2; h++) {
                    MMA16816(acc[nt * 2 + h], ahr, bh[nt][2 * h], bh[nt][2 * h + 1]);
                    MMA16816(acc[nt * 2 + h], alr, bh[nt][2 * h], bh[nt][2 * h + 1]);
                    MMA16816(acc[nt * 2 + h], ahr, bl[nt][2 * h], bl[nt][2 * h + 1]);
                }
        }
#pragma unroll
        for (int nt4 = 0; nt4 < 4; nt4++) {
            int col = ch * 64 + wx * 32 + nt4 * 8 + (lane & 3) * 2;
            float b0 = ((float*)(sm + LG_B2))[col], b1v = ((float*)(sm + LG_B2))[col + 1];
            float c0 = ((float*)(sm + LG_CG))[col], c1v = ((float*)(sm + LG_CG))[col + 1];
            float f;
            f = fmaxf(acc[nt4][0] + b0, 0.f);  s1[0] += f * c0;  s2[0] += f; s3[0] += f * f;
            f = fmaxf(acc[nt4][1] + b1v, 0.f); s1[0] += f * c1v; s2[0] += f; s3[0] += f * f;
            f = fmaxf(acc[nt4][2] + b0, 0.f);  s1[1] += f * c0;  s2[1] += f; s3[1] += f * f;
            f = fmaxf(acc[nt4][3] + b1v, 0.f); s1[1] += f * c1v; s2[1] += f; s3[1] += f * f;
        }
        __syncthreads();
    }
#pragma unroll
    for (int off = 1; off <= 2; off <<= 1) {
#pragma unroll
        for (int i = 0; i < 2; i++) {
            s1[i] += __shfl_xor_sync(0xffffffffu, s1[i], off);
            s2[i] += __shfl_xor_sync(0xffffffffu, s2[i], off);
            s3[i] += __shfl_xor_sync(0xffffffffu, s3[i], off);
        }
    }
    if ((lane & 3) == 0) {
        int row = wy * 16 + (lane >> 2);
        float* red = (float*)(sm + LG_RED);
        atomicAdd(&red[row],           s1[0]);
        atomicAdd(&red[row + 8],       s1[1]);
        atomicAdd(&red[64 + row],      s2[0]);
        atomicAdd(&red[64 + row + 8],  s2[1]);
        atomicAdd(&red[128 + row],     s3[0]);
        atomicAdd(&red[128 + row + 8], s3[1]);
    }
    __syncthreads();
    if (tid < 64) {
        float* red = (float*)(sm + LG_RED);
        float S1 = red[tid], S2 = red[64 + tid], S3 = red[128 + tid];
        float Cg = g_CgCb[0], Cb = g_CgCb[1];
        float mu = S2 * (1.f / (float)Dd);
        float var = S3 * (1.f / (float)Dd) - mu * mu;
        float rstd = rsqrtf(var + LN_EPS);
        g_logits[(size_t)(n0 + tid) * Ee + e] = rstd * (S1 - mu * Cg) + Cb;
    }
}

// ===================== routing =====================
__global__ void route_kernel() {
    int n = blockIdx.x * 256 + threadIdx.x;
    float l[Ee];
    float m = -1e30f;
#pragma unroll
    for (int e = 0; e < Ee; e++) { l[e] = g_logits[(size_t)n * Ee + e]; m = fmaxf(m, l[e]); }
    float s = 0.f;
#pragma unroll
    for (int e = 0; e < Ee; e++) { l[e] = expf(l[e] - m); s += l[e]; }
    float inv = 1.f / s;
#pragma unroll
    for (int e = 0; e < Ee; e++) l[e] *= inv;
    int i0 = 0; float b0 = l[0];
#pragma unroll
    for (int e = 1; e < Ee; e++) if (l[e] > b0) { b0 = l[e]; i0 = e; }
    int i1 = -1; float b1 = -1.f;
#pragma unroll
    for (int e = 0; e < Ee; e++) if (e != i0 && l[e] > b1) { b1 = l[e]; i1 = e; }
    int p0 = atomicAdd(&g_cnt[i0], 1);
    int p1 = atomicAdd(&g_cnt[i1], 1);
    g_te[2 * n] = i0; g_tp[2 * n] = p0; g_tw[2 * n] = b0;
    g_te[2 * n + 1] = i1; g_tp[2 * n + 1] = p1; g_tw[2 * n + 1] = b1;
}

__global__ void scan_kernel() {
    int a = 0;
    for (int e = 0; e < Ee; e++) { g_off[e] = a; a += g_cnt[e]; }
}

__global__ void scatter_kernel() {
    int n = blockIdx.x * 256 + threadIdx.x;
#pragma unroll
    for (int i = 0; i < 2; i++) {
        int slot = g_off[g_te[2 * n + i]] + g_tp[2 * n + i];
        g_ptok[slot] = n;
        g_pw[slot] = g_tw[2 * n + i];
    }
}

// ===================== expert GEMM1 (1-term; gate+up; 3-stage; ftile-fastest grid) =====================
#define G1_STAGE 20480
#define G1_SMEM (1024 + 3 * G1_STAGE)

__global__ __launch_bounds__(256, 2) void moe_gemm1() {
    extern __shared__ char sm[];
    int e = blockIdx.z;
    int cnt = g_cnt[e];
    int r0 = blockIdx.y * 128;
    if (r0 >= cnt) return;
    int off = g_off[e];
    int f0 = blockIdx.x * 64;
    int tid = threadIdx.x, lane = tid & 31, wid = tid >> 5;
    int wy = wid & 3, wx = wid >> 2;

    int* stok = (int*)sm;
    if (tid < 128) {
        int lr = r0 + tid; if (lr >= cnt) lr = cnt - 1;
        stok[tid] = g_ptok[off + lr];
    }
    __syncthreads();

    uint32_t sb0 = smem_u32(sm) + 1024;

    uint32_t sdst[4];
    const char* gsrc[4];
#pragma unroll
    for (int j = 0; j < 4; j++) {
        int sid = tid + 256 * j;
        int region = sid >> 9;
        int rid = sid & 511;
        int row = rid >> 2, seg = rid & 3;
        sdst[j] = (uint32_t)(region * 10240 + row * 80 + seg * 16);
        const unsigned short* g;
        if (region == 0) g = g_xh + (size_t)stok[row] * Dd;
        else             g = (row < 64) ? g_WgH + ((size_t)e * Ff + f0 + row) * Dd
                                        : g_WuH + ((size_t)e * Ff + f0 + row - 64) * Dd;
        gsrc[j] = (const char*)(g + seg * 8);
    }

    float accG[2][4][4], accU[2][4][4];
#pragma unroll
    for (int a = 0; a < 2; a++)
#pragma unroll
        for (int b = 0; b < 4; b++)
#pragma unroll
            for (int c = 0; c < 4; c++) { accG[a][b][c] = 0.f; accU[a][b][c] = 0.f; }

    uint32_t aoff = (uint32_t)((wy * 32 + (lane & 15)) * 80 + (lane >> 4) * 16);
    uint32_t boff = (uint32_t)((wx * 32 + ((lane & 7) | ((lane >> 4) << 3))) * 80 + ((lane >> 3) & 1) * 16);

    const int NCH = 32;
#pragma unroll
    for (int j = 0; j < 4; j++) CPASYNC16(sb0 + sdst[j], gsrc[j]);
    CP_COMMIT();
#pragma unroll
    for (int j = 0; j < 4; j++) CPASYNC16(sb0 + G1_STAGE + sdst[j], gsrc[j] + 64);
    CP_COMMIT();

    for (int ch = 0; ch < NCH; ch++) {
        if (ch == NCH - 1) { CP_WAIT(0); } else { CP_WAIT(1); }
        __syncthreads();
        if (ch + 2 < NCH) {
            uint32_t stg = sb0 + ((ch + 2) % 3) * G1_STAGE;
            int cb = (ch + 2) * 64;
#pragma unroll
            for (int j = 0; j < 4; j++) CPASYNC16(stg + sdst[j], gsrc[j] + cb);
            CP_COMMIT();
        }
        uint32_t s = sb0 + (ch % 3) * G1_STAGE;
#pragma unroll
        for (int k16 = 0; k16 < 2; k16++) {
            uint32_t kb = k16 * 32;
            uint32_t ah[2][4], bg[2][4], bu[2][4];
#pragma unroll
            for (int mt = 0; mt < 2; mt++)
                LDSM4(ah[mt], s + aoff + mt * (16 * 80) + kb);
#pragma unroll
            for (int nt = 0; nt < 2; nt++) {
                LDSM4(bg[nt], s + 10240 + boff + nt * (16 * 80) + kb);
                LDSM4(bu[nt], s + 10240 + 5120 + boff + nt * (16 * 80) + kb);
            }
#pragma unroll
            for (int mt = 0; mt < 2; mt++)
#pragma unroll
                for (int nt = 0; nt < 2; nt++)
#pragma unroll
                    for (int h = 0; h < 2; h++) {
                        MMA16816(accG[mt][nt * 2 + h], ah[mt], bg[nt][2 * h], bg[nt][2 * h + 1]);
                        MMA16816(accU[mt][nt * 2 + h], ah[mt], bu[nt][2 * h], bu[nt][2 * h + 1]);
                    }
        }
    }

#pragma unroll
    for (int mt = 0; mt < 2; mt++)
#pragma unroll
        for (int rh = 0; rh < 2; rh++) {
            int lr = wy * 32 + mt * 16 + (lane >> 2) + rh * 8;
            if (r0 + lr < cnt) {
                int slot = off + r0 + lr;
#pragma unroll
                for (int nt8 = 0; nt8 < 4; nt8++) {
                    int col = f0 + wx * 32 + nt8 * 8 + (lane & 3) * 2;
                    float g0 = accG[mt][nt8][rh * 2 + 0], g1 = accG[mt][nt8][rh * 2 + 1];
                    float u0 = accU[mt][nt8][rh * 2 + 0], u1 = accU[mt][nt8][rh * 2 + 1];
                    float h0 = g0 / (1.f + __expf(-g0)) * u0;
                    float h1 = g1 / (1.f + __expf(-g1)) * u1;
                    unsigned short a0 = __half_as_ushort(__float2half_rn(h0));
                    unsigned short a1 = __half_as_ushort(__float2half_rn(h1));
                    size_t idx = ((size_t)slot * Ff + col) >> 1;
                    ((uint32_t*)g_Hh)[idx] = (uint32_t)a0 | ((uint32_t)a1 << 16);
                }
            }
        }
}

// ===================== expert GEMM2 (1-term; 128x128 tile; 3-stage; dtile-fastest) =====================
// stage: A_hi 128x(32) @0 (10240), B_hi 128x(32) @10240 (10240) = 20480
#define G2_STAGE 20480
#define G2_SMEM (3 * G2_STAGE)

__global__ __launch_bounds__(256, 2) void moe_gemm2(float* __restrict__ out) {
    extern __shared__ char sm[];
    int e = blockIdx.z;
    int cnt = g_cnt[e];
    int r0 = blockIdx.y * 128;
    if (r0 >= cnt) return;
    int off = g_off[e];
    int d0 = blockIdx.x * 128;
    int tid = threadIdx.x, lane = tid & 31, wid = tid >> 5;
    int wy = wid & 3, wx = wid >> 2;   // wy: 4 x 32-row groups, wx: 2 x 64-col groups

    uint32_t sb0 = smem_u32(sm);

    uint32_t sdst[4];
    const char* gsrc[4];
#pragma unroll
    for (int j = 0; j < 4; j++) {
        int sid = tid + 256 * j;   // 0..1023
        const unsigned short* g;
        uint32_t so;
        if (sid < 512) {
            int row = sid >> 2, seg = sid & 3;
            so = row * 80u + seg * 16u;
            int lr = r0 + row; if (lr >= cnt) lr = cnt - 1;
            g = g_Hh + (size_t)(off + lr) * Ff + seg * 8;
        } else {
            int rid = sid - 512;
            int row = rid >> 2, seg = rid & 3;
            so = 10240u + row * 80u + seg * 16u;
            g = g_WdH + ((size_t)e * Dd + d0 + row) * Ff + seg * 8;
        }
        sdst[j] = so;
        gsrc[j] = (const char*)g;
    }

    float acc[2][8][4];
#pragma unroll
    for (int a = 0; a < 2; a++)
#pragma unroll
        for (int b = 0; b < 8; b++)
#pragma unroll
            for (int c = 0; c < 4; c++) acc[a][b][c] = 0.f;

    uint32_t aoff = (uint32_t)((wy * 32 + (lane & 15)) * 80 + (lane >> 4) * 16);
    uint32_t boff = (uint32_t)((wx * 64 + ((lane & 7) | ((lane >> 4) << 3))) * 80 + ((lane >> 3) & 1) * 16);

    const int NCH = 88;
#pragma unroll
    for (int j = 0; j < 4; j++) CPASYNC16(sb0 + sdst[j], gsrc[j]);
    CP_COMMIT();
#pragma unroll
    for (int j = 0; j < 4; j++) CPASYNC16(sb0 + G2_STAGE + sdst[j], gsrc[j] + 64);
    CP_COMMIT();

    for (int ch = 0; ch < NCH; ch++) {
        if (ch == NCH - 1) { CP_WAIT(0); } else { CP_WAIT(1); }
        __syncthreads();
        if (ch + 2 < NCH) {
            uint32_t stg = sb0 + ((ch + 2) % 3) * G2_STAGE;
            int cb = (ch + 2) * 64;
#pragma unroll
            for (int j = 0; j < 4; j++) CPASYNC16(stg + sdst[j], gsrc[j] + cb);
            CP_COMMIT();
        }
        uint32_t s = sb0 + (ch % 3) * G2_STAGE;
#pragma unroll
        for (int k16 = 0; k16 < 2; k16++) {
            uint32_t kb = k16 * 32;
            uint32_t ah[2][4], bf[4][4];
#pragma unroll
            for (int mt = 0; mt < 2; mt++)
                LDSM4(ah[mt], s + aoff + mt * (16 * 80) + kb);
#pragma unroll
            for (int nt = 0; nt < 4; nt++) LDSM4(bf[nt], s + 10240 + boff + nt * (16 * 80) + kb);
#pragma unroll
            for (int mt = 0; mt < 2; mt++)
#pragma unroll
                for (int nt = 0; nt < 4; nt++)
#pragma unroll
                    for (int h = 0; h < 2; h++)
                        MMA16816(acc[mt][nt * 2 + h], ah[mt], bf[nt][2 * h], bf[nt][2 * h + 1]);
        }
    }

#pragma unroll
    for (int mt = 0; mt < 2; mt++)
#pragma unroll
        for (int rh = 0; rh < 2; rh++) {
            int lr = wy * 32 + mt * 16 + (lane >> 2) + rh * 8;
            if (r0 + lr < cnt) {
                int slot = off + r0 + lr;
                int tok = g_ptok[slot];
                float w = g_pw[slot];
                float* op = out + (size_t)tok * Dd + d0 + wx * 64 + (lane & 3) * 2;
#pragma unroll
                for (int nt8 = 0; nt8 < 8; nt8++) {
                    atomicAdd(op + nt8 * 8,     acc[mt][nt8][rh * 2 + 0] * w);
                    atomicAdd(op + nt8 * 8 + 1, acc[mt][nt8][rh * 2 + 1] * w);
                }
            }
        }
}

// ===================== launch =====================
extern "C" void kernel_launch(void* const* d_in, const int* in_sizes, int n_in,
                              void* d_out, int out_size) {
    (void)in_sizes; (void)n_in;
    const float* x       = (const float*)d_in[0];
    const float* hist    = (const float*)d_in[1];
    const float* persona = (const float*)d_in[2];
    const float* W1x     = (const float*)d_in[3];
    const float* W1h     = (const float*)d_in[4];
    const float* W1p     = (const float*)d_in[5];
    const float* b1      = (const float*)d_in[6];
    const float* W2      = (const float*)d_in[7];
    const float* b2      = (const float*)d_in[8];
    const float* ln_g    = (const float*)d_in[9];
    const float* ln_b    = (const float*)d_in[10];
    const float* Wg      = (const float*)d_in[11];
    const float* bg      = (const float*)d_in[12];
    const float* Wgate   = (const float*)d_in[13];
    const float* Wup     = (const float*)d_in[14];
    const float* Wdown   = (const float*)d_in[15];
    const float* Ag      = (const float*)d_in[16];
    const float* Bg      = (const float*)d_in[17];
    const float* Au      = (const float*)d_in[18];
    const float* Bu      = (const float*)d_in[19];
    const float* Ad      = (const float*)d_in[20];
    const float* Bd      = (const float*)d_in[21];
    float* out = (float*)d_out;

    cudaFuncSetAttribute(moe_gemm1, cudaFuncAttributeMaxDynamicSharedMemorySize, G1_SMEM);
    cudaFuncSetAttribute(moe_gemm2, cudaFuncAttributeMaxDynamicSharedMemorySize, G2_SMEM);
    cudaFuncSetAttribute(logits_kernel, cudaFuncAttributeMaxDynamicSharedMemorySize, LG_SMEM);
    cudaFuncSetAttribute(base_mma, cudaFuncAttributeMaxDynamicSharedMemorySize, BM_SMEM);

    void* cntp = nullptr;
    cudaGetSymbolAddress(&cntp, g_cnt);

    cudaMemsetAsync(out, 0, (size_t)out_size * sizeof(float));
    cudaMemsetAsync(cntp, 0, Ee * sizeof(int));

    prep_kernel<<<13, 128>>>(hist, W1h, b1, persona, W1p, ln_g, ln_b, Wg, bg);
    w2t_kernel<<<dim3(Dd / 32, HIDk / 32), 256>>>(W2);
    w1t_kernel<<<dim3(HIDk / 32, Dd / 32), 256>>>(W1x);
    xconv_kernel<<<(Nn * Dd) / 4 / 256, 256>>>(x);
    base_mma<<<Nn / 64, 256, BM_SMEM>>>();
    merge_kernel<<<dim3(1056, Ee), 256>>>(Wgate, Wup, Wdown, Ag, Bg, Au, Bu, Ad, Bd);
    logits_kernel<<<dim3(Nn / 64, Ee), 256, LG_SMEM>>>(b2);
    route_kernel<<<Nn / 256, 256>>>();
    scan_kernel<<<1, 1>>>();
    scatter_kernel<<<Nn / 256, 256>>>();
    moe_gemm1<<<dim3(Ff / 64, NP / 128, Ee), 256, G1_SMEM>>>();
    moe_gemm2<<<dim3(Dd / 128, NP / 128, Ee), 256, G2_SMEM>>>(out);
}

// round 10
// speedup vs baseline: 6.7220x; 1.0209x over previous
#include <cuda_runtime.h>
#include <cuda_fp16.h>
#include <math.h>
#include <stdint.h>

#define Bb 4
#define Ss 2048
#define Dd 1024
#define Hh 512
#define Ee 8
#define Ff 2816
#define Rr 16
#define HIDk 128
#define Nn 8192
#define NP 16384
#define LN_EPS 1e-5f

// ===================== baseline-PTX helpers =====================
__device__ __forceinline__ uint32_t smem_u32(const void* p) {
    uint32_t a;
    asm("{ .reg .u64 t; cvta.to.shared.u64 t, %1; cvt.u32.u64 %0, t; }" : "=r"(a) : "l"(p));
    return a;
}

#define CPASYNC16(dst, src) \
    asm volatile("cp.async.cg.shared.global [%0], [%1], 16;\n" :: "r"(dst), "l"(src))
#define CP_COMMIT() asm volatile("cp.async.commit_group;\n" ::: "memory")
#define CP_WAIT(N)  asm volatile("cp.async.wait_group %0;\n" :: "n"(N) : "memory")

#define LDSM4(R, addr) \
    asm volatile("ldmatrix.sync.aligned.m8n8.x4.shared.b16 {%0,%1,%2,%3}, [%4];" \
        : "=r"((R)[0]), "=r"((R)[1]), "=r"((R)[2]), "=r"((R)[3]) : "r"(addr))

#define MMA16816(C, A, B0, B1) \
    asm volatile("mma.sync.aligned.m16n8k16.row.col.f32.f16.f16.f32 " \
        "{%0,%1,%2,%3}, {%4,%5,%6,%7}, {%8,%9}, {%0,%1,%2,%3};" \
        : "+f"((C)[0]), "+f"((C)[1]), "+f"((C)[2]), "+f"((C)[3]) \
        : "r"((A)[0]), "r"((A)[1]), "r"((A)[2]), "r"((A)[3]), "r"(B0), "r"(B1))

__device__ __forceinline__ void f2h_split(float v, unsigned short& hi, unsigned short& lo) {
    __half h = __float2half_rn(v);
    hi = __half_as_ushort(h);
    lo = __half_as_ushort(__float2half_rn(v - __half2float(h)));
}

// ===================== static device scratch =====================
__device__ float g_base[Nn * HIDk];
__device__ float g_hb[Bb * HIDk];
__device__ float g_pk[Ee * HIDk];
__device__ float g_cgw[Dd];
__device__ float g_CgCb[2];
__device__ float g_logits[Nn * Ee];
__device__ int   g_cnt[Ee];
__device__ int   g_off[Ee];
__device__ int   g_te[Nn * 2];
__device__ int   g_tp[Nn * 2];
__device__ float g_tw[Nn * 2];
__device__ int   g_ptok[NP];
__device__ float g_pw[NP];
// fp16 split storage
__device__ unsigned short g_xh[(size_t)Nn * Dd];
__device__ unsigned short g_xl[(size_t)Nn * Dd];
__device__ unsigned short g_WgH[(size_t)Ee * Ff * Dd];   // [e][f][d]  K-major (hi)
__device__ unsigned short g_WuH[(size_t)Ee * Ff * Dd];
__device__ unsigned short g_WdH[(size_t)Ee * Dd * Ff];   // [e][d][f]  K-major (hi)
__device__ unsigned short g_Hh[(size_t)NP * Ff];
__device__ unsigned short g_W2TH[(size_t)Dd * HIDk];     // W2^T [d][k] hi
__device__ unsigned short g_W2TL[(size_t)Dd * HIDk];     // lo
__device__ unsigned short g_W1TH[(size_t)HIDk * Dd];     // W1x^T [k][d] hi
__device__ unsigned short g_W1TL[(size_t)HIDk * Dd];     // lo

// ===================== prep =====================
__global__ void prep_kernel(const float* __restrict__ hist, const float* __restrict__ W1h,
                            const float* __restrict__ b1,
                            const float* __restrict__ persona, const float* __restrict__ W1p,
                            const float* __restrict__ ln_g, const float* __restrict__ ln_b,
                            const float* __restrict__ Wg, const float* __restrict__ bg) {
    int bx = blockIdx.x, tid = threadIdx.x;
    if (bx < 4) {
        float acc = b1[tid];
        const float* hr = hist + bx * Hh;
        for (int k = 0; k < Hh; k++) acc += hr[k] * W1h[k * HIDk + tid];
        g_hb[bx * HIDk + tid] = acc;
    } else if (bx < 12) {
        int e = bx - 4;
        float acc = 0.f;
        const float* pr = persona + e * Dd;
        for (int k = 0; k < Dd; k++) acc += pr[k] * W1p[k * HIDk + tid];
        g_pk[e * HIDk + tid] = acc;
    } else {
        __shared__ float sg[128], sb[128];
        float a = 0.f, b = 0.f;
        for (int d = tid; d < Dd; d += 128) {
            float w = Wg[d];
            float c = ln_g[d] * w;
            g_cgw[d] = c;
            a += c;
            b += ln_b[d] * w;
        }
        sg[tid] = a; sb[tid] = b;
        __syncthreads();
        for (int s = 64; s > 0; s >>= 1) {
            if (tid < s) { sg[tid] += sg[tid + s]; sb[tid] += sb[tid + s]; }
            __syncthreads();
        }
        if (tid == 0) { g_CgCb[0] = sg[0]; g_CgCb[1] = sb[0] + bg[0]; }
    }
}

// ===================== W2 -> W2^T fp16 hi/lo =====================
__global__ void w2t_kernel(const float* __restrict__ W2) {
    __shared__ float T[32][33];
    int d0 = blockIdx.x * 32, k0 = blockIdx.y * 32;
    int tid = threadIdx.x;
#pragma unroll
    for (int i = 0; i < 4; i++) {
        int kk = (tid >> 5) + i * 8, dd = tid & 31;
        T[kk][dd] = W2[(size_t)(k0 + kk) * Dd + d0 + dd];
    }
    __syncthreads();
#pragma unroll
    for (int i = 0; i < 4; i++) {
        int dd = (tid >> 5) + i * 8, kk = tid & 31;
        unsigned short hi, lo;
        f2h_split(T[kk][dd], hi, lo);
        g_W2TH[(size_t)(d0 + dd) * HIDk + k0 + kk] = hi;
        g_W2TL[(size_t)(d0 + dd) * HIDk + k0 + kk] = lo;
    }
}

// ===================== W1x -> W1x^T fp16 hi/lo =====================
__global__ void w1t_kernel(const float* __restrict__ W1x) {
    __shared__ float T[32][33];
    int k0 = blockIdx.x * 32, d0 = blockIdx.y * 32;
    int tid = threadIdx.x;
#pragma unroll
    for (int i = 0; i < 4; i++) {
        int dd = (tid >> 5) + i * 8, kk = tid & 31;
        T[dd][kk] = W1x[(size_t)(d0 + dd) * HIDk + k0 + kk];
    }
    __syncthreads();
#pragma unroll
    for (int i = 0; i < 4; i++) {
        int kk = (tid >> 5) + i * 8, dd = tid & 31;
        unsigned short hi, lo;
        f2h_split(T[dd][kk], hi, lo);
        g_W1TH[(size_t)(k0 + kk) * Dd + d0 + dd] = hi;
        g_W1TL[(size_t)(k0 + kk) * Dd + d0 + dd] = lo;
    }
}

// ===================== x -> fp16 hi/lo =====================
__global__ void xconv_kernel(const float* __restrict__ x) {
    size_t i = (size_t)blockIdx.x * 256 + threadIdx.x;
    float4 v = ((const float4*)x)[i];
    unsigned short h0, l0, h1, l1, h2, l2, h3, l3;
    f2h_split(v.x, h0, l0); f2h_split(v.y, h1, l1);
    f2h_split(v.z, h2, l2); f2h_split(v.w, h3, l3);
    uint2 ph = make_uint2((uint32_t)h0 | ((uint32_t)h1 << 16), (uint32_t)h2 | ((uint32_t)h3 << 16));
    uint2 pl = make_uint2((uint32_t)l0 | ((uint32_t)l1 << 16), (uint32_t)l2 | ((uint32_t)l3 << 16));
    *(uint2*)(g_xh + i * 4) = ph;
    *(uint2*)(g_xl + i * 4) = pl;
}

// ===================== base = x @ W1x + hb (tensor-core, 3-term) =====================
#define BM_STAGE 30720
#define BM_SMEM (3 * BM_STAGE)

__global__ __launch_bounds__(256, 2) void base_mma() {
    extern __shared__ char sm[];
    int n0 = blockIdx.x * 64;
    int tid = threadIdx.x, lane = tid & 31, wid = tid >> 5;
    int wy = wid & 1, wx = wid >> 1;
    uint32_t sb0 = smem_u32(sm);

    uint32_t sdst[6];
    const char* gsrc[6];
#pragma unroll
    for (int j = 0; j < 6; j++) {
        int sid = tid + 256 * j;
        const unsigned short* g;
        uint32_t so;
        if (sid < 256) {
            int row = sid >> 2, seg = sid & 3;
            so = row * 80u + seg * 16u;
            g = g_xh + (size_t)(n0 + row) * Dd + seg * 8;
        } else if (sid < 512) {
            int rid = sid - 256;
            int row = rid >> 2, seg = rid & 3;
            so = 5120u + row * 80u + seg * 16u;
            g = g_xl + (size_t)(n0 + row) * Dd + seg * 8;
        } else if (sid < 1024) {
            int rid = sid - 512;
            int row = rid >> 2, seg = rid & 3;
            so = 10240u + row * 80u + seg * 16u;
            g = g_W1TH + (size_t)row * Dd + seg * 8;
        } else {
            int rid = sid - 1024;
            int row = rid >> 2, seg = rid & 3;
            so = 20480u + row * 80u + seg * 16u;
            g = g_W1TL + (size_t)row * Dd + seg * 8;
        }
        sdst[j] = so;
        gsrc[j] = (const char*)g;
    }

    float acc[2][4][4];
#pragma unroll
    for (int a = 0; a < 2; a++)
#pragma unroll
        for (int b = 0; b < 4; b++)
#pragma unroll
            for (int c = 0; c < 4; c++) acc[a][b][c] = 0.f;

    uint32_t aoff = (uint32_t)((wy * 32 + (lane & 15)) * 80 + (lane >> 4) * 16);
    uint32_t boff = (uint32_t)((wx * 32 + ((lane & 7) | ((lane >> 4) << 3))) * 80 + ((lane >> 3) & 1) * 16);

    const int NCH = 32;
#pragma unroll
    for (int j = 0; j < 6; j++) CPASYNC16(sb0 + sdst[j], gsrc[j]);
    CP_COMMIT();
#pragma unroll
    for (int j = 0; j < 6; j++) CPASYNC16(sb0 + BM_STAGE + sdst[j], gsrc[j] + 64);
    CP_COMMIT();

    for (int ch = 0; ch < NCH; ch++) {
        if (ch == NCH - 1) { CP_WAIT(0); } else { CP_WAIT(1); }
        __syncthreads();
        if (ch + 2 < NCH) {
            uint32_t stg = sb0 + ((ch + 2) % 3) * BM_STAGE;
            int cb = (ch + 2) * 64;
#pragma unroll
            for (int j = 0; j < 6; j++) CPASYNC16(stg + sdst[j], gsrc[j] + cb);
            CP_COMMIT();
        }
        uint32_t s = sb0 + (ch % 3) * BM_STAGE;
#pragma unroll
        for (int k16 = 0; k16 < 2; k16++) {
            uint32_t kb = k16 * 32;
            uint32_t ah[2][4], al[2][4], bh[2][4], bl[2][4];
#pragma unroll
            for (int mt = 0; mt < 2; mt++) {
                LDSM4(ah[mt], s + aoff + mt * (16 * 80) + kb);
                LDSM4(al[mt], s + 5120 + aoff + mt * (16 * 80) + kb);
            }
#pragma unroll
            for (int nt = 0; nt < 2; nt++) {
                LDSM4(bh[nt], s + 10240 + boff + nt * (16 * 80) + kb);
                LDSM4(bl[nt], s + 20480 + boff + nt * (16 * 80) + kb);
            }
#pragma unroll
            for (int mt = 0; mt < 2; mt++)
#pragma unroll
                for (int nt = 0; nt < 2; nt++)
#pragma unroll
                    for (int h = 0; h < 2; h++) {
                        MMA16816(acc[mt][nt * 2 + h], ah[mt], bh[nt][2 * h], bh[nt][2 * h + 1]);
                        MMA16816(acc[mt][nt * 2 + h], ah[mt], bl[nt][2 * h], bl[nt][2 * h + 1]);
                        MMA16816(acc[mt][nt * 2 + h], al[mt], bh[nt][2 * h], bh[nt][2 * h + 1]);
                    }
        }
    }

#pragma unroll
    for (int mt = 0; mt < 2; mt++)
#pragma unroll
        for (int rh = 0; rh < 2; rh++) {
            int row = n0 + wy * 32 + mt * 16 + (lane >> 2) + rh * 8;
            const float* hb = g_hb + (row >> 11) * HIDk;
#pragma unroll
            for (int nq = 0; nq < 4; nq++) {
                int col = wx * 32 + nq * 8 + (lane & 3) * 2;
                g_base[(size_t)row * HIDk + col]     = acc[mt][nq][rh * 2]     + hb[col];
                g_base[(size_t)row * HIDk + col + 1] = acc[mt][nq][rh * 2 + 1] + hb[col + 1];
            }
        }
}

// ===================== merge: W' = W + A@B -> transposed fp16 hi =====================
__global__ __launch_bounds__(256) void merge_kernel(
    const float* __restrict__ Wgate, const float* __restrict__ Wup, const float* __restrict__ Wdown,
    const float* __restrict__ Ag, const float* __restrict__ Bg,
    const float* __restrict__ Au, const float* __restrict__ Bu,
    const float* __restrict__ Ad, const float* __restrict__ Bd) {
    __shared__ float As[128][17];
    __shared__ float Bs[16][65];
    __shared__ unsigned short Thi[64][136];
    int e = blockIdx.y, t = blockIdx.x, tid = threadIdx.x;
    const float *src, *Ap, *Bp;
    unsigned short *dhi;
    int r0, c0, rowStride, outStride;
    if (t < 352) {
        int kt = t / 44, ft = t % 44;
        r0 = kt * 128; c0 = ft * 64; rowStride = Ff; outStride = Dd;
        src = Wgate + (size_t)e * Dd * Ff; Ap = Ag + (size_t)e * Dd * Rr; Bp = Bg + (size_t)e * Rr * Ff;
        dhi = g_WgH + (size_t)e * Ff * Dd;
    } else if (t < 704) {
        t -= 352;
        int kt = t / 44, ft = t % 44;
        r0 = kt * 128; c0 = ft * 64; rowStride = Ff; outStride = Dd;
        src = Wup + (size_t)e * Dd * Ff; Ap = Au + (size_t)e * Dd * Rr; Bp = Bu + (size_t)e * Rr * Ff;
        dhi = g_WuH + (size_t)e * Ff * Dd;
    } else {
        t -= 704;
        int kt = t / 16, ft = t % 16;
        r0 = kt * 128; c0 = ft * 64; rowStride = Dd; outStride = Ff;
        src = Wdown + (size_t)e * Ff * Dd; Ap = Ad + (size_t)e * Ff * Rr; Bp = Bd + (size_t)e * Rr * Dd;
        dhi = g_WdH + (size_t)e * Dd * Ff;
    }
    {
        int r = tid >> 1, k0 = (tid & 1) * 8;
#pragma unroll
        for (int kk = 0; kk < 8; kk++)
            As[r][k0 + kk] = Ap[(size_t)(r0 + r) * Rr + k0 + kk];
    }
    for (int i = tid; i < 1024; i += 256) {
        int k = i >> 6, c = i & 63;
        Bs[k][c] = Bp[(size_t)k * rowStride + c0 + c];
    }
    __syncthreads();
    {
        int c = tid & 63, rb = tid >> 6;
        float vbuf[32];
        for (int rr = 0; rr < 32; rr++) {
            int r = rb * 32 + rr;
            float v = src[(size_t)(r0 + r) * rowStride + c0 + c];
#pragma unroll
            for (int k = 0; k < 16; k++) v += As[r][k] * Bs[k][c];
            vbuf[rr] = v;
        }
        for (int w = 0; w < 32; w++) {
            int rr = (w + c) & 31;
            Thi[c][rb * 32 + rr] = __half_as_ushort(__float2half_rn(vbuf[rr]));
        }
    }
    __syncthreads();
    {
        int c = tid >> 2, qq = tid & 3;
        const uint4* sh = (const uint4*)&Thi[c][qq * 32];
        uint4* dH = (uint4*)(dhi + (size_t)(c0 + c) * outStride + r0 + qq * 32);
#pragma unroll
        for (int m = 0; m < 4; m++) dH[m] = sh[m];
    }
}

// ===================== fused gate logits via mma.sync =====================
#define LG_AHI 0
#define LG_ALO 17408
#define LG_B0  34816
#define LG_BSTG 34816
#define LG_RED (LG_B0 + 2 * LG_BSTG)
#define LG_B2  (LG_RED + 768)
#define LG_CG  (LG_B2 + 4096)
#define LG_SMEM (LG_CG + 4096)

__global__ __launch_bounds__(256) void logits_kernel(const float* __restrict__ b2) {
    extern __shared__ char sm[];
    uint32_t sb = smem_u32(sm);
    int e = blockIdx.y, n0 = blockIdx.x * 64;
    int tid = threadIdx.x, lane = tid & 31, wid = tid >> 5;
    int wy = wid & 3, wx = wid >> 2;

    if (tid < 192) ((float*)(sm + LG_RED))[tid] = 0.f;
#pragma unroll
    for (int i = 0; i < 4; i++) {
        ((float*)(sm + LG_B2))[tid + 256 * i] = b2[tid + 256 * i];
        ((float*)(sm + LG_CG))[tid + 256 * i] = g_cgw[tid + 256 * i];
    }
    {
        int t = tid >> 2, kq = (tid & 3) * 32;
        const float4* bp = (const float4*)(g_base + (size_t)(n0 + t) * HIDk + kq);
        const float4* pp = (const float4*)(g_pk + e * HIDk + kq);
        unsigned short* ah = (unsigned short*)(sm + LG_AHI) + t * 136 + kq;
        unsigned short* al = (unsigned short*)(sm + LG_ALO) + t * 136 + kq;
#pragma unroll
        for (int q = 0; q < 8; q++) {
            float4 a = bp[q], p = pp[q];
            float v[4] = {fmaxf(a.x + p.x, 0.f), fmaxf(a.y + p.y, 0.f),
                          fmaxf(a.z + p.z, 0.f), fmaxf(a.w + p.w, 0.f)};
#pragma unroll
            for (int c = 0; c < 4; c++) {
                unsigned short hi, lo;
                f2h_split(v[c], hi, lo);
                ah[q * 4 + c] = hi;
                al[q * 4 + c] = lo;
            }
        }
    }
    uint32_t sdst[8];
    uint32_t gofs[8];
    int ghl[8];
#pragma unroll
    for (int j = 0; j < 8; j++) {
        int sid = tid + 256 * j;
        int hl = sid >> 10;
        int rid = sid & 1023;
        int row = rid >> 4, seg = rid & 15;
        sdst[j] = (uint32_t)(hl * 17408 + row * 272 + seg * 16);
        gofs[j] = (uint32_t)(row * HIDk + seg * 8);
        ghl[j] = hl;
    }
#pragma unroll
    for (int j = 0; j < 8; j++) {
        const unsigned short* g = (ghl[j] ? g_W2TL : g_W2TH) + gofs[j];
        CPASYNC16(sb + LG_B0 + sdst[j], (const char*)g);
    }
    CP_COMMIT();
    __syncthreads();

    float s1[2] = {0.f, 0.f}, s2[2] = {0.f, 0.f}, s3[2] = {0.f, 0.f};
    uint32_t aoff = (uint32_t)((wy * 16 + (lane & 15)) * 272 + (lane >> 4) * 16);
    uint32_t boff = (uint32_t)(((wx * 32 + ((lane & 7) | ((lane >> 4) << 3))) * 272) + ((lane >> 3) & 1) * 16);

    for (int ch = 0; ch < 16; ch++) {
        if (ch + 1 < 16) {
            uint32_t stg = sb + LG_B0 + ((ch + 1) & 1) * LG_BSTG;
            uint32_t dadd = (uint32_t)((ch + 1) * 64 * HIDk);
#pragma unroll
            for (int j = 0; j < 8; j++) {
                const unsigned short* g = (ghl[j] ? g_W2TL : g_W2TH) + gofs[j] + dadd;
                CPASYNC16(stg + sdst[j], (const char*)g);
            }
            CP_COMMIT();
            CP_WAIT(1);
        } else {
            CP_WAIT(0);
        }
        __syncthreads();
        uint32_t sB = sb + LG_B0 + (ch & 1) * LG_BSTG;
        float acc[4][4];
#pragma unroll
        for (int a = 0; a < 4; a++)
#pragma unroll
            for (int c = 0; c < 4; c++) acc[a][c] = 0.f;
#pragma unroll
        for (int k16 = 0; k16 < 8; k16++) {
            uint32_t kb = (uint32_t)(k16 * 32);
            uint32_t ahr[4], alr[4], bh[2][4], bl[2][4];
            LDSM4(ahr, sb + LG_AHI + aoff + kb);
            LDSM4(alr, sb + LG_ALO + aoff + kb);
            LDSM4(bh[0], sB + boff + kb);
            LDSM4(bh[1], sB + boff + 16 * 272 + kb);
            LDSM4(bl[0], sB + 17408 + boff + kb);
            LDSM4(bl[1], sB + 17408 + boff + 16 * 272 + kb);
#pragma unroll
            for (int nt = 0; nt < 2; nt++)
#pragma unroll
                for (int h = 0; h < 2; h++) {
                    MMA16816(acc[nt * 2 + h], ahr, bh[nt][2 * h], bh[nt][2 * h + 1]);
                    MMA16816(acc[nt * 2 + h], alr, bh[nt][2 * h], bh[nt][2 * h + 1]);
                    MMA16816(acc[nt * 2 + h], ahr, bl[nt][2 * h], bl[nt][2 * h + 1]);
                }
        }
#pragma unroll
        for (int nt4 = 0; nt4 < 4; nt4++) {
            int col = ch * 64 + wx * 32 + nt4 * 8 + (lane & 3) * 2;
            float b0 = ((float*)(sm + LG_B2))[col], b1v = ((float*)(sm + LG_B2))[col + 1];
            float c0 = ((float*)(sm + LG_CG))[col], c1v = ((float*)(sm + LG_CG))[col + 1];
            float f;
            f = fmaxf(acc[nt4][0] + b0, 0.f);  s1[0] += f * c0;  s2[0] += f; s3[0] += f * f;
            f = fmaxf(acc[nt4][1] + b1v, 0.f); s1[0] += f * c1v; s2[0] += f; s3[0] += f * f;
            f = fmaxf(acc[nt4][2] + b0, 0.f);  s1[1] += f * c0;  s2[1] += f; s3[1] += f * f;
            f = fmaxf(acc[nt4][3] + b1v, 0.f); s1[1] += f * c1v; s2[1] += f; s3[1] += f * f;
        }
        __syncthreads();
    }
#pragma unroll
    for (int off = 1; off <= 2; off <<= 1) {
#pragma unroll
        for (int i = 0; i < 2; i++) {
            s1[i] += __shfl_xor_sync(0xffffffffu, s1[i], off);
            s2[i] += __shfl_xor_sync(0xffffffffu, s2[i], off);
            s3[i] += __shfl_xor_sync(0xffffffffu, s3[i], off);
        }
    }
    if ((lane & 3) == 0) {
        int row = wy * 16 + (lane >> 2);
        float* red = (float*)(sm + LG_RED);
        atomicAdd(&red[row],           s1[0]);
        atomicAdd(&red[row + 8],       s1[1]);
        atomicAdd(&red[64 + row],      s2[0]);
        atomicAdd(&red[64 + row + 8],  s2[1]);
        atomicAdd(&red[128 + row],     s3[0]);
        atomicAdd(&red[128 + row + 8], s3[1]);
    }
    __syncthreads();
    if (tid < 64) {
        float* red = (float*)(sm + LG_RED);
        float S1 = red[tid], S2 = red[64 + tid], S3 = red[128 + tid];
        float Cg = g_CgCb[0], Cb = g_CgCb[1];
        float mu = S2 * (1.f / (float)Dd);
        float var = S3 * (1.f / (float)Dd) - mu * mu;
        float rstd = rsqrtf(var + LN_EPS);
        g_logits[(size_t)(n0 + tid) * Ee + e] = rstd * (S1 - mu * Cg) + Cb;
    }
}

// ===================== routing =====================
__global__ void route_kernel() {
    int n = blockIdx.x * 256 + threadIdx.x;
    float l[Ee];
    float m = -1e30f;
#pragma unroll
    for (int e = 0; e < Ee; e++) { l[e] = g_logits[(size_t)n * Ee + e]; m = fmaxf(m, l[e]); }
    float s = 0.f;
#pragma unroll
    for (int e = 0; e < Ee; e++) { l[e] = expf(l[e] - m); s += l[e]; }
    float inv = 1.f / s;
#pragma unroll
    for (int e = 0; e < Ee; e++) l[e] *= inv;
    int i0 = 0; float b0 = l[0];
#pragma unroll
    for (int e = 1; e < Ee; e++) if (l[e] > b0) { b0 = l[e]; i0 = e; }
    int i1 = -1; float b1 = -1.f;
#pragma unroll
    for (int e = 0; e < Ee; e++) if (e != i0 && l[e] > b1) { b1 = l[e]; i1 = e; }
    int p0 = atomicAdd(&g_cnt[i0], 1);
    int p1 = atomicAdd(&g_cnt[i1], 1);
    g_te[2 * n] = i0; g_tp[2 * n] = p0; g_tw[2 * n] = b0;
    g_te[2 * n + 1] = i1; g_tp[2 * n + 1] = p1; g_tw[2 * n + 1] = b1;
}

__global__ void scan_kernel() {
    int a = 0;
    for (int e = 0; e < Ee; e++) { g_off[e] = a; a += g_cnt[e]; }
}

__global__ void scatter_kernel() {
    int n = blockIdx.x * 256 + threadIdx.x;
#pragma unroll
    for (int i = 0; i < 2; i++) {
        int slot = g_off[g_te[2 * n + i]] + g_tp[2 * n + i];
        g_ptok[slot] = n;
        g_pw[slot] = g_tw[2 * n + i];
    }
}

// ===================== expert GEMM1 (1-term; gate+up; 3-stage; ftile-fastest grid) =====================
#define G1_STAGE 20480
#define G1_SMEM (1024 + 3 * G1_STAGE)

__global__ __launch_bounds__(256, 2) void moe_gemm1() {
    extern __shared__ char sm[];
    int e = blockIdx.z;
    int cnt = g_cnt[e];
    int r0 = blockIdx.y * 128;
    if (r0 >= cnt) return;
    int off = g_off[e];
    int f0 = blockIdx.x * 64;
    int tid = threadIdx.x, lane = tid & 31, wid = tid >> 5;
    int wy = wid & 3, wx = wid >> 2;

    int* stok = (int*)sm;
    if (tid < 128) {
        int lr = r0 + tid; if (lr >= cnt) lr = cnt - 1;
        stok[tid] = g_ptok[off + lr];
    }
    __syncthreads();

    uint32_t sb0 = smem_u32(sm) + 1024;

    uint32_t sdst[4];
    const char* gsrc[4];
#pragma unroll
    for (int j = 0; j < 4; j++) {
        int sid = tid + 256 * j;
        int region = sid >> 9;
        int rid = sid & 511;
        int row = rid >> 2, seg = rid & 3;
        sdst[j] = (uint32_t)(region * 10240 + row * 80 + seg * 16);
        const unsigned short* g;
        if (region == 0) g = g_xh + (size_t)stok[row] * Dd;
        else             g = (row < 64) ? g_WgH + ((size_t)e * Ff + f0 + row) * Dd
                                        : g_WuH + ((size_t)e * Ff + f0 + row - 64) * Dd;
        gsrc[j] = (const char*)(g + seg * 8);
    }

    float accG[2][4][4], accU[2][4][4];
#pragma unroll
    for (int a = 0; a < 2; a++)
#pragma unroll
        for (int b = 0; b < 4; b++)
#pragma unroll
            for (int c = 0; c < 4; c++) { accG[a][b][c] = 0.f; accU[a][b][c] = 0.f; }

    uint32_t aoff = (uint32_t)((wy * 32 + (lane & 15)) * 80 + (lane >> 4) * 16);
    uint32_t boff = (uint32_t)((wx * 32 + ((lane & 7) | ((lane >> 4) << 3))) * 80 + ((lane >> 3) & 1) * 16);

    const int NCH = 32;
#pragma unroll
    for (int j = 0; j < 4; j++) CPASYNC16(sb0 + sdst[j], gsrc[j]);
    CP_COMMIT();
#pragma unroll
    for (int j = 0; j < 4; j++) CPASYNC16(sb0 + G1_STAGE + sdst[j], gsrc[j] + 64);
    CP_COMMIT();

    for (int ch = 0; ch < NCH; ch++) {
        if (ch == NCH - 1) { CP_WAIT(0); } else { CP_WAIT(1); }
        __syncthreads();
        if (ch + 2 < NCH) {
            uint32_t stg = sb0 + ((ch + 2) % 3) * G1_STAGE;
            int cb = (ch + 2) * 64;
#pragma unroll
            for (int j = 0; j < 4; j++) CPASYNC16(stg + sdst[j], gsrc[j] + cb);
            CP_COMMIT();
        }
        uint32_t s = sb0 + (ch % 3) * G1_STAGE;
#pragma unroll
        for (int k16 = 0; k16 < 2; k16++) {
            uint32_t kb = k16 * 32;
            uint32_t ah[2][4], bg[2][4], bu[2][4];
#pragma unroll
            for (int mt = 0; mt < 2; mt++)
                LDSM4(ah[mt], s + aoff + mt * (16 * 80) + kb);
#pragma unroll
            for (int nt = 0; nt < 2; nt++) {
                LDSM4(bg[nt], s + 10240 + boff + nt * (16 * 80) + kb);
                LDSM4(bu[nt], s + 10240 + 5120 + boff + nt * (16 * 80) + kb);
            }
#pragma unroll
            for (int mt = 0; mt < 2; mt++)
#pragma unroll
                for (int nt = 0; nt < 2; nt++)
#pragma unroll
                    for (int h = 0; h < 2; h++) {
                        MMA16816(accG[mt][nt * 2 + h], ah[mt], bg[nt][2 * h], bg[nt][2 * h + 1]);
                        MMA16816(accU[mt][nt * 2 + h], ah[mt], bu[nt][2 * h], bu[nt][2 * h + 1]);
                    }
        }
    }

#pragma unroll
    for (int mt = 0; mt < 2; mt++)
#pragma unroll
        for (int rh = 0; rh < 2; rh++) {
            int lr = wy * 32 + mt * 16 + (lane >> 2) + rh * 8;
            if (r0 + lr < cnt) {
                int slot = off + r0 + lr;
#pragma unroll
                for (int nt8 = 0; nt8 < 4; nt8++) {
                    int col = f0 + wx * 32 + nt8 * 8 + (lane & 3) * 2;
                    float g0 = accG[mt][nt8][rh * 2 + 0], g1 = accG[mt][nt8][rh * 2 + 1];
                    float u0 = accU[mt][nt8][rh * 2 + 0], u1 = accU[mt][nt8][rh * 2 + 1];
                    float h0 = g0 / (1.f + __expf(-g0)) * u0;
                    float h1 = g1 / (1.f + __expf(-g1)) * u1;
                    unsigned short a0 = __half_as_ushort(__float2half_rn(h0));
                    unsigned short a1 = __half_as_ushort(__float2half_rn(h1));
                    size_t idx = ((size_t)slot * Ff + col) >> 1;
                    ((uint32_t*)g_Hh)[idx] = (uint32_t)a0 | ((uint32_t)a1 << 16);
                }
            }
        }
}

// ===================== expert GEMM2 (1-term; 128x128 tile; 3-stage; dtile-fastest) =====================
#define G2_STAGE 20480
#define G2_SMEM (3 * G2_STAGE)

__global__ __launch_bounds__(256, 2) void moe_gemm2(float* __restrict__ out) {
    extern __shared__ char sm[];
    int e = blockIdx.z;
    int cnt = g_cnt[e];
    int r0 = blockIdx.y * 128;
    if (r0 >= cnt) return;
    int off = g_off[e];
    int d0 = blockIdx.x * 128;
    int tid = threadIdx.x, lane = tid & 31, wid = tid >> 5;
    int wy = wid & 3, wx = wid >> 2;

    uint32_t sb0 = smem_u32(sm);

    uint32_t sdst[4];
    const char* gsrc[4];
#pragma unroll
    for (int j = 0; j < 4; j++) {
        int sid = tid + 256 * j;
        const unsigned short* g;
        uint32_t so;
        if (sid < 512) {
            int row = sid >> 2, seg = sid & 3;
            so = row * 80u + seg * 16u;
            int lr = r0 + row; if (lr >= cnt) lr = cnt - 1;
            g = g_Hh + (size_t)(off + lr) * Ff + seg * 8;
        } else {
            int rid = sid - 512;
            int row = rid >> 2, seg = rid & 3;
            so = 10240u + row * 80u + seg * 16u;
            g = g_WdH + ((size_t)e * Dd + d0 + row) * Ff + seg * 8;
        }
        sdst[j] = so;
        gsrc[j] = (const char*)g;
    }

    float acc[2][8][4];
#pragma unroll
    for (int a = 0; a < 2; a++)
#pragma unroll
        for (int b = 0; b < 8; b++)
#pragma unroll
            for (int c = 0; c < 4; c++) acc[a][b][c] = 0.f;

    uint32_t aoff = (uint32_t)((wy * 32 + (lane & 15)) * 80 + (lane >> 4) * 16);
    uint32_t boff = (uint32_t)((wx * 64 + ((lane & 7) | ((lane >> 4) << 3))) * 80 + ((lane >> 3) & 1) * 16);

    const int NCH = 88;
#pragma unroll
    for (int j = 0; j < 4; j++) CPASYNC16(sb0 + sdst[j], gsrc[j]);
    CP_COMMIT();
#pragma unroll
    for (int j = 0; j < 4; j++) CPASYNC16(sb0 + G2_STAGE + sdst[j], gsrc[j] + 64);
    CP_COMMIT();

    for (int ch = 0; ch < NCH; ch++) {
        if (ch == NCH - 1) { CP_WAIT(0); } else { CP_WAIT(1); }
        __syncthreads();
        if (ch + 2 < NCH) {
            uint32_t stg = sb0 + ((ch + 2) % 3) * G2_STAGE;
            int cb = (ch + 2) * 64;
#pragma unroll
            for (int j = 0; j < 4; j++) CPASYNC16(stg + sdst[j], gsrc[j] + cb);
            CP_COMMIT();
        }
        uint32_t s = sb0 + (ch % 3) * G2_STAGE;
#pragma unroll
        for (int k16 = 0; k16 < 2; k16++) {
            uint32_t kb = k16 * 32;
            uint32_t ah[2][4], bf[4][4];
#pragma unroll
            for (int mt = 0; mt < 2; mt++)
                LDSM4(ah[mt], s + aoff + mt * (16 * 80) + kb);
#pragma unroll
            for (int nt = 0; nt < 4; nt++) LDSM4(bf[nt], s + 10240 + boff + nt * (16 * 80) + kb);
#pragma unroll
            for (int mt = 0; mt < 2; mt++)
#pragma unroll
                for (int nt = 0; nt < 4; nt++)
#pragma unroll
                    for (int h = 0; h < 2; h++)
                        MMA16816(acc[mt][nt * 2 + h], ah[mt], bf[nt][2 * h], bf[nt][2 * h + 1]);
        }
    }

#pragma unroll
    for (int mt = 0; mt < 2; mt++)
#pragma unroll
        for (int rh = 0; rh < 2; rh++) {
            int lr = wy * 32 + mt * 16 + (lane >> 2) + rh * 8;
            if (r0 + lr < cnt) {
                int slot = off + r0 + lr;
                int tok = g_ptok[slot];
                float w = g_pw[slot];
                float* op = out + (size_t)tok * Dd + d0 + wx * 64 + (lane & 3) * 2;
#pragma unroll
                for (int nt8 = 0; nt8 < 8; nt8++) {
                    atomicAdd(op + nt8 * 8,     acc[mt][nt8][rh * 2 + 0] * w);
                    atomicAdd(op + nt8 * 8 + 1, acc[mt][nt8][rh * 2 + 1] * w);
                }
            }
        }
}

// ===================== launch =====================
extern "C" void kernel_launch(void* const* d_in, const int* in_sizes, int n_in,
                              void* d_out, int out_size) {
    (void)in_sizes; (void)n_in;
    const float* x       = (const float*)d_in[0];
    const float* hist    = (const float*)d_in[1];
    const float* persona = (const float*)d_in[2];
    const float* W1x     = (const float*)d_in[3];
    const float* W1h     = (const float*)d_in[4];
    const float* W1p     = (const float*)d_in[5];
    const float* b1      = (const float*)d_in[6];
    const float* W2      = (const float*)d_in[7];
    const float* b2      = (const float*)d_in[8];
    const float* ln_g    = (const float*)d_in[9];
    const float* ln_b    = (const float*)d_in[10];
    const float* Wg      = (const float*)d_in[11];
    const float* bg      = (const float*)d_in[12];
    const float* Wgate   = (const float*)d_in[13];
    const float* Wup     = (const float*)d_in[14];
    const float* Wdown   = (const float*)d_in[15];
    const float* Ag      = (const float*)d_in[16];
    const float* Bg      = (const float*)d_in[17];
    const float* Au      = (const float*)d_in[18];
    const float* Bu      = (const float*)d_in[19];
    const float* Ad      = (const float*)d_in[20];
    const float* Bd      = (const float*)d_in[21];
    float* out = (float*)d_out;

    // Lazily-created side stream + fork/join events (created on the first,
    // uncaptured correctness call; reused identically in every capture).
    static cudaStream_t s2 = nullptr;
    static cudaEvent_t evFork = nullptr, evJoin = nullptr;
    if (!s2) {
        cudaStreamCreateWithFlags(&s2, cudaStreamNonBlocking);
        cudaEventCreateWithFlags(&evFork, cudaEventDisableTiming);
        cudaEventCreateWithFlags(&evJoin, cudaEventDisableTiming);
    }

    cudaFuncSetAttribute(moe_gemm1, cudaFuncAttributeMaxDynamicSharedMemorySize, G1_SMEM);
    cudaFuncSetAttribute(moe_gemm2, cudaFuncAttributeMaxDynamicSharedMemorySize, G2_SMEM);
    cudaFuncSetAttribute(logits_kernel, cudaFuncAttributeMaxDynamicSharedMemorySize, LG_SMEM);
    cudaFuncSetAttribute(base_mma, cudaFuncAttributeMaxDynamicSharedMemorySize, BM_SMEM);

    void* cntp = nullptr;
    cudaGetSymbolAddress(&cntp, g_cnt);

    cudaMemsetAsync(out, 0, (size_t)out_size * sizeof(float));
    cudaMemsetAsync(cntp, 0, Ee * sizeof(int));

    // Fork: merge (independent of the gating chain) runs on s2.
    cudaEventRecord(evFork, 0);
    cudaStreamWaitEvent(s2, evFork, 0);
    merge_kernel<<<dim3(1056, Ee), 256, 0, s2>>>(Wgate, Wup, Wdown, Ag, Bg, Au, Bu, Ad, Bd);
    cudaEventRecord(evJoin, s2);

    // Gating chain on the main stream.
    prep_kernel<<<13, 128>>>(hist, W1h, b1, persona, W1p, ln_g, ln_b, Wg, bg);
    w2t_kernel<<<dim3(Dd / 32, HIDk / 32), 256>>>(W2);
    w1t_kernel<<<dim3(HIDk / 32, Dd / 32), 256>>>(W1x);
    xconv_kernel<<<(Nn * Dd) / 4 / 256, 256>>>(x);
    base_mma<<<Nn / 64, 256, BM_SMEM>>>();
    logits_kernel<<<dim3(Nn / 64, Ee), 256, LG_SMEM>>>(b2);
    route_kernel<<<Nn / 256, 256>>>();
    scan_kernel<<<1, 1>>>();
    scatter_kernel<<<Nn / 256, 256>>>();

    // Join: experts need both merged weights and routing.
    cudaStreamWaitEvent(0, evJoin, 0);
    moe_gemm1<<<dim3(Ff / 64, NP / 128, Ee), 256, G1_SMEM>>>();
    moe_gemm2<<<dim3(Dd / 128, NP / 128, Ee), 256, G2_SMEM>>>(out);
}